// round 2
// baseline (speedup 1.0000x reference)
#include <cuda_runtime.h>
#include <cstdint>
#include <cstddef>

// ---------------------------------------------------------------------------
// graph12: multimodal gated fusion.
//   B=16384 rows, d=1024, hidden 64 (gf), head 50/50/8.
// Pipeline:
//  k0: rearrange W1[2048,64] -> W1r[1024,128]  (cols 0-63 = top, 64-127 = bottom)
//  k1: per-row attention softmax, modality softmax stats, w_uni, w_bi, unimodal
//  kP(0): PQ1[49152,128] = x[49152,1024] @ W1r
//  k3: stage-1 gf second layers (3 pairs) -> a_v,a_l,v_l (g_bi3), bimodal sum
//  k4: per-row stage-2 softmax dots -> w_tri
//  kP(1): PQ2 = g_bi3 @ W1r
//  k6: stage-2 gf second layers (6 pairs) -> trimodal sum
//  k7: fused BN + 3-layer head + softmax -> y2
// ---------------------------------------------------------------------------

#define NB    16384
#define ND    1024
#define NR3   (NB*3)          // 49152

__device__ float g_W1r  [1024*128];
__device__ float g_PQ1  [(size_t)NR3*128];
__device__ float g_PQ2  [(size_t)NR3*128];
__device__ float g_uni  [(size_t)NB*ND];
__device__ float g_bi3  [(size_t)NR3*ND];    // [b][p][j], p: 0=a_v 1=a_l 2=v_l
__device__ float g_bisum[(size_t)NB*ND];     // a_v+a_l+v_l (divide by 3 in k7)
__device__ float g_tri  [(size_t)NB*ND];     // sum of 6 (divide by 6 in k7)
__device__ float g_wuni [NB*3];
__device__ float g_wbi  [NB*3];
__device__ float g_sbi  [NB*3];              // sav, sal, svl (pre-softmax)
__device__ float g_wtri [NB*6];

// -------------------------- block reductions (256 thr) ----------------------
template<int NV>
__device__ __forceinline__ void blockReduceSumN(float* v, float* rbuf) {
    int tid = threadIdx.x, lane = tid & 31, w = tid >> 5;
#pragma unroll
    for (int n = 0; n < NV; n++) {
        float x = v[n];
#pragma unroll
        for (int o = 16; o > 0; o >>= 1) x += __shfl_down_sync(0xffffffffu, x, o);
        if (lane == 0) rbuf[n*8 + w] = x;
    }
    __syncthreads();
    if (tid < NV) {
        float s = rbuf[tid*8];
#pragma unroll
        for (int q = 1; q < 8; q++) s += rbuf[tid*8 + q];
        rbuf[tid*8] = s;
    }
    __syncthreads();
#pragma unroll
    for (int n = 0; n < NV; n++) v[n] = rbuf[n*8];
    __syncthreads();
}

template<int NV>
__device__ __forceinline__ void blockReduceMaxN(float* v, float* rbuf) {
    int tid = threadIdx.x, lane = tid & 31, w = tid >> 5;
#pragma unroll
    for (int n = 0; n < NV; n++) {
        float x = v[n];
#pragma unroll
        for (int o = 16; o > 0; o >>= 1) x = fmaxf(x, __shfl_down_sync(0xffffffffu, x, o));
        if (lane == 0) rbuf[n*8 + w] = x;
    }
    __syncthreads();
    if (tid < NV) {
        float s = rbuf[tid*8];
#pragma unroll
        for (int q = 1; q < 8; q++) s = fmaxf(s, rbuf[tid*8 + q]);
        rbuf[tid*8] = s;
    }
    __syncthreads();
#pragma unroll
    for (int n = 0; n < NV; n++) v[n] = rbuf[n*8];
    __syncthreads();
}

// -------------------------- k0: W1 rearrange --------------------------------
__global__ void k0_w1r(const float* __restrict__ W1) {
    int i = blockIdx.x * 256 + threadIdx.x;
    if (i < 1024*128) {
        int k = i >> 7, j = i & 127;
        g_W1r[i] = (j < 64) ? W1[(size_t)k*64 + j]
                            : W1[(size_t)(1024 + k)*64 + (j - 64)];
    }
}

// -------------------------- k1: attention + stage-1 stats -------------------
__global__ __launch_bounds__(256) void k1_att(
    const float* __restrict__ x, const float* __restrict__ attW,
    const float* __restrict__ attb, float* __restrict__ outW, int wflag)
{
    __shared__ float sm[3072];
    __shared__ float rbuf[6*8];
    __shared__ float bc[4];
    int b = blockIdx.x, tid = threadIdx.x;
    const float* xr = x + (size_t)b*3072;
    for (int i = tid; i < 3072; i += 256) sm[i] = xr[i];
    __syncthreads();

    float red[3];
    float a0 = 0.f, a1 = 0.f, a2 = 0.f;
    float m0 = -1e30f, m1 = -1e30f, m2 = -1e30f;
    for (int i = tid; i < 1024; i += 256) {
        float w = attW[i];
        float av = sm[i], vv = sm[1024 + i], lv = sm[2048 + i];
        a0 = fmaf(av, w, a0); a1 = fmaf(vv, w, a1); a2 = fmaf(lv, w, a2);
        m0 = fmaxf(m0, av);  m1 = fmaxf(m1, vv);  m2 = fmaxf(m2, lv);
    }
    red[0] = a0; red[1] = a1; red[2] = a2;
    blockReduceSumN<3>(red, rbuf);
    float att0 = red[0], att1 = red[1], att2 = red[2];
    red[0] = m0; red[1] = m1; red[2] = m2;
    blockReduceMaxN<3>(red, rbuf);
    float Ma = red[0], Mv = red[1], Ml = red[2];

    float red6[6] = {0.f, 0.f, 0.f, 0.f, 0.f, 0.f};
    for (int i = tid; i < 1024; i += 256) {
        float ea = expf(sm[i] - Ma);
        float ev = expf(sm[1024 + i] - Mv);
        float el = expf(sm[2048 + i] - Ml);
        red6[0] += ea; red6[1] += ev; red6[2] += el;
        red6[3] = fmaf(ea, ev, red6[3]);
        red6[4] = fmaf(ea, el, red6[4]);
        red6[5] = fmaf(ev, el, red6[5]);
    }
    blockReduceSumN<6>(red6, rbuf);

    if (tid == 0) {
        float ab = attb[0];
        float t0 = tanhf(att0 + ab), t1 = tanhf(att1 + ab), t2 = tanhf(att2 + ab);
        float mm = fmaxf(t0, fmaxf(t1, t2));
        float e0 = expf(t0 - mm), e1 = expf(t1 - mm), e2 = expf(t2 - mm);
        float inv = 1.f / (e0 + e1 + e2);
        float sa = e0*inv, sv = e1*inv, sl = e2*inv;
        float dav = red6[3] / (red6[0]*red6[1]);
        float dal = red6[4] / (red6[0]*red6[2]);
        float dvl = red6[5] / (red6[1]*red6[2]);
        float sav = (sa + sv) / (dav + 0.5f);
        float sal = (sa + sl) / (dal + 0.5f);
        float svl = (sl + sv) / (dvl + 0.5f);
        g_wuni[b*3+0] = sa; g_wuni[b*3+1] = sv; g_wuni[b*3+2] = sl;
        g_sbi [b*3+0] = sav; g_sbi[b*3+1] = sal; g_sbi[b*3+2] = svl;
        float m3 = fmaxf(sav, fmaxf(sal, svl));
        float f0 = expf(sav - m3), f1 = expf(sal - m3), f2 = expf(svl - m3);
        float fi = 1.f / (f0 + f1 + f2);
        g_wbi[b*3+0] = f0*fi; g_wbi[b*3+1] = f1*fi; g_wbi[b*3+2] = f2*fi;
        if (wflag) {
            float* o = outW + (size_t)b*12;
            o[0] = sa; o[1] = sv; o[2] = sl;
            o[3] = f0*fi; o[4] = f1*fi; o[5] = f2*fi;
        }
        bc[0] = sa; bc[1] = sv; bc[2] = sl;
    }
    __syncthreads();
    float sa = bc[0], sv = bc[1], sl = bc[2];
    float* ur = g_uni + (size_t)b*1024;
    for (int i = tid; i < 1024; i += 256)
        ur[i] = (sa*sm[i] + sv*sm[1024+i] + sl*sm[2048+i]) * (1.0f/3.0f);
}

// -------------------------- kP: projection GEMM -----------------------------
// C[49152,128] = A[49152,1024] @ g_W1r[1024,128]
__global__ __launch_bounds__(256) void k_proj(const float* __restrict__ x, int which)
{
    const float* A = which ? g_bi3 : x;
    float* C = which ? g_PQ2 : g_PQ1;
    __shared__ float As[16][129];
    __shared__ float Bs[16][128];
    int tid = threadIdx.x;
    size_t m0 = (size_t)blockIdx.x * 128;
    int tm = (tid >> 4) * 4, tn = (tid & 15) * 4;
    float acc[2][2][4][4] = {};

    for (int kk = 0; kk < 1024; kk += 16) {
        for (int i = tid; i < 2048; i += 256) {
            int m = i >> 4, k = i & 15;
            As[k][m] = A[(m0 + m)*1024 + kk + k];
        }
        for (int i = tid; i < 2048; i += 256) {
            int k = i >> 7, n = i & 127;
            Bs[k][n] = g_W1r[(size_t)(kk + k)*128 + n];
        }
        __syncthreads();
#pragma unroll
        for (int k = 0; k < 16; k++) {
            float ar[2][4], br[2][4];
#pragma unroll
            for (int u = 0; u < 4; u++) {
                ar[0][u] = As[k][tm + u];
                ar[1][u] = As[k][64 + tm + u];
            }
            float4 b0 = *(const float4*)&Bs[k][tn];
            float4 b1 = *(const float4*)&Bs[k][64 + tn];
            br[0][0]=b0.x; br[0][1]=b0.y; br[0][2]=b0.z; br[0][3]=b0.w;
            br[1][0]=b1.x; br[1][1]=b1.y; br[1][2]=b1.z; br[1][3]=b1.w;
#pragma unroll
            for (int i2 = 0; i2 < 2; i2++)
#pragma unroll
            for (int j2 = 0; j2 < 2; j2++)
#pragma unroll
            for (int u = 0; u < 4; u++)
#pragma unroll
            for (int v = 0; v < 4; v++)
                acc[i2][j2][u][v] = fmaf(ar[i2][u], br[j2][v], acc[i2][j2][u][v]);
        }
        __syncthreads();
    }
#pragma unroll
    for (int i2 = 0; i2 < 2; i2++)
#pragma unroll
    for (int j2 = 0; j2 < 2; j2++)
#pragma unroll
    for (int u = 0; u < 4; u++) {
        size_t row = m0 + tm + i2*64 + u;
        float4 o;
        o.x = acc[i2][j2][u][0]; o.y = acc[i2][j2][u][1];
        o.z = acc[i2][j2][u][2]; o.w = acc[i2][j2][u][3];
        *(float4*)&C[row*128 + tn + j2*64] = o;
    }
}

// -------------------------- k3: stage-1 gf second layer ---------------------
__global__ __launch_bounds__(256) void k3_stage1(
    const float* __restrict__ W2, const float* __restrict__ b1,
    const float* __restrict__ b2)
{
    __shared__ float Ws[64][128];
    __shared__ float Ts[64][64];
    int tid = threadIdx.x;
    int b0 = blockIdx.x * 64, n0 = blockIdx.y * 128;
    for (int i = tid; i < 8192; i += 256) {
        int k = i >> 7, n = i & 127;
        Ws[k][n] = W2[(size_t)k*1024 + n0 + n];
    }
    int r0 = (tid >> 5) * 8, c0 = (tid & 31) * 4;
    float4 b2v = *(const float4*)&b2[n0 + c0];
    float bis[8][4] = {};
#pragma unroll 1
    for (int p = 0; p < 3; p++) {
        int f = (p == 2) ? 1 : 0;
        int s = (p == 0) ? 1 : 2;
        __syncthreads();
        for (int i = tid; i < 4096; i += 256) {
            int r = i >> 6, k = i & 63;
            size_t base = (size_t)(b0 + r) * 3;
            float tv = g_PQ1[(base + f)*128 + k] + g_PQ1[(base + s)*128 + 64 + k] + b1[k];
            Ts[r][k] = tv > 0.f ? tv : 0.2f * tv;
        }
        __syncthreads();
        float acc[8][4] = {};
#pragma unroll 8
        for (int k = 0; k < 64; k++) {
            float4 w = *(const float4*)&Ws[k][c0];
#pragma unroll
            for (int u = 0; u < 8; u++) {
                float a = Ts[r0 + u][k];
                acc[u][0] = fmaf(a, w.x, acc[u][0]);
                acc[u][1] = fmaf(a, w.y, acc[u][1]);
                acc[u][2] = fmaf(a, w.z, acc[u][2]);
                acc[u][3] = fmaf(a, w.w, acc[u][3]);
            }
        }
#pragma unroll
        for (int u = 0; u < 8; u++) {
            int row = b0 + r0 + u;
            float wb = g_wbi[(size_t)row*3 + p];
            float4 o;
            float g, q;
            g = tanhf(acc[u][0] + b2v.x); q = wb*g; o.x = q > 0.f ? q : 0.01f*q;
            g = tanhf(acc[u][1] + b2v.y); q = wb*g; o.y = q > 0.f ? q : 0.01f*q;
            g = tanhf(acc[u][2] + b2v.z); q = wb*g; o.z = q > 0.f ? q : 0.01f*q;
            g = tanhf(acc[u][3] + b2v.w); q = wb*g; o.w = q > 0.f ? q : 0.01f*q;
            bis[u][0] += o.x; bis[u][1] += o.y; bis[u][2] += o.z; bis[u][3] += o.w;
            *(float4*)&g_bi3[((size_t)row*3 + p)*1024 + n0 + c0] = o;
        }
    }
#pragma unroll
    for (int u = 0; u < 8; u++) {
        float4 o; o.x = bis[u][0]; o.y = bis[u][1]; o.z = bis[u][2]; o.w = bis[u][3];
        *(float4*)&g_bisum[(size_t)(b0 + r0 + u)*1024 + n0 + c0] = o;
    }
}

// -------------------------- k4: stage-2 weights -----------------------------
__global__ __launch_bounds__(256) void k4_tri(
    const float* __restrict__ x, float* __restrict__ outW, int wflag)
{
    __shared__ float sm[6144];       // av, al, vl, a1, v1, l1
    __shared__ float rbuf[12*8];
    int b = blockIdx.x, tid = threadIdx.x;
    const float* br = g_bi3 + (size_t)b*3072;
    const float* xr = x + (size_t)b*3072;
    for (int i = tid; i < 3072; i += 256) { sm[i] = br[i]; sm[3072 + i] = xr[i]; }
    __syncthreads();

    float mx[6] = {-1e30f, -1e30f, -1e30f, -1e30f, -1e30f, -1e30f};
    for (int i = tid; i < 1024; i += 256) {
#pragma unroll
        for (int v = 0; v < 6; v++) mx[v] = fmaxf(mx[v], sm[v*1024 + i]);
    }
    blockReduceMaxN<6>(mx, rbuf);

    float zs[12] = {};
    for (int i = tid; i < 1024; i += 256) {
        float e[6];
#pragma unroll
        for (int v = 0; v < 6; v++) { e[v] = expf(sm[v*1024 + i] - mx[v]); zs[v] += e[v]; }
        zs[6]  = fmaf(e[0], e[2], zs[6]);
        zs[7]  = fmaf(e[0], e[1], zs[7]);
        zs[8]  = fmaf(e[1], e[2], zs[8]);
        zs[9]  = fmaf(e[0], e[5], zs[9]);
        zs[10] = fmaf(e[1], e[4], zs[10]);
        zs[11] = fmaf(e[2], e[3], zs[11]);
    }
    blockReduceSumN<12>(zs, rbuf);

    if (tid == 0) {
        float d0 = zs[6]  / (zs[0]*zs[2]);
        float d1 = zs[7]  / (zs[0]*zs[1]);
        float d2 = zs[8]  / (zs[1]*zs[2]);
        float d3 = zs[9]  / (zs[0]*zs[5]);
        float d4 = zs[10] / (zs[1]*zs[4]);
        float d5 = zs[11] / (zs[2]*zs[3]);
        float sa = g_wuni[b*3+0], sv = g_wuni[b*3+1], sl = g_wuni[b*3+2];
        float sav = g_sbi[b*3+0], sal = g_sbi[b*3+1], svl = g_sbi[b*3+2];
        float n[6];
        n[0] = (sav + svl) / (d0 + 0.5f);
        n[1] = (sav + sal) / (d1 + 0.5f);
        n[2] = (sal + svl) / (d2 + 0.5f);
        n[3] = (sav + sl ) / (d3 + 0.5f);
        n[4] = (sal + sv ) / (d4 + 0.5f);
        n[5] = (sa  + svl) / (d5 + 0.5f);
        float m = n[0];
#pragma unroll
        for (int k = 1; k < 6; k++) m = fmaxf(m, n[k]);
        float e[6], ssum = 0.f;
#pragma unroll
        for (int k = 0; k < 6; k++) { e[k] = expf(n[k] - m); ssum += e[k]; }
        float inv = 1.f / ssum;
#pragma unroll
        for (int k = 0; k < 6; k++) {
            g_wtri[b*6 + k] = e[k]*inv;
            if (wflag) outW[(size_t)b*12 + 6 + k] = e[k]*inv;
        }
    }
}

// -------------------------- k6: stage-2 gf second layer ---------------------
__global__ __launch_bounds__(256) void k6_stage2(
    const float* __restrict__ W2, const float* __restrict__ b1,
    const float* __restrict__ b2)
{
    __shared__ float Ws[64][128];
    __shared__ float Ts[64][64];
    int tid = threadIdx.x;
    int b0 = blockIdx.x * 64, n0 = blockIdx.y * 128;
    for (int i = tid; i < 8192; i += 256) {
        int k = i >> 7, n = i & 127;
        Ws[k][n] = W2[(size_t)k*1024 + n0 + n];
    }
    int r0 = (tid >> 5) * 8, c0 = (tid & 31) * 4;
    float4 b2v = *(const float4*)&b2[n0 + c0];
    float tri[8][4] = {};
    const int PR[6] = {0, 0, 2, 0, 1, 2};
    const int QR[6] = {2, 1, 1, 2, 1, 0};
    const int QS[6] = {0, 0, 0, 1, 1, 1};   // 0 -> PQ2, 1 -> PQ1
#pragma unroll 1
    for (int p = 0; p < 6; p++) {
        const float* Qb = QS[p] ? g_PQ1 : g_PQ2;
        int fr = PR[p], qr = QR[p];
        __syncthreads();
        for (int i = tid; i < 4096; i += 256) {
            int r = i >> 6, k = i & 63;
            size_t base = (size_t)(b0 + r) * 3;
            float tv = g_PQ2[(base + fr)*128 + k] + Qb[(base + qr)*128 + 64 + k] + b1[k];
            Ts[r][k] = tv > 0.f ? tv : 0.2f * tv;
        }
        __syncthreads();
        float acc[8][4] = {};
#pragma unroll 8
        for (int k = 0; k < 64; k++) {
            float4 w = *(const float4*)&Ws[k][c0];
#pragma unroll
            for (int u = 0; u < 8; u++) {
                float a = Ts[r0 + u][k];
                acc[u][0] = fmaf(a, w.x, acc[u][0]);
                acc[u][1] = fmaf(a, w.y, acc[u][1]);
                acc[u][2] = fmaf(a, w.z, acc[u][2]);
                acc[u][3] = fmaf(a, w.w, acc[u][3]);
            }
        }
#pragma unroll
        for (int u = 0; u < 8; u++) {
            int row = b0 + r0 + u;
            float wt = g_wtri[(size_t)row*6 + p];
            float g, q;
            g = tanhf(acc[u][0] + b2v.x); q = wt*g; tri[u][0] += (q > 0.f ? q : 0.01f*q);
            g = tanhf(acc[u][1] + b2v.y); q = wt*g; tri[u][1] += (q > 0.f ? q : 0.01f*q);
            g = tanhf(acc[u][2] + b2v.z); q = wt*g; tri[u][2] += (q > 0.f ? q : 0.01f*q);
            g = tanhf(acc[u][3] + b2v.w); q = wt*g; tri[u][3] += (q > 0.f ? q : 0.01f*q);
        }
    }
#pragma unroll
    for (int u = 0; u < 8; u++) {
        float4 o; o.x = tri[u][0]; o.y = tri[u][1]; o.z = tri[u][2]; o.w = tri[u][3];
        *(float4*)&g_tri[(size_t)(b0 + r0 + u)*1024 + n0 + c0] = o;
    }
}

// -------------------------- k7: fused head ----------------------------------
__global__ __launch_bounds__(256) void k7_final(
    const float* __restrict__ bng, const float* __restrict__ bnb,
    const float* __restrict__ l1W, const float* __restrict__ l1b,
    const float* __restrict__ l2W, const float* __restrict__ l2b,
    const float* __restrict__ l3W, const float* __restrict__ l3b,
    float* __restrict__ out)
{
    __shared__ float pool[11264];
    // offsets: sA=0 (2048), sW=2048 (2048), Y1=4096 (3328), Y2=7424 (3328), Y3=10752 (512)
    float* sA = pool;
    float* sW = pool + 2048;
    float* Y1 = pool + 4096;
    float* Y2 = pool + 7424;
    float* Y3 = pool + 10752;
    int tid = threadIdx.x;
    int b0 = blockIdx.x * 64;
    int rr = (tid >> 4) * 4, cc = (tid & 15) * 4;
    const float BNS = rsqrtf(1.0f + 1e-5f);

    float acc[4][4] = {};
    for (int kk = 0; kk < 3072; kk += 32) {
        int region = kk >> 10;
        const float* src = region == 0 ? g_uni : (region == 1 ? g_bisum : g_tri);
        float mult = region == 0 ? 1.f : (region == 1 ? (1.f/3.f) : (1.f/6.f));
        __syncthreads();
        for (int i = tid; i < 2048; i += 256) {
            int r = i >> 5, k = i & 31;
            int j = kk + k;
            float vv = src[(size_t)(b0 + r)*1024 + (j & 1023)];
            sA[r*32 + k] = vv * (mult * BNS * bng[j]) + bnb[j];
        }
        for (int i = tid; i < 2048; i += 256) {
            int k = i >> 6, n = i & 63;
            int j = kk + k;
            sW[k*64 + n] = (n < 50) ? l1W[(size_t)j*50 + n] : 0.f;
        }
        __syncthreads();
#pragma unroll 8
        for (int k = 0; k < 32; k++) {
            float4 w = *(const float4*)&sW[k*64 + cc];
#pragma unroll
            for (int u = 0; u < 4; u++) {
                float a = sA[(rr + u)*32 + k];
                acc[u][0] = fmaf(a, w.x, acc[u][0]);
                acc[u][1] = fmaf(a, w.y, acc[u][1]);
                acc[u][2] = fmaf(a, w.z, acc[u][2]);
                acc[u][3] = fmaf(a, w.w, acc[u][3]);
            }
        }
    }
    __syncthreads();
    // y1 = tanh(. + b); load l2W/l3W into freed sA/sW region
#pragma unroll
    for (int u = 0; u < 4; u++)
#pragma unroll
    for (int v = 0; v < 4; v++)
        if (cc + v < 50)
            Y1[(rr + u)*52 + cc + v] = tanhf(acc[u][v] + l1b[cc + v]);
    for (int i = tid; i < 2500; i += 256) {
        int k = i / 50, c = i - k*50;
        pool[k*52 + c] = l2W[i];           // W2s at pool[0..2599]
    }
    for (int i = tid; i < 400; i += 256) pool[2600 + i] = l3W[i];   // W3s
    __syncthreads();

    float acc2[4][4] = {};
#pragma unroll 5
    for (int k = 0; k < 50; k++) {
        float4 w = *(const float4*)&pool[k*52 + cc];
#pragma unroll
        for (int u = 0; u < 4; u++) {
            float a = Y1[(rr + u)*52 + k];
            acc2[u][0] = fmaf(a, w.x, acc2[u][0]);
            acc2[u][1] = fmaf(a, w.y, acc2[u][1]);
            acc2[u][2] = fmaf(a, w.z, acc2[u][2]);
            acc2[u][3] = fmaf(a, w.w, acc2[u][3]);
        }
    }
#pragma unroll
    for (int u = 0; u < 4; u++)
#pragma unroll
    for (int v = 0; v < 4; v++)
        if (cc + v < 50)
            Y2[(rr + u)*52 + cc + v] = tanhf(acc2[u][v] + l2b[cc + v]);
    __syncthreads();

    for (int t = tid; t < 512; t += 256) {
        int r = t >> 3, c = t & 7;
        float a = l3b[c];
        for (int k = 0; k < 50; k++)
            a = fmaf(Y2[r*52 + k], pool[2600 + k*8 + c], a);
        Y3[r*8 + c] = a;
    }
    __syncthreads();
    if (tid < 64) {
        int r = tid;
        float m = -1e30f;
#pragma unroll
        for (int c = 0; c < 8; c++) m = fmaxf(m, Y3[r*8 + c]);
        float e[8], s = 0.f;
#pragma unroll
        for (int c = 0; c < 8; c++) { e[c] = expf(Y3[r*8 + c] - m); s += e[c]; }
        float inv = 1.f / s;
        float* orow = out + (size_t)(b0 + r)*8;
#pragma unroll
        for (int c = 0; c < 8; c++) orow[c] = e[c]*inv;
    }
}

// -------------------------- launch ------------------------------------------
extern "C" void kernel_launch(void* const* d_in, const int* in_sizes, int n_in,
                              void* d_out, int out_size)
{
    const float* x    = (const float*)d_in[0];
    const float* attW = (const float*)d_in[1];
    const float* attb = (const float*)d_in[2];
    const float* gfW1 = (const float*)d_in[3];
    const float* gfb1 = (const float*)d_in[4];
    const float* gfW2 = (const float*)d_in[5];
    const float* gfb2 = (const float*)d_in[6];
    const float* bng  = (const float*)d_in[7];
    const float* bnb  = (const float*)d_in[8];
    const float* l1W  = (const float*)d_in[9];
    const float* l1b  = (const float*)d_in[10];
    const float* l2W  = (const float*)d_in[11];
    const float* l2b  = (const float*)d_in[12];
    const float* l3W  = (const float*)d_in[13];
    const float* l3b  = (const float*)d_in[14];
    float* out  = (float*)d_out;
    int wflag = (out_size >= NB*20) ? 1 : 0;
    float* outW = out + (size_t)NB*8;

    k0_w1r<<<512, 256>>>(gfW1);
    k1_att<<<NB, 256>>>(x, attW, attb, outW, wflag);
    k_proj<<<NR3/128, 256>>>(x, 0);
    dim3 g3(NB/64, 8);
    k3_stage1<<<g3, 256>>>(gfW2, gfb1, gfb2);
    k4_tri<<<NB, 256>>>(x, outW, wflag);
    k_proj<<<NR3/128, 256>>>(x, 1);
    k6_stage2<<<g3, 256>>>(gfW2, gfb1, gfb2);
    k7_final<<<NB/64, 256>>>(bng, bnb, l1W, l1b, l2W, l2b, l3W, l3b, out);
}

// round 3
// speedup vs baseline: 1.3225x; 1.3225x over previous
#include <cuda_runtime.h>
#include <cstdint>
#include <cstddef>

// ---------------------------------------------------------------------------
// graph12: multimodal gated fusion — Round 2: tf32 tensor-core GEMMs.
//  k0: rearrange W1[2048,64] -> W1r[1024,128]
//  k1: per-row attention softmax, stage-1 stats, w_uni, w_bi, unimodal (fp32)
//  kP(0): PQ1[49152,128] = x @ W1r            (tf32 mma)
//  k3: stage-1 gf second layers (3 pairs)     (tf32 mma, fused epilogue)
//  k4: stage-2 softmax dots -> w_tri          (fp32)
//  kP(1): PQ2 = g_bi3 @ W1r                   (tf32 mma)
//  k6: stage-2 gf second layers (6 pairs)     (tf32 mma, fused epilogue)
//  k7: fused BN + 3-layer head + softmax      (fp32)
// ---------------------------------------------------------------------------

#define NB    16384
#define ND    1024
#define NR3   (NB*3)          // 49152

__device__ float g_W1r  [1024*128];
__device__ float g_PQ1  [(size_t)NR3*128];
__device__ float g_PQ2  [(size_t)NR3*128];
__device__ float g_uni  [(size_t)NB*ND];
__device__ float g_bi3  [(size_t)NR3*ND];    // [b][p][j], p: 0=a_v 1=a_l 2=v_l
__device__ float g_bisum[(size_t)NB*ND];     // a_v+a_l+v_l (divide by 3 in k7)
__device__ float g_tri  [(size_t)NB*ND];     // sum of 6 (divide by 6 in k7)
__device__ float g_wuni [NB*3];
__device__ float g_wbi  [NB*3];
__device__ float g_sbi  [NB*3];              // sav, sal, svl (pre-softmax)
__device__ float g_wtri [NB*6];

// -------------------------- tf32 helpers ------------------------------------
__device__ __forceinline__ unsigned f2tf(float f) {
    unsigned r;
    asm("cvt.rna.tf32.f32 %0, %1;" : "=r"(r) : "f"(f));
    return r;
}

__device__ __forceinline__ void mma_tf32(float4& d, const unsigned* a, const unsigned* b) {
    asm volatile(
        "mma.sync.aligned.m16n8k8.row.col.f32.tf32.tf32.f32 "
        "{%0,%1,%2,%3}, {%4,%5,%6,%7}, {%8,%9}, {%0,%1,%2,%3};"
        : "+f"(d.x), "+f"(d.y), "+f"(d.z), "+f"(d.w)
        : "r"(a[0]), "r"(a[1]), "r"(a[2]), "r"(a[3]), "r"(b[0]), "r"(b[1]));
}

// -------------------------- block reductions (256 thr) ----------------------
template<int NV>
__device__ __forceinline__ void blockReduceSumN(float* v, float* rbuf) {
    int tid = threadIdx.x, lane = tid & 31, w = tid >> 5;
#pragma unroll
    for (int n = 0; n < NV; n++) {
        float x = v[n];
#pragma unroll
        for (int o = 16; o > 0; o >>= 1) x += __shfl_down_sync(0xffffffffu, x, o);
        if (lane == 0) rbuf[n*8 + w] = x;
    }
    __syncthreads();
    if (tid < NV) {
        float s = rbuf[tid*8];
#pragma unroll
        for (int q = 1; q < 8; q++) s += rbuf[tid*8 + q];
        rbuf[tid*8] = s;
    }
    __syncthreads();
#pragma unroll
    for (int n = 0; n < NV; n++) v[n] = rbuf[n*8];
    __syncthreads();
}

template<int NV>
__device__ __forceinline__ void blockReduceMaxN(float* v, float* rbuf) {
    int tid = threadIdx.x, lane = tid & 31, w = tid >> 5;
#pragma unroll
    for (int n = 0; n < NV; n++) {
        float x = v[n];
#pragma unroll
        for (int o = 16; o > 0; o >>= 1) x = fmaxf(x, __shfl_down_sync(0xffffffffu, x, o));
        if (lane == 0) rbuf[n*8 + w] = x;
    }
    __syncthreads();
    if (tid < NV) {
        float s = rbuf[tid*8];
#pragma unroll
        for (int q = 1; q < 8; q++) s = fmaxf(s, rbuf[tid*8 + q]);
        rbuf[tid*8] = s;
    }
    __syncthreads();
#pragma unroll
    for (int n = 0; n < NV; n++) v[n] = rbuf[n*8];
    __syncthreads();
}

// -------------------------- k0: W1 rearrange --------------------------------
__global__ void k0_w1r(const float* __restrict__ W1) {
    int i = blockIdx.x * 256 + threadIdx.x;
    if (i < 1024*128) {
        int k = i >> 7, j = i & 127;
        g_W1r[i] = (j < 64) ? W1[(size_t)k*64 + j]
                            : W1[(size_t)(1024 + k)*64 + (j - 64)];
    }
}

// -------------------------- k1: attention + stage-1 stats -------------------
__global__ __launch_bounds__(256) void k1_att(
    const float* __restrict__ x, const float* __restrict__ attW,
    const float* __restrict__ attb, float* __restrict__ outW, int wflag)
{
    __shared__ float sm[3072];
    __shared__ float rbuf[6*8];
    __shared__ float bc[4];
    int b = blockIdx.x, tid = threadIdx.x;
    const float* xr = x + (size_t)b*3072;
    for (int i = tid; i < 3072; i += 256) sm[i] = xr[i];
    __syncthreads();

    float red[3];
    float a0 = 0.f, a1 = 0.f, a2 = 0.f;
    float m0 = -1e30f, m1 = -1e30f, m2 = -1e30f;
    for (int i = tid; i < 1024; i += 256) {
        float w = attW[i];
        float av = sm[i], vv = sm[1024 + i], lv = sm[2048 + i];
        a0 = fmaf(av, w, a0); a1 = fmaf(vv, w, a1); a2 = fmaf(lv, w, a2);
        m0 = fmaxf(m0, av);  m1 = fmaxf(m1, vv);  m2 = fmaxf(m2, lv);
    }
    red[0] = a0; red[1] = a1; red[2] = a2;
    blockReduceSumN<3>(red, rbuf);
    float att0 = red[0], att1 = red[1], att2 = red[2];
    red[0] = m0; red[1] = m1; red[2] = m2;
    blockReduceMaxN<3>(red, rbuf);
    float Ma = red[0], Mv = red[1], Ml = red[2];

    float red6[6] = {0.f, 0.f, 0.f, 0.f, 0.f, 0.f};
    for (int i = tid; i < 1024; i += 256) {
        float ea = expf(sm[i] - Ma);
        float ev = expf(sm[1024 + i] - Mv);
        float el = expf(sm[2048 + i] - Ml);
        red6[0] += ea; red6[1] += ev; red6[2] += el;
        red6[3] = fmaf(ea, ev, red6[3]);
        red6[4] = fmaf(ea, el, red6[4]);
        red6[5] = fmaf(ev, el, red6[5]);
    }
    blockReduceSumN<6>(red6, rbuf);

    if (tid == 0) {
        float ab = attb[0];
        float t0 = tanhf(att0 + ab), t1 = tanhf(att1 + ab), t2 = tanhf(att2 + ab);
        float mm = fmaxf(t0, fmaxf(t1, t2));
        float e0 = expf(t0 - mm), e1 = expf(t1 - mm), e2 = expf(t2 - mm);
        float inv = 1.f / (e0 + e1 + e2);
        float sa = e0*inv, sv = e1*inv, sl = e2*inv;
        float dav = red6[3] / (red6[0]*red6[1]);
        float dal = red6[4] / (red6[0]*red6[2]);
        float dvl = red6[5] / (red6[1]*red6[2]);
        float sav = (sa + sv) / (dav + 0.5f);
        float sal = (sa + sl) / (dal + 0.5f);
        float svl = (sl + sv) / (dvl + 0.5f);
        g_wuni[b*3+0] = sa; g_wuni[b*3+1] = sv; g_wuni[b*3+2] = sl;
        g_sbi [b*3+0] = sav; g_sbi[b*3+1] = sal; g_sbi[b*3+2] = svl;
        float m3 = fmaxf(sav, fmaxf(sal, svl));
        float f0 = expf(sav - m3), f1 = expf(sal - m3), f2 = expf(svl - m3);
        float fi = 1.f / (f0 + f1 + f2);
        g_wbi[b*3+0] = f0*fi; g_wbi[b*3+1] = f1*fi; g_wbi[b*3+2] = f2*fi;
        if (wflag) {
            float* o = outW + (size_t)b*12;
            o[0] = sa; o[1] = sv; o[2] = sl;
            o[3] = f0*fi; o[4] = f1*fi; o[5] = f2*fi;
        }
        bc[0] = sa; bc[1] = sv; bc[2] = sl;
    }
    __syncthreads();
    float sa = bc[0], sv = bc[1], sl = bc[2];
    float* ur = g_uni + (size_t)b*1024;
    for (int i = tid; i < 1024; i += 256)
        ur[i] = (sa*sm[i] + sv*sm[1024+i] + sl*sm[2048+i]) * (1.0f/3.0f);
}

// -------------------------- kP: projection GEMM (tf32 mma) ------------------
// C[49152,128] = A[49152,1024] @ g_W1r[1024,128]
// CTA 128x128, 8 warps as 4(m) x 2(n); warp tile 32x64.
__global__ __launch_bounds__(256) void k_proj_mma(const float* __restrict__ x, int which)
{
    const float* A = which ? g_bi3 : x;
    float* C = which ? g_PQ2 : g_PQ1;
    __shared__ float As[128*36];     // row-major [128][36] pad -> conflict-free
    __shared__ float Bs[32*136];     // [32][136]

    int tid = threadIdx.x;
    size_t m0 = (size_t)blockIdx.x * 128;
    int lane = tid & 31, wid = tid >> 5;
    int g = lane >> 2, t4 = lane & 3;
    int wm = wid >> 1, wn = wid & 1;

    float4 acc[2][8] = {};

    for (int kk = 0; kk < 1024; kk += 32) {
        for (int i = tid; i < 1024; i += 256) {
            int r = i >> 3, kq = i & 7;
            float4 v = *(const float4*)&A[(m0 + r)*1024 + kk + kq*4];
            float* d = &As[r*36 + kq*4];
            d[0] = __uint_as_float(f2tf(v.x));
            d[1] = __uint_as_float(f2tf(v.y));
            d[2] = __uint_as_float(f2tf(v.z));
            d[3] = __uint_as_float(f2tf(v.w));
        }
        for (int i = tid; i < 1024; i += 256) {
            int k = i >> 5, nq = i & 31;
            float4 v = *(const float4*)&g_W1r[(size_t)(kk + k)*128 + nq*4];
            float* d = &Bs[k*136 + nq*4];
            d[0] = __uint_as_float(f2tf(v.x));
            d[1] = __uint_as_float(f2tf(v.y));
            d[2] = __uint_as_float(f2tf(v.z));
            d[3] = __uint_as_float(f2tf(v.w));
        }
        __syncthreads();
#pragma unroll
        for (int ks = 0; ks < 4; ks++) {
            unsigned a[2][4], bf[8][2];
#pragma unroll
            for (int m = 0; m < 2; m++) {
                int r = wm*32 + m*16 + g;
                a[m][0] = __float_as_uint(As[r*36 + ks*8 + t4]);
                a[m][1] = __float_as_uint(As[(r+8)*36 + ks*8 + t4]);
                a[m][2] = __float_as_uint(As[r*36 + ks*8 + t4 + 4]);
                a[m][3] = __float_as_uint(As[(r+8)*36 + ks*8 + t4 + 4]);
            }
#pragma unroll
            for (int n = 0; n < 8; n++) {
                int c = wn*64 + n*8 + g;
                bf[n][0] = __float_as_uint(Bs[(ks*8 + t4)*136 + c]);
                bf[n][1] = __float_as_uint(Bs[(ks*8 + t4 + 4)*136 + c]);
            }
#pragma unroll
            for (int m = 0; m < 2; m++)
#pragma unroll
            for (int n = 0; n < 8; n++)
                mma_tf32(acc[m][n], a[m], bf[n]);
        }
        __syncthreads();
    }
#pragma unroll
    for (int m = 0; m < 2; m++) {
        size_t r0 = m0 + wm*32 + m*16 + g;
        size_t r1 = r0 + 8;
#pragma unroll
        for (int n = 0; n < 8; n++) {
            int col = wn*64 + n*8 + t4*2;
            float2 o0; o0.x = acc[m][n].x; o0.y = acc[m][n].y;
            float2 o1; o1.x = acc[m][n].z; o1.y = acc[m][n].w;
            *(float2*)&C[r0*128 + col] = o0;
            *(float2*)&C[r1*128 + col] = o1;
        }
    }
}

// -------------------------- k3: stage-1 gf second layer (tf32 mma) ----------
// C[16384,1024] = lrelu(PQ combos)[.,64] @ W2[64,1024], 3 pairs.
// CTA 128 rows x 64 cols; 8 warps as 4(m) x 2(n); warp tile 32x32.
// dynamic smem: As [128][68] + Bs [64][72]
#define K3_SMEM ((128*68 + 64*72)*4)

__global__ __launch_bounds__(256) void k3_mma(
    const float* __restrict__ W2, const float* __restrict__ b1,
    const float* __restrict__ b2)
{
    extern __shared__ float sm3[];
    float* As = sm3;             // [128][68]
    float* Bs = sm3 + 128*68;    // [64][72]
    int tid = threadIdx.x;
    int b0 = blockIdx.x * 128, n0 = blockIdx.y * 64;

    for (int i = tid; i < 4096; i += 256) {
        int k = i >> 6, n = i & 63;
        Bs[k*72 + n] = __uint_as_float(f2tf(W2[(size_t)k*1024 + n0 + n]));
    }
    int lane = tid & 31, wid = tid >> 5;
    int g = lane >> 2, t4 = lane & 3;
    int wm = wid >> 1, wn = wid & 1;
    int rw = wm*32, cw = wn*32;

    float4 bis[2][4] = {};
#pragma unroll 1
    for (int p = 0; p < 3; p++) {
        int f = (p == 2) ? 1 : 0;
        int s = (p == 0) ? 1 : 2;
        __syncthreads();
        for (int i = tid; i < 8192; i += 256) {
            int r = i >> 6, k = i & 63;
            size_t base = (size_t)(b0 + r) * 3;
            float tv = g_PQ1[(base+f)*128 + k] + g_PQ1[(base+s)*128 + 64 + k] + b1[k];
            tv = tv > 0.f ? tv : 0.2f*tv;
            As[r*68 + k] = __uint_as_float(f2tf(tv));
        }
        __syncthreads();
        float4 acc[2][4] = {};
#pragma unroll
        for (int ks = 0; ks < 8; ks++) {
            unsigned a[2][4], bf[4][2];
#pragma unroll
            for (int m = 0; m < 2; m++) {
                int r = rw + m*16 + g;
                a[m][0] = __float_as_uint(As[r*68 + ks*8 + t4]);
                a[m][1] = __float_as_uint(As[(r+8)*68 + ks*8 + t4]);
                a[m][2] = __float_as_uint(As[r*68 + ks*8 + t4 + 4]);
                a[m][3] = __float_as_uint(As[(r+8)*68 + ks*8 + t4 + 4]);
            }
#pragma unroll
            for (int n = 0; n < 4; n++) {
                int c = cw + n*8 + g;
                bf[n][0] = __float_as_uint(Bs[(ks*8 + t4)*72 + c]);
                bf[n][1] = __float_as_uint(Bs[(ks*8 + t4 + 4)*72 + c]);
            }
#pragma unroll
            for (int m = 0; m < 2; m++)
#pragma unroll
            for (int n = 0; n < 4; n++)
                mma_tf32(acc[m][n], a[m], bf[n]);
        }
#pragma unroll
        for (int m = 0; m < 2; m++) {
            int r0 = b0 + rw + m*16 + g;
            int r1 = r0 + 8;
            float wb0 = g_wbi[r0*3 + p];
            float wb1 = g_wbi[r1*3 + p];
#pragma unroll
            for (int n = 0; n < 4; n++) {
                int col = n0 + cw + n*8 + t4*2;
                float2 b2v = *(const float2*)&b2[col];
                float q;
                float2 o0, o1;
                q = tanhf(acc[m][n].x + b2v.x)*wb0; o0.x = q > 0.f ? q : 0.01f*q;
                q = tanhf(acc[m][n].y + b2v.y)*wb0; o0.y = q > 0.f ? q : 0.01f*q;
                q = tanhf(acc[m][n].z + b2v.x)*wb1; o1.x = q > 0.f ? q : 0.01f*q;
                q = tanhf(acc[m][n].w + b2v.y)*wb1; o1.y = q > 0.f ? q : 0.01f*q;
                bis[m][n].x += o0.x; bis[m][n].y += o0.y;
                bis[m][n].z += o1.x; bis[m][n].w += o1.y;
                *(float2*)&g_bi3[((size_t)r0*3 + p)*1024 + col] = o0;
                *(float2*)&g_bi3[((size_t)r1*3 + p)*1024 + col] = o1;
            }
        }
    }
#pragma unroll
    for (int m = 0; m < 2; m++) {
        size_t r0 = b0 + rw + m*16 + g, r1 = r0 + 8;
#pragma unroll
        for (int n = 0; n < 4; n++) {
            int col = n0 + cw + n*8 + t4*2;
            float2 o0; o0.x = bis[m][n].x; o0.y = bis[m][n].y;
            float2 o1; o1.x = bis[m][n].z; o1.y = bis[m][n].w;
            *(float2*)&g_bisum[r0*1024 + col] = o0;
            *(float2*)&g_bisum[r1*1024 + col] = o1;
        }
    }
}

// -------------------------- k4: stage-2 weights -----------------------------
__global__ __launch_bounds__(256) void k4_tri(
    const float* __restrict__ x, float* __restrict__ outW, int wflag)
{
    __shared__ float sm[6144];       // av, al, vl, a1, v1, l1
    __shared__ float rbuf[12*8];
    int b = blockIdx.x, tid = threadIdx.x;
    const float* br = g_bi3 + (size_t)b*3072;
    const float* xr = x + (size_t)b*3072;
    for (int i = tid; i < 3072; i += 256) { sm[i] = br[i]; sm[3072 + i] = xr[i]; }
    __syncthreads();

    float mx[6] = {-1e30f, -1e30f, -1e30f, -1e30f, -1e30f, -1e30f};
    for (int i = tid; i < 1024; i += 256) {
#pragma unroll
        for (int v = 0; v < 6; v++) mx[v] = fmaxf(mx[v], sm[v*1024 + i]);
    }
    blockReduceMaxN<6>(mx, rbuf);

    float zs[12] = {};
    for (int i = tid; i < 1024; i += 256) {
        float e[6];
#pragma unroll
        for (int v = 0; v < 6; v++) { e[v] = expf(sm[v*1024 + i] - mx[v]); zs[v] += e[v]; }
        zs[6]  = fmaf(e[0], e[2], zs[6]);
        zs[7]  = fmaf(e[0], e[1], zs[7]);
        zs[8]  = fmaf(e[1], e[2], zs[8]);
        zs[9]  = fmaf(e[0], e[5], zs[9]);
        zs[10] = fmaf(e[1], e[4], zs[10]);
        zs[11] = fmaf(e[2], e[3], zs[11]);
    }
    blockReduceSumN<12>(zs, rbuf);

    if (tid == 0) {
        float d0 = zs[6]  / (zs[0]*zs[2]);
        float d1 = zs[7]  / (zs[0]*zs[1]);
        float d2 = zs[8]  / (zs[1]*zs[2]);
        float d3 = zs[9]  / (zs[0]*zs[5]);
        float d4 = zs[10] / (zs[1]*zs[4]);
        float d5 = zs[11] / (zs[2]*zs[3]);
        float sa = g_wuni[b*3+0], sv = g_wuni[b*3+1], sl = g_wuni[b*3+2];
        float sav = g_sbi[b*3+0], sal = g_sbi[b*3+1], svl = g_sbi[b*3+2];
        float n[6];
        n[0] = (sav + svl) / (d0 + 0.5f);
        n[1] = (sav + sal) / (d1 + 0.5f);
        n[2] = (sal + svl) / (d2 + 0.5f);
        n[3] = (sav + sl ) / (d3 + 0.5f);
        n[4] = (sal + sv ) / (d4 + 0.5f);
        n[5] = (sa  + svl) / (d5 + 0.5f);
        float m = n[0];
#pragma unroll
        for (int k = 1; k < 6; k++) m = fmaxf(m, n[k]);
        float e[6], ssum = 0.f;
#pragma unroll
        for (int k = 0; k < 6; k++) { e[k] = expf(n[k] - m); ssum += e[k]; }
        float inv = 1.f / ssum;
#pragma unroll
        for (int k = 0; k < 6; k++) {
            g_wtri[b*6 + k] = e[k]*inv;
            if (wflag) outW[(size_t)b*12 + 6 + k] = e[k]*inv;
        }
    }
}

// -------------------------- k6: stage-2 gf second layer (tf32 mma) ----------
__global__ __launch_bounds__(256) void k6_mma(
    const float* __restrict__ W2, const float* __restrict__ b1,
    const float* __restrict__ b2)
{
    extern __shared__ float sm6[];
    float* As = sm6;             // [128][68]
    float* Bs = sm6 + 128*68;    // [64][72]
    int tid = threadIdx.x;
    int b0 = blockIdx.x * 128, n0 = blockIdx.y * 64;

    for (int i = tid; i < 4096; i += 256) {
        int k = i >> 6, n = i & 63;
        Bs[k*72 + n] = __uint_as_float(f2tf(W2[(size_t)k*1024 + n0 + n]));
    }
    int lane = tid & 31, wid = tid >> 5;
    int g = lane >> 2, t4 = lane & 3;
    int wm = wid >> 1, wn = wid & 1;
    int rw = wm*32, cw = wn*32;

    const int PR[6] = {0, 0, 2, 0, 1, 2};
    const int QR[6] = {2, 1, 1, 2, 1, 0};
    const int QS[6] = {0, 0, 0, 1, 1, 1};   // 0 -> PQ2, 1 -> PQ1

    float4 tri[2][4] = {};
#pragma unroll 1
    for (int p = 0; p < 6; p++) {
        const float* Qb = QS[p] ? g_PQ1 : g_PQ2;
        int fr = PR[p], qr = QR[p];
        __syncthreads();
        for (int i = tid; i < 8192; i += 256) {
            int r = i >> 6, k = i & 63;
            size_t base = (size_t)(b0 + r) * 3;
            float tv = g_PQ2[(base+fr)*128 + k] + Qb[(base+qr)*128 + 64 + k] + b1[k];
            tv = tv > 0.f ? tv : 0.2f*tv;
            As[r*68 + k] = __uint_as_float(f2tf(tv));
        }
        __syncthreads();
        float4 acc[2][4] = {};
#pragma unroll
        for (int ks = 0; ks < 8; ks++) {
            unsigned a[2][4], bf[4][2];
#pragma unroll
            for (int m = 0; m < 2; m++) {
                int r = rw + m*16 + g;
                a[m][0] = __float_as_uint(As[r*68 + ks*8 + t4]);
                a[m][1] = __float_as_uint(As[(r+8)*68 + ks*8 + t4]);
                a[m][2] = __float_as_uint(As[r*68 + ks*8 + t4 + 4]);
                a[m][3] = __float_as_uint(As[(r+8)*68 + ks*8 + t4 + 4]);
            }
#pragma unroll
            for (int n = 0; n < 4; n++) {
                int c = cw + n*8 + g;
                bf[n][0] = __float_as_uint(Bs[(ks*8 + t4)*72 + c]);
                bf[n][1] = __float_as_uint(Bs[(ks*8 + t4 + 4)*72 + c]);
            }
#pragma unroll
            for (int m = 0; m < 2; m++)
#pragma unroll
            for (int n = 0; n < 4; n++)
                mma_tf32(acc[m][n], a[m], bf[n]);
        }
#pragma unroll
        for (int m = 0; m < 2; m++) {
            int r0 = b0 + rw + m*16 + g;
            int r1 = r0 + 8;
            float wt0 = g_wtri[(size_t)r0*6 + p];
            float wt1 = g_wtri[(size_t)r1*6 + p];
#pragma unroll
            for (int n = 0; n < 4; n++) {
                int col = n0 + cw + n*8 + t4*2;
                float2 b2v = *(const float2*)&b2[col];
                float q;
                q = tanhf(acc[m][n].x + b2v.x)*wt0; tri[m][n].x += (q > 0.f ? q : 0.01f*q);
                q = tanhf(acc[m][n].y + b2v.y)*wt0; tri[m][n].y += (q > 0.f ? q : 0.01f*q);
                q = tanhf(acc[m][n].z + b2v.x)*wt1; tri[m][n].z += (q > 0.f ? q : 0.01f*q);
                q = tanhf(acc[m][n].w + b2v.y)*wt1; tri[m][n].w += (q > 0.f ? q : 0.01f*q);
            }
        }
    }
#pragma unroll
    for (int m = 0; m < 2; m++) {
        size_t r0 = b0 + rw + m*16 + g, r1 = r0 + 8;
#pragma unroll
        for (int n = 0; n < 4; n++) {
            int col = n0 + cw + n*8 + t4*2;
            float2 o0; o0.x = tri[m][n].x; o0.y = tri[m][n].y;
            float2 o1; o1.x = tri[m][n].z; o1.y = tri[m][n].w;
            *(float2*)&g_tri[r0*1024 + col] = o0;
            *(float2*)&g_tri[r1*1024 + col] = o1;
        }
    }
}

// -------------------------- k7: fused head ----------------------------------
__global__ __launch_bounds__(256) void k7_final(
    const float* __restrict__ bng, const float* __restrict__ bnb,
    const float* __restrict__ l1W, const float* __restrict__ l1b,
    const float* __restrict__ l2W, const float* __restrict__ l2b,
    const float* __restrict__ l3W, const float* __restrict__ l3b,
    float* __restrict__ out)
{
    __shared__ float pool[11264];
    float* sA = pool;
    float* sW = pool + 2048;
    float* Y1 = pool + 4096;
    float* Y2 = pool + 7424;
    float* Y3 = pool + 10752;
    int tid = threadIdx.x;
    int b0 = blockIdx.x * 64;
    int rr = (tid >> 4) * 4, cc = (tid & 15) * 4;
    const float BNS = rsqrtf(1.0f + 1e-5f);

    float acc[4][4] = {};
    for (int kk = 0; kk < 3072; kk += 32) {
        int region = kk >> 10;
        const float* src = region == 0 ? g_uni : (region == 1 ? g_bisum : g_tri);
        float mult = region == 0 ? 1.f : (region == 1 ? (1.f/3.f) : (1.f/6.f));
        __syncthreads();
        for (int i = tid; i < 2048; i += 256) {
            int r = i >> 5, k = i & 31;
            int j = kk + k;
            float vv = src[(size_t)(b0 + r)*1024 + (j & 1023)];
            sA[r*32 + k] = vv * (mult * BNS * bng[j]) + bnb[j];
        }
        for (int i = tid; i < 2048; i += 256) {
            int k = i >> 6, n = i & 63;
            int j = kk + k;
            sW[k*64 + n] = (n < 50) ? l1W[(size_t)j*50 + n] : 0.f;
        }
        __syncthreads();
#pragma unroll 8
        for (int k = 0; k < 32; k++) {
            float4 w = *(const float4*)&sW[k*64 + cc];
#pragma unroll
            for (int u = 0; u < 4; u++) {
                float a = sA[(rr + u)*32 + k];
                acc[u][0] = fmaf(a, w.x, acc[u][0]);
                acc[u][1] = fmaf(a, w.y, acc[u][1]);
                acc[u][2] = fmaf(a, w.z, acc[u][2]);
                acc[u][3] = fmaf(a, w.w, acc[u][3]);
            }
        }
    }
    __syncthreads();
#pragma unroll
    for (int u = 0; u < 4; u++)
#pragma unroll
    for (int v = 0; v < 4; v++)
        if (cc + v < 50)
            Y1[(rr + u)*52 + cc + v] = tanhf(acc[u][v] + l1b[cc + v]);
    for (int i = tid; i < 2500; i += 256) {
        int k = i / 50, c = i - k*50;
        pool[k*52 + c] = l2W[i];
    }
    for (int i = tid; i < 400; i += 256) pool[2600 + i] = l3W[i];
    __syncthreads();

    float acc2[4][4] = {};
#pragma unroll 5
    for (int k = 0; k < 50; k++) {
        float4 w = *(const float4*)&pool[k*52 + cc];
#pragma unroll
        for (int u = 0; u < 4; u++) {
            float a = Y1[(rr + u)*52 + k];
            acc2[u][0] = fmaf(a, w.x, acc2[u][0]);
            acc2[u][1] = fmaf(a, w.y, acc2[u][1]);
            acc2[u][2] = fmaf(a, w.z, acc2[u][2]);
            acc2[u][3] = fmaf(a, w.w, acc2[u][3]);
        }
    }
#pragma unroll
    for (int u = 0; u < 4; u++)
#pragma unroll
    for (int v = 0; v < 4; v++)
        if (cc + v < 50)
            Y2[(rr + u)*52 + cc + v] = tanhf(acc2[u][v] + l2b[cc + v]);
    __syncthreads();

    for (int t = tid; t < 512; t += 256) {
        int r = t >> 3, c = t & 7;
        float a = l3b[c];
        for (int k = 0; k < 50; k++)
            a = fmaf(Y2[r*52 + k], pool[2600 + k*8 + c], a);
        Y3[r*8 + c] = a;
    }
    __syncthreads();
    if (tid < 64) {
        int r = tid;
        float m = -1e30f;
#pragma unroll
        for (int c = 0; c < 8; c++) m = fmaxf(m, Y3[r*8 + c]);
        float e[8], s = 0.f;
#pragma unroll
        for (int c = 0; c < 8; c++) { e[c] = expf(Y3[r*8 + c] - m); s += e[c]; }
        float inv = 1.f / s;
        float* orow = out + (size_t)(b0 + r)*8;
#pragma unroll
        for (int c = 0; c < 8; c++) orow[c] = e[c]*inv;
    }
}

// -------------------------- launch ------------------------------------------
extern "C" void kernel_launch(void* const* d_in, const int* in_sizes, int n_in,
                              void* d_out, int out_size)
{
    const float* x    = (const float*)d_in[0];
    const float* attW = (const float*)d_in[1];
    const float* attb = (const float*)d_in[2];
    const float* gfW1 = (const float*)d_in[3];
    const float* gfb1 = (const float*)d_in[4];
    const float* gfW2 = (const float*)d_in[5];
    const float* gfb2 = (const float*)d_in[6];
    const float* bng  = (const float*)d_in[7];
    const float* bnb  = (const float*)d_in[8];
    const float* l1W  = (const float*)d_in[9];
    const float* l1b  = (const float*)d_in[10];
    const float* l2W  = (const float*)d_in[11];
    const float* l2b  = (const float*)d_in[12];
    const float* l3W  = (const float*)d_in[13];
    const float* l3b  = (const float*)d_in[14];
    float* out  = (float*)d_out;
    int wflag = (out_size >= NB*20) ? 1 : 0;
    float* outW = out + (size_t)NB*8;

    cudaFuncSetAttribute(k3_mma, cudaFuncAttributeMaxDynamicSharedMemorySize, K3_SMEM);
    cudaFuncSetAttribute(k6_mma, cudaFuncAttributeMaxDynamicSharedMemorySize, K3_SMEM);

    k0_w1r<<<512, 256>>>(gfW1);
    k1_att<<<NB, 256>>>(x, attW, attb, outW, wflag);
    k_proj_mma<<<NR3/128, 256>>>(x, 0);
    dim3 g3(NB/128, 16);
    k3_mma<<<g3, 256, K3_SMEM>>>(gfW2, gfb1, gfb2);
    k4_tri<<<NB, 256>>>(x, outW, wflag);
    k_proj_mma<<<NR3/128, 256>>>(x, 1);
    k6_mma<<<g3, 256, K3_SMEM>>>(gfW2, gfb1, gfb2);
    k7_final<<<NB/64, 256>>>(bng, bnb, l1W, l1b, l2W, l2b, l3W, l3b, out);
}

// round 4
// speedup vs baseline: 2.6441x; 1.9993x over previous
#include <cuda_runtime.h>
#include <cstdint>
#include <cstddef>

// ---------------------------------------------------------------------------
// graph12 — Round 4: precomputed tf32 activations + cp.async staging.
//  k0x:  prep (W1r tf32, W2r tf32, l1Wp pad+tf32, bnsc)
//  k1:   attention + stage-1 stats (fp32, float4 loads)
//  kP(0):PQ1 = x @ W1r             (tf32 mma, double-buffered)
//  kact1: stage-1 activations (3 planes, tf32-rounded)
//  k3:   stage-1 second layer      (tf32 mma, cp.async staging)
//  k4:   stage-2 weights + bisum   (fp32)
//  kP(1):PQ2 = g_bi3 @ W1r
//  kact2: stage-2 activations (6 planes)
//  k6:   stage-2 second layer      (tf32 mma)
//  k7:   BN + head layer1 tf32 mma + small fp32 layers + softmax
// ---------------------------------------------------------------------------

#define NB    16384
#define ND    1024
#define NR3   (NB*3)          // 49152

__device__ float g_W1r  [1024*128];          // tf32-rounded
__device__ float g_W2r  [64*1024];           // tf32-rounded
__device__ float g_l1Wp [3072*64];           // tf32-rounded, padded 50->64
__device__ float g_bnsc [3072];              // BNS * gamma * region-mult
__device__ float g_PQ1  [(size_t)NR3*128];
__device__ float g_PQ2  [(size_t)NR3*128];
__device__ float g_act1 [(size_t)3*NB*64];   // tf32-rounded lrelu activations
__device__ float g_act2 [(size_t)6*NB*64];
__device__ float g_uni  [(size_t)NB*ND];
__device__ float g_bi3  [(size_t)NR3*ND];    // [b][p][1024]
__device__ float g_bisum[(size_t)NB*ND];     // sum of 3 planes (NOT /3)
__device__ float g_tri  [(size_t)NB*ND];     // sum of 6 (NOT /6)
__device__ float g_wuni [NB*3];
__device__ float g_wbi  [NB*3];
__device__ float g_sbi  [NB*3];
__device__ float g_wtri [NB*6];

// -------------------------- helpers -----------------------------------------
__device__ __forceinline__ float f2tf_f(float f) {
    unsigned r;
    asm("cvt.rna.tf32.f32 %0, %1;" : "=r"(r) : "f"(f));
    return __uint_as_float(r);
}

__device__ __forceinline__ void mma_tf32(float4& d, const unsigned* a, const unsigned* b) {
    asm volatile(
        "mma.sync.aligned.m16n8k8.row.col.f32.tf32.tf32.f32 "
        "{%0,%1,%2,%3}, {%4,%5,%6,%7}, {%8,%9}, {%0,%1,%2,%3};"
        : "+f"(d.x), "+f"(d.y), "+f"(d.z), "+f"(d.w)
        : "r"(a[0]), "r"(a[1]), "r"(a[2]), "r"(a[3]), "r"(b[0]), "r"(b[1]));
}

__device__ __forceinline__ void cpasync16(float* dst_smem, const float* src) {
    unsigned d = (unsigned)__cvta_generic_to_shared(dst_smem);
    asm volatile("cp.async.cg.shared.global [%0], [%1], 16;" :: "r"(d), "l"(src));
}
#define CP_COMMIT  asm volatile("cp.async.commit_group;")
#define CP_WAIT0   asm volatile("cp.async.wait_group 0;")

// -------------------------- block reductions (256 thr) ----------------------
template<int NV>
__device__ __forceinline__ void blockReduceSumN(float* v, float* rbuf) {
    int tid = threadIdx.x, lane = tid & 31, w = tid >> 5;
#pragma unroll
    for (int n = 0; n < NV; n++) {
        float x = v[n];
#pragma unroll
        for (int o = 16; o > 0; o >>= 1) x += __shfl_down_sync(0xffffffffu, x, o);
        if (lane == 0) rbuf[n*8 + w] = x;
    }
    __syncthreads();
    if (tid < NV) {
        float s = rbuf[tid*8];
#pragma unroll
        for (int q = 1; q < 8; q++) s += rbuf[tid*8 + q];
        rbuf[tid*8] = s;
    }
    __syncthreads();
#pragma unroll
    for (int n = 0; n < NV; n++) v[n] = rbuf[n*8];
    __syncthreads();
}

template<int NV>
__device__ __forceinline__ void blockReduceMaxN(float* v, float* rbuf) {
    int tid = threadIdx.x, lane = tid & 31, w = tid >> 5;
#pragma unroll
    for (int n = 0; n < NV; n++) {
        float x = v[n];
#pragma unroll
        for (int o = 16; o > 0; o >>= 1) x = fmaxf(x, __shfl_down_sync(0xffffffffu, x, o));
        if (lane == 0) rbuf[n*8 + w] = x;
    }
    __syncthreads();
    if (tid < NV) {
        float s = rbuf[tid*8];
#pragma unroll
        for (int q = 1; q < 8; q++) s = fmaxf(s, rbuf[tid*8 + q]);
        rbuf[tid*8] = s;
    }
    __syncthreads();
#pragma unroll
    for (int n = 0; n < NV; n++) v[n] = rbuf[n*8];
    __syncthreads();
}

// -------------------------- k0x: prep ---------------------------------------
__global__ void k0_prep(const float* __restrict__ W1, const float* __restrict__ W2,
                        const float* __restrict__ l1W, const float* __restrict__ bng)
{
    int i = blockIdx.x * 256 + threadIdx.x;
    if (i < 131072) {                         // W1r
        int k = i >> 7, j = i & 127;
        float v = (j < 64) ? W1[(size_t)k*64 + j] : W1[(size_t)(1024 + k)*64 + (j - 64)];
        g_W1r[i] = f2tf_f(v);
    } else if (i < 196608) {                  // W2r
        int i2 = i - 131072;
        g_W2r[i2] = f2tf_f(W2[i2]);
    } else if (i < 393216) {                  // l1Wp
        int i3 = i - 196608;
        int row = i3 >> 6, c = i3 & 63;
        g_l1Wp[i3] = (c < 50) ? f2tf_f(l1W[(size_t)row*50 + c]) : 0.f;
    } else if (i < 396288) {                  // bnsc
        int j = i - 393216;
        float mult = (j < 1024) ? 1.f : ((j < 2048) ? (1.f/3.f) : (1.f/6.f));
        g_bnsc[j] = bng[j] * rsqrtf(1.0f + 1e-5f) * mult;
    }
}

// -------------------------- k1: attention + stage-1 stats -------------------
__global__ __launch_bounds__(256) void k1_att(
    const float* __restrict__ x, const float* __restrict__ attW,
    const float* __restrict__ attb, float* __restrict__ outW, int wflag)
{
    __shared__ float sm[3072];
    __shared__ float rbuf[6*8];
    __shared__ float bc[4];
    int b = blockIdx.x, tid = threadIdx.x;
    const float4* xr4 = (const float4*)(x + (size_t)b*3072);
    for (int i = tid; i < 768; i += 256) ((float4*)sm)[i] = xr4[i];
    __syncthreads();

    float red[3];
    float a0 = 0.f, a1 = 0.f, a2 = 0.f;
    float m0 = -1e30f, m1 = -1e30f, m2 = -1e30f;
    for (int i = tid; i < 1024; i += 256) {
        float w = attW[i];
        float av = sm[i], vv = sm[1024 + i], lv = sm[2048 + i];
        a0 = fmaf(av, w, a0); a1 = fmaf(vv, w, a1); a2 = fmaf(lv, w, a2);
        m0 = fmaxf(m0, av);  m1 = fmaxf(m1, vv);  m2 = fmaxf(m2, lv);
    }
    red[0] = a0; red[1] = a1; red[2] = a2;
    blockReduceSumN<3>(red, rbuf);
    float att0 = red[0], att1 = red[1], att2 = red[2];
    red[0] = m0; red[1] = m1; red[2] = m2;
    blockReduceMaxN<3>(red, rbuf);
    float Ma = red[0], Mv = red[1], Ml = red[2];

    float red6[6] = {0.f, 0.f, 0.f, 0.f, 0.f, 0.f};
    for (int i = tid; i < 1024; i += 256) {
        float ea = expf(sm[i] - Ma);
        float ev = expf(sm[1024 + i] - Mv);
        float el = expf(sm[2048 + i] - Ml);
        red6[0] += ea; red6[1] += ev; red6[2] += el;
        red6[3] = fmaf(ea, ev, red6[3]);
        red6[4] = fmaf(ea, el, red6[4]);
        red6[5] = fmaf(ev, el, red6[5]);
    }
    blockReduceSumN<6>(red6, rbuf);

    if (tid == 0) {
        float ab = attb[0];
        float t0 = tanhf(att0 + ab), t1 = tanhf(att1 + ab), t2 = tanhf(att2 + ab);
        float mm = fmaxf(t0, fmaxf(t1, t2));
        float e0 = expf(t0 - mm), e1 = expf(t1 - mm), e2 = expf(t2 - mm);
        float inv = 1.f / (e0 + e1 + e2);
        float sa = e0*inv, sv = e1*inv, sl = e2*inv;
        float dav = red6[3] / (red6[0]*red6[1]);
        float dal = red6[4] / (red6[0]*red6[2]);
        float dvl = red6[5] / (red6[1]*red6[2]);
        float sav = (sa + sv) / (dav + 0.5f);
        float sal = (sa + sl) / (dal + 0.5f);
        float svl = (sl + sv) / (dvl + 0.5f);
        g_wuni[b*3+0] = sa; g_wuni[b*3+1] = sv; g_wuni[b*3+2] = sl;
        g_sbi [b*3+0] = sav; g_sbi[b*3+1] = sal; g_sbi[b*3+2] = svl;
        float m3 = fmaxf(sav, fmaxf(sal, svl));
        float f0 = expf(sav - m3), f1 = expf(sal - m3), f2 = expf(svl - m3);
        float fi = 1.f / (f0 + f1 + f2);
        g_wbi[b*3+0] = f0*fi; g_wbi[b*3+1] = f1*fi; g_wbi[b*3+2] = f2*fi;
        if (wflag) {
            float* o = outW + (size_t)b*12;
            o[0] = sa; o[1] = sv; o[2] = sl;
            o[3] = f0*fi; o[4] = f1*fi; o[5] = f2*fi;
        }
        bc[0] = sa; bc[1] = sv; bc[2] = sl;
    }
    __syncthreads();
    float sa = bc[0], sv = bc[1], sl = bc[2];
    float* ur = g_uni + (size_t)b*1024;
    for (int i = tid; i < 1024; i += 256)
        ur[i] = (sa*sm[i] + sv*sm[1024+i] + sl*sm[2048+i]) * (1.0f/3.0f);
}

// -------------------------- kP: projection GEMM (tf32 mma, dbl-buffered) ----
// C[49152,128] = A[49152,1024] @ g_W1r[1024,128]
#define KP_SMEM ((2*(128*36 + 32*136))*4)
__global__ __launch_bounds__(256) void k_proj_mma(const float* __restrict__ x, int which)
{
    const float* A = which ? g_bi3 : x;
    float* C = which ? g_PQ2 : g_PQ1;
    extern __shared__ float smp[];
    float* AsB = smp;                 // [2][128*36]
    float* BsB = smp + 2*128*36;      // [2][32*136]

    int tid = threadIdx.x;
    size_t m0 = (size_t)blockIdx.x * 128;
    int lane = tid & 31, wid = tid >> 5;
    int g = lane >> 2, t4 = lane & 3;
    int wm = wid >> 1, wn = wid & 1;

    float4 acc[2][8] = {};

    // prologue: tile 0 (B cp.async, A register->smem with cvt)
#pragma unroll
    for (int j = 0; j < 4; j++) {
        int i = tid + j*256;
        int k = i >> 5, c4 = i & 31;
        cpasync16(&BsB[k*136 + c4*4], &g_W1r[(size_t)k*128 + c4*4]);
    }
    CP_COMMIT;
#pragma unroll
    for (int j = 0; j < 4; j++) {
        int i = tid + j*256;
        int r = i >> 3, kq = i & 7;
        float4 v = *(const float4*)&A[(m0 + r)*1024 + kq*4];
        float* d = &AsB[r*36 + kq*4];
        d[0] = f2tf_f(v.x); d[1] = f2tf_f(v.y); d[2] = f2tf_f(v.z); d[3] = f2tf_f(v.w);
    }

    for (int t = 0; t < 32; t++) {
        int cur = t & 1, nxt = cur ^ 1;
        float* Ac = AsB + cur*128*36;
        float* Bc = BsB + cur*32*136;
        bool pf = (t + 1 < 32);
        float4 vA[4];
        if (pf) {
            int kk = (t + 1) * 32;
#pragma unroll
            for (int j = 0; j < 4; j++) {
                int i = tid + j*256;
                int r = i >> 3, kq = i & 7;
                vA[j] = *(const float4*)&A[(m0 + r)*1024 + kk + kq*4];
            }
        }
        CP_WAIT0;
        __syncthreads();
        if (pf) {
            int kk = (t + 1) * 32;
#pragma unroll
            for (int j = 0; j < 4; j++) {
                int i = tid + j*256;
                int k = i >> 5, c4 = i & 31;
                cpasync16(&BsB[nxt*32*136 + k*136 + c4*4],
                          &g_W1r[(size_t)(kk + k)*128 + c4*4]);
            }
            CP_COMMIT;
        }
#pragma unroll
        for (int ks = 0; ks < 4; ks++) {
            unsigned a[2][4], bf[8][2];
#pragma unroll
            for (int m = 0; m < 2; m++) {
                int r = wm*32 + m*16 + g;
                a[m][0] = __float_as_uint(Ac[r*36 + ks*8 + t4]);
                a[m][1] = __float_as_uint(Ac[(r+8)*36 + ks*8 + t4]);
                a[m][2] = __float_as_uint(Ac[r*36 + ks*8 + t4 + 4]);
                a[m][3] = __float_as_uint(Ac[(r+8)*36 + ks*8 + t4 + 4]);
            }
#pragma unroll
            for (int n = 0; n < 8; n++) {
                int c = wn*64 + n*8 + g;
                bf[n][0] = __float_as_uint(Bc[(ks*8 + t4)*136 + c]);
                bf[n][1] = __float_as_uint(Bc[(ks*8 + t4 + 4)*136 + c]);
            }
#pragma unroll
            for (int m = 0; m < 2; m++)
#pragma unroll
            for (int n = 0; n < 8; n++)
                mma_tf32(acc[m][n], a[m], bf[n]);
        }
        if (pf) {
#pragma unroll
            for (int j = 0; j < 4; j++) {
                int i = tid + j*256;
                int r = i >> 3, kq = i & 7;
                float* d = &AsB[nxt*128*36 + r*36 + kq*4];
                d[0] = f2tf_f(vA[j].x); d[1] = f2tf_f(vA[j].y);
                d[2] = f2tf_f(vA[j].z); d[3] = f2tf_f(vA[j].w);
            }
        }
    }
#pragma unroll
    for (int m = 0; m < 2; m++) {
        size_t r0 = m0 + wm*32 + m*16 + g;
        size_t r1 = r0 + 8;
#pragma unroll
        for (int n = 0; n < 8; n++) {
            int col = wn*64 + n*8 + t4*2;
            float2 o0; o0.x = acc[m][n].x; o0.y = acc[m][n].y;
            float2 o1; o1.x = acc[m][n].z; o1.y = acc[m][n].w;
            *(float2*)&C[r0*128 + col] = o0;
            *(float2*)&C[r1*128 + col] = o1;
        }
    }
}

// -------------------------- kact1: stage-1 activations ----------------------
#define ACT1_SMEM ((96*128 + 64)*4)
__global__ __launch_bounds__(256) void kact1(const float* __restrict__ b1)
{
    extern __shared__ float smA1[];
    float* smP = smA1;            // [96][128]
    float* b1s = smA1 + 96*128;
    int tid = threadIdx.x;
    int b0 = blockIdx.x * 32;
    const float4* src = (const float4*)(g_PQ1 + (size_t)(3*b0)*128);
    for (int i = tid; i < 3072; i += 256) ((float4*)smP)[i] = src[i];
    if (tid < 64) b1s[tid] = b1[tid];
    __syncthreads();
    for (int i = tid; i < 6144; i += 256) {
        int p = i >> 11, r = (i >> 6) & 31, k = i & 63;
        int f = (p == 2) ? 1 : 0;
        int s = (p == 0) ? 1 : 2;
        float tv = smP[(3*r + f)*128 + k] + smP[(3*r + s)*128 + 64 + k] + b1s[k];
        tv = tv > 0.f ? tv : 0.2f*tv;
        g_act1[((size_t)p*NB + b0 + r)*64 + k] = f2tf_f(tv);
    }
}

// -------------------------- kact2: stage-2 activations ----------------------
#define ACT2_SMEM ((2*96*128 + 64)*4)
__global__ __launch_bounds__(256) void kact2(const float* __restrict__ b1)
{
    extern __shared__ float smA2[];
    float* smP2 = smA2;             // [96][128] from PQ2
    float* smP1 = smA2 + 96*128;    // [96][128] from PQ1
    float* b1s  = smA2 + 2*96*128;
    int tid = threadIdx.x;
    int b0 = blockIdx.x * 32;
    const float4* s2 = (const float4*)(g_PQ2 + (size_t)(3*b0)*128);
    const float4* s1 = (const float4*)(g_PQ1 + (size_t)(3*b0)*128);
    for (int i = tid; i < 3072; i += 256) { ((float4*)smP2)[i] = s2[i]; ((float4*)smP1)[i] = s1[i]; }
    if (tid < 64) b1s[tid] = b1[tid];
    __syncthreads();
    const int PR[6] = {0, 0, 2, 0, 1, 2};
    const int QR[6] = {2, 1, 1, 2, 1, 0};
    const int QS[6] = {0, 0, 0, 1, 1, 1};   // 0 -> PQ2, 1 -> PQ1
    for (int i = tid; i < 12288; i += 256) {
        int p = i >> 11, r = (i >> 6) & 31, k = i & 63;
        const float* Qb = QS[p] ? smP1 : smP2;
        float tv = smP2[(3*r + PR[p])*128 + k] + Qb[(3*r + QR[p])*128 + 64 + k] + b1s[k];
        tv = tv > 0.f ? tv : 0.2f*tv;
        g_act2[((size_t)p*NB + b0 + r)*64 + k] = f2tf_f(tv);
    }
}

// -------------------------- k3: stage-1 gf second layer ---------------------
// CTA 128 rows x 64 cols; 8 warps 4(m) x 2(n); warp tile 32x32.
#define K3_SMEM ((128*68 + 64*72)*4)
__global__ __launch_bounds__(256) void k3_mma(const float* __restrict__ b2)
{
    extern __shared__ float sm3[];
    float* As = sm3;             // [128][68]
    float* Bs = sm3 + 128*68;    // [64][72]
    int tid = threadIdx.x;
    int b0 = blockIdx.x * 128, n0 = blockIdx.y * 64;

    // B once (cp.async, pre-rounded W2r)
    for (int i = tid; i < 1024; i += 256) {
        int k = i >> 4, c4 = i & 15;
        cpasync16(&Bs[k*72 + c4*4], &g_W2r[(size_t)k*1024 + n0 + c4*4]);
    }
    int lane = tid & 31, wid = tid >> 5;
    int g = lane >> 2, t4 = lane & 3;
    int wm = wid >> 1, wn = wid & 1;
    int rw = wm*32, cw = wn*32;

#pragma unroll 1
    for (int p = 0; p < 3; p++) {
        if (p) __syncthreads();
        const float* Ap = g_act1 + ((size_t)p*NB + b0)*64;
        for (int i = tid; i < 2048; i += 256) {
            int r = i >> 4, c4 = i & 15;
            cpasync16(&As[r*68 + c4*4], &Ap[(size_t)r*64 + c4*4]);
        }
        CP_COMMIT; CP_WAIT0;
        __syncthreads();
        float4 acc[2][4] = {};
#pragma unroll
        for (int ks = 0; ks < 8; ks++) {
            unsigned a[2][4], bf[4][2];
#pragma unroll
            for (int m = 0; m < 2; m++) {
                int r = rw + m*16 + g;
                a[m][0] = __float_as_uint(As[r*68 + ks*8 + t4]);
                a[m][1] = __float_as_uint(As[(r+8)*68 + ks*8 + t4]);
                a[m][2] = __float_as_uint(As[r*68 + ks*8 + t4 + 4]);
                a[m][3] = __float_as_uint(As[(r+8)*68 + ks*8 + t4 + 4]);
            }
#pragma unroll
            for (int n = 0; n < 4; n++) {
                int c = cw + n*8 + g;
                bf[n][0] = __float_as_uint(Bs[(ks*8 + t4)*72 + c]);
                bf[n][1] = __float_as_uint(Bs[(ks*8 + t4 + 4)*72 + c]);
            }
#pragma unroll
            for (int m = 0; m < 2; m++)
#pragma unroll
            for (int n = 0; n < 4; n++)
                mma_tf32(acc[m][n], a[m], bf[n]);
        }
#pragma unroll
        for (int m = 0; m < 2; m++) {
            int r0 = b0 + rw + m*16 + g;
            int r1 = r0 + 8;
            float wb0 = g_wbi[r0*3 + p];
            float wb1 = g_wbi[r1*3 + p];
#pragma unroll
            for (int n = 0; n < 4; n++) {
                int col = n0 + cw + n*8 + t4*2;
                float2 b2v = *(const float2*)&b2[col];
                float q;
                float2 o0, o1;
                q = tanhf(acc[m][n].x + b2v.x)*wb0; o0.x = q > 0.f ? q : 0.01f*q;
                q = tanhf(acc[m][n].y + b2v.y)*wb0; o0.y = q > 0.f ? q : 0.01f*q;
                q = tanhf(acc[m][n].z + b2v.x)*wb1; o1.x = q > 0.f ? q : 0.01f*q;
                q = tanhf(acc[m][n].w + b2v.y)*wb1; o1.y = q > 0.f ? q : 0.01f*q;
                *(float2*)&g_bi3[((size_t)r0*3 + p)*1024 + col] = o0;
                *(float2*)&g_bi3[((size_t)r1*3 + p)*1024 + col] = o1;
            }
        }
    }
}

// -------------------------- k4: stage-2 weights + bisum ---------------------
__global__ __launch_bounds__(256) void k4_tri(
    const float* __restrict__ x, float* __restrict__ outW, int wflag)
{
    __shared__ float sm[6144];       // av, al, vl, a1, v1, l1
    __shared__ float rbuf[12*8];
    int b = blockIdx.x, tid = threadIdx.x;
    const float4* br4 = (const float4*)(g_bi3 + (size_t)b*3072);
    const float4* xr4 = (const float4*)(x + (size_t)b*3072);
    for (int i = tid; i < 768; i += 256) {
        ((float4*)sm)[i] = br4[i];
        ((float4*)sm)[768 + i] = xr4[i];
    }
    __syncthreads();

    // bisum
    for (int i = tid; i < 1024; i += 256)
        g_bisum[(size_t)b*1024 + i] = sm[i] + sm[1024+i] + sm[2048+i];

    float mx[6] = {-1e30f, -1e30f, -1e30f, -1e30f, -1e30f, -1e30f};
    for (int i = tid; i < 1024; i += 256) {
#pragma unroll
        for (int v = 0; v < 6; v++) mx[v] = fmaxf(mx[v], sm[v*1024 + i]);
    }
    blockReduceMaxN<6>(mx, rbuf);

    float zs[12] = {};
    for (int i = tid; i < 1024; i += 256) {
        float e[6];
#pragma unroll
        for (int v = 0; v < 6; v++) { e[v] = expf(sm[v*1024 + i] - mx[v]); zs[v] += e[v]; }
        zs[6]  = fmaf(e[0], e[2], zs[6]);
        zs[7]  = fmaf(e[0], e[1], zs[7]);
        zs[8]  = fmaf(e[1], e[2], zs[8]);
        zs[9]  = fmaf(e[0], e[5], zs[9]);
        zs[10] = fmaf(e[1], e[4], zs[10]);
        zs[11] = fmaf(e[2], e[3], zs[11]);
    }
    blockReduceSumN<12>(zs, rbuf);

    if (tid == 0) {
        float d0 = zs[6]  / (zs[0]*zs[2]);
        float d1 = zs[7]  / (zs[0]*zs[1]);
        float d2 = zs[8]  / (zs[1]*zs[2]);
        float d3 = zs[9]  / (zs[0]*zs[5]);
        float d4 = zs[10] / (zs[1]*zs[4]);
        float d5 = zs[11] / (zs[2]*zs[3]);
        float sa = g_wuni[b*3+0], sv = g_wuni[b*3+1], sl = g_wuni[b*3+2];
        float sav = g_sbi[b*3+0], sal = g_sbi[b*3+1], svl = g_sbi[b*3+2];
        float n[6];
        n[0] = (sav + svl) / (d0 + 0.5f);
        n[1] = (sav + sal) / (d1 + 0.5f);
        n[2] = (sal + svl) / (d2 + 0.5f);
        n[3] = (sav + sl ) / (d3 + 0.5f);
        n[4] = (sal + sv ) / (d4 + 0.5f);
        n[5] = (sa  + svl) / (d5 + 0.5f);
        float m = n[0];
#pragma unroll
        for (int k = 1; k < 6; k++) m = fmaxf(m, n[k]);
        float e[6], ssum = 0.f;
#pragma unroll
        for (int k = 0; k < 6; k++) { e[k] = expf(n[k] - m); ssum += e[k]; }
        float inv = 1.f / ssum;
#pragma unroll
        for (int k = 0; k < 6; k++) {
            g_wtri[b*6 + k] = e[k]*inv;
            if (wflag) outW[(size_t)b*12 + 6 + k] = e[k]*inv;
        }
    }
}

// -------------------------- k6: stage-2 gf second layer ---------------------
__global__ __launch_bounds__(256) void k6_mma(const float* __restrict__ b2)
{
    extern __shared__ float sm6[];
    float* As = sm6;             // [128][68]
    float* Bs = sm6 + 128*68;    // [64][72]
    int tid = threadIdx.x;
    int b0 = blockIdx.x * 128, n0 = blockIdx.y * 64;

    for (int i = tid; i < 1024; i += 256) {
        int k = i >> 4, c4 = i & 15;
        cpasync16(&Bs[k*72 + c4*4], &g_W2r[(size_t)k*1024 + n0 + c4*4]);
    }
    int lane = tid & 31, wid = tid >> 5;
    int g = lane >> 2, t4 = lane & 3;
    int wm = wid >> 1, wn = wid & 1;
    int rw = wm*32, cw = wn*32;

    float4 tri[2][4] = {};
#pragma unroll 1
    for (int p = 0; p < 6; p++) {
        if (p) __syncthreads();
        const float* Ap = g_act2 + ((size_t)p*NB + b0)*64;
        for (int i = tid; i < 2048; i += 256) {
            int r = i >> 4, c4 = i & 15;
            cpasync16(&As[r*68 + c4*4], &Ap[(size_t)r*64 + c4*4]);
        }
        CP_COMMIT; CP_WAIT0;
        __syncthreads();
        float4 acc[2][4] = {};
#pragma unroll
        for (int ks = 0; ks < 8; ks++) {
            unsigned a[2][4], bf[4][2];
#pragma unroll
            for (int m = 0; m < 2; m++) {
                int r = rw + m*16 + g;
                a[m][0] = __float_as_uint(As[r*68 + ks*8 + t4]);
                a[m][1] = __float_as_uint(As[(r+8)*68 + ks*8 + t4]);
                a[m][2] = __float_as_uint(As[r*68 + ks*8 + t4 + 4]);
                a[m][3] = __float_as_uint(As[(r+8)*68 + ks*8 + t4 + 4]);
            }
#pragma unroll
            for (int n = 0; n < 4; n++) {
                int c = cw + n*8 + g;
                bf[n][0] = __float_as_uint(Bs[(ks*8 + t4)*72 + c]);
                bf[n][1] = __float_as_uint(Bs[(ks*8 + t4 + 4)*72 + c]);
            }
#pragma unroll
            for (int m = 0; m < 2; m++)
#pragma unroll
            for (int n = 0; n < 4; n++)
                mma_tf32(acc[m][n], a[m], bf[n]);
        }
#pragma unroll
        for (int m = 0; m < 2; m++) {
            int r0 = b0 + rw + m*16 + g;
            int r1 = r0 + 8;
            float wt0 = g_wtri[(size_t)r0*6 + p];
            float wt1 = g_wtri[(size_t)r1*6 + p];
#pragma unroll
            for (int n = 0; n < 4; n++) {
                int col = n0 + cw + n*8 + t4*2;
                float2 b2v = *(const float2*)&b2[col];
                float q;
                q = tanhf(acc[m][n].x + b2v.x)*wt0; tri[m][n].x += (q > 0.f ? q : 0.01f*q);
                q = tanhf(acc[m][n].y + b2v.y)*wt0; tri[m][n].y += (q > 0.f ? q : 0.01f*q);
                q = tanhf(acc[m][n].z + b2v.x)*wt1; tri[m][n].z += (q > 0.f ? q : 0.01f*q);
                q = tanhf(acc[m][n].w + b2v.y)*wt1; tri[m][n].w += (q > 0.f ? q : 0.01f*q);
            }
        }
    }
#pragma unroll
    for (int m = 0; m < 2; m++) {
        size_t r0 = b0 + rw + m*16 + g, r1 = r0 + 8;
#pragma unroll
        for (int n = 0; n < 4; n++) {
            int col = n0 + cw + n*8 + t4*2;
            float2 o0; o0.x = tri[m][n].x; o0.y = tri[m][n].y;
            float2 o1; o1.x = tri[m][n].z; o1.y = tri[m][n].w;
            *(float2*)&g_tri[r0*1024 + col] = o0;
            *(float2*)&g_tri[r1*1024 + col] = o1;
        }
    }
}

// -------------------------- k7: fused head (tf32 layer1) --------------------
// CTA = 64 rows. smem pool layout (floats):
//  As 0..2303 [64][36], Bs 2304..4607 [32][72], Y1 4608.. (64*52),
//  Y2 7936.., Y3 11264.. (512), W23 11776.. (2600 + 400)
#define K7_SMEM ((64*36 + 32*72 + 64*52*2 + 512 + 3000)*4)
__global__ __launch_bounds__(256) void k7_final(
    const float* __restrict__ bnb,
    const float* __restrict__ l1b,
    const float* __restrict__ l2W, const float* __restrict__ l2b,
    const float* __restrict__ l3W, const float* __restrict__ l3b,
    float* __restrict__ out)
{
    extern __shared__ float pool[];
    float* As  = pool;
    float* Bs  = pool + 2304;
    float* Y1  = pool + 4608;
    float* Y2  = pool + 7936;
    float* Y3  = pool + 11264;
    float* W23 = pool + 11776;
    int tid = threadIdx.x;
    int b0 = blockIdx.x * 64;
    int lane = tid & 31, wid = tid >> 5;
    int g = lane >> 2, t4 = lane & 3;
    int wm = wid >> 2, wn = wid & 3;      // 2 x 4 warps
    int rw = wm*32, cw = wn*16;

    // stage small weights early
    for (int i = tid; i < 2500; i += 256) {
        int k = i / 50, c = i - k*50;
        W23[k*52 + c] = l2W[i];
    }
    for (int i = tid; i < 400; i += 256) W23[2600 + i] = l3W[i];

    float4 acc[2][2] = {};
    for (int t = 0; t < 96; t++) {
        int kk = t * 32;
        int region = kk >> 10;
        const float* src = region == 0 ? g_uni : (region == 1 ? g_bisum : g_tri);
        __syncthreads();
        // A: 64 rows x 32 cols, BN fused, tf32-rounded
        for (int i = tid; i < 512; i += 256) {
            int r = i >> 3, c4 = i & 7;
            float4 v = *(const float4*)&src[(size_t)(b0 + r)*1024 + (kk & 1023) + c4*4];
            int j = kk + c4*4;
            float* d = &As[r*36 + c4*4];
            d[0] = f2tf_f(fmaf(v.x, g_bnsc[j],   bnb[j]));
            d[1] = f2tf_f(fmaf(v.y, g_bnsc[j+1], bnb[j+1]));
            d[2] = f2tf_f(fmaf(v.z, g_bnsc[j+2], bnb[j+2]));
            d[3] = f2tf_f(fmaf(v.w, g_bnsc[j+3], bnb[j+3]));
        }
        // B: l1Wp tile [32][64]
        for (int i = tid; i < 512; i += 256) {
            int k = i >> 4, c4 = i & 15;
            cpasync16(&Bs[k*72 + c4*4], &g_l1Wp[(size_t)(kk + k)*64 + c4*4]);
        }
        CP_COMMIT; CP_WAIT0;
        __syncthreads();
#pragma unroll
        for (int ks = 0; ks < 4; ks++) {
            unsigned a[2][4], bf[2][2];
#pragma unroll
            for (int m = 0; m < 2; m++) {
                int r = rw + m*16 + g;
                a[m][0] = __float_as_uint(As[r*36 + ks*8 + t4]);
                a[m][1] = __float_as_uint(As[(r+8)*36 + ks*8 + t4]);
                a[m][2] = __float_as_uint(As[r*36 + ks*8 + t4 + 4]);
                a[m][3] = __float_as_uint(As[(r+8)*36 + ks*8 + t4 + 4]);
            }
#pragma unroll
            for (int n = 0; n < 2; n++) {
                int c = cw + n*8 + g;
                bf[n][0] = __float_as_uint(Bs[(ks*8 + t4)*72 + c]);
                bf[n][1] = __float_as_uint(Bs[(ks*8 + t4 + 4)*72 + c]);
            }
#pragma unroll
            for (int m = 0; m < 2; m++)
#pragma unroll
            for (int n = 0; n < 2; n++)
                mma_tf32(acc[m][n], a[m], bf[n]);
        }
    }
    __syncthreads();
    // epilogue: y1 = tanh(acc + l1b)
#pragma unroll
    for (int m = 0; m < 2; m++) {
        int r0 = rw + m*16 + g, r1 = r0 + 8;
#pragma unroll
        for (int n = 0; n < 2; n++) {
            int c = cw + n*8 + t4*2;
            if (c < 50)   { Y1[r0*52 + c]   = tanhf(acc[m][n].x + l1b[c]);
                            Y1[r1*52 + c]   = tanhf(acc[m][n].z + l1b[c]); }
            if (c+1 < 50) { Y1[r0*52 + c+1] = tanhf(acc[m][n].y + l1b[c+1]);
                            Y1[r1*52 + c+1] = tanhf(acc[m][n].w + l1b[c+1]); }
        }
    }
    __syncthreads();

    // layer 2: [64,50] @ [50,50], fp32
    for (int o = tid; o < 3200; o += 256) {
        int r = o / 50, c = o - r*50;
        float a = l2b[c];
        for (int k = 0; k < 50; k++)
            a = fmaf(Y1[r*52 + k], W23[k*52 + c], a);
        Y2[r*52 + c] = tanhf(a);
    }
    __syncthreads();

    // layer 3: [64,50] @ [50,8]
    for (int o = tid; o < 512; o += 256) {
        int r = o >> 3, c = o & 7;
        float a = l3b[c];
        for (int k = 0; k < 50; k++)
            a = fmaf(Y2[r*52 + k], W23[2600 + k*8 + c], a);
        Y3[r*8 + c] = a;
    }
    __syncthreads();
    if (tid < 64) {
        int r = tid;
        float m = -1e30f;
#pragma unroll
        for (int c = 0; c < 8; c++) m = fmaxf(m, Y3[r*8 + c]);
        float e[8], s = 0.f;
#pragma unroll
        for (int c = 0; c < 8; c++) { e[c] = expf(Y3[r*8 + c] - m); s += e[c]; }
        float inv = 1.f / s;
        float* orow = out + (size_t)(b0 + r)*8;
#pragma unroll
        for (int c = 0; c < 8; c++) orow[c] = e[c]*inv;
    }
}

// -------------------------- launch ------------------------------------------
extern "C" void kernel_launch(void* const* d_in, const int* in_sizes, int n_in,
                              void* d_out, int out_size)
{
    const float* x    = (const float*)d_in[0];
    const float* attW = (const float*)d_in[1];
    const float* attb = (const float*)d_in[2];
    const float* gfW1 = (const float*)d_in[3];
    const float* gfb1 = (const float*)d_in[4];
    const float* gfW2 = (const float*)d_in[5];
    const float* gfb2 = (const float*)d_in[6];
    const float* bng  = (const float*)d_in[7];
    const float* bnb  = (const float*)d_in[8];
    const float* l1W  = (const float*)d_in[9];
    const float* l1b  = (const float*)d_in[10];
    const float* l2W  = (const float*)d_in[11];
    const float* l2b  = (const float*)d_in[12];
    const float* l3W  = (const float*)d_in[13];
    const float* l3b  = (const float*)d_in[14];
    float* out  = (float*)d_out;
    int wflag = (out_size >= NB*20) ? 1 : 0;
    float* outW = out + (size_t)NB*8;

    static int attr_done = 0;
    if (!attr_done) {
        cudaFuncSetAttribute(k_proj_mma, cudaFuncAttributeMaxDynamicSharedMemorySize, KP_SMEM);
        cudaFuncSetAttribute(k3_mma,     cudaFuncAttributeMaxDynamicSharedMemorySize, K3_SMEM);
        cudaFuncSetAttribute(k6_mma,     cudaFuncAttributeMaxDynamicSharedMemorySize, K3_SMEM);
        cudaFuncSetAttribute(k7_final,   cudaFuncAttributeMaxDynamicSharedMemorySize, K7_SMEM);
        cudaFuncSetAttribute(kact1,      cudaFuncAttributeMaxDynamicSharedMemorySize, ACT1_SMEM);
        cudaFuncSetAttribute(kact2,      cudaFuncAttributeMaxDynamicSharedMemorySize, ACT2_SMEM);
        attr_done = 1;
    }

    k0_prep<<<1549, 256>>>(gfW1, gfW2, l1W, bng);
    k1_att<<<NB, 256>>>(x, attW, attb, outW, wflag);
    k_proj_mma<<<NR3/128, 256, KP_SMEM>>>(x, 0);
    kact1<<<NB/32, 256, ACT1_SMEM>>>(gfb1);
    dim3 g3(NB/128, 16);
    k3_mma<<<g3, 256, K3_SMEM>>>(gfb2);
    k4_tri<<<NB, 256>>>(x, outW, wflag);
    k_proj_mma<<<NR3/128, 256, KP_SMEM>>>(x, 1);
    kact2<<<NB/32, 256, ACT2_SMEM>>>(gfb1);
    k6_mma<<<g3, 256, K3_SMEM>>>(gfb2);
    k7_final<<<NB/64, 256, K7_SMEM>>>(bnb, l1b, l2W, l2b, l3W, l3b, out);
}

// round 6
// speedup vs baseline: 2.6622x; 1.0069x over previous
#include <cuda_runtime.h>
#include <cstdint>
#include <cstddef>

// ---------------------------------------------------------------------------
// graph12 — Round 5: zero-cvt pipelined kP (raw-fp32 tf32 feed) +
//                    double-buffered plane loads in k3/k6.
// ---------------------------------------------------------------------------

#define NB    16384
#define ND    1024
#define NR3   (NB*3)          // 49152

__device__ float g_W1r  [1024*128];          // tf32-rounded
__device__ float g_W2r  [64*1024];           // tf32-rounded
__device__ float g_l1Wp [3072*64];           // tf32-rounded, padded 50->64
__device__ float g_bnsc [3072];              // BNS * gamma * region-mult
__device__ float g_PQ1  [(size_t)NR3*128];
__device__ float g_PQ2  [(size_t)NR3*128];
__device__ float g_act1 [(size_t)3*NB*64];   // tf32-rounded lrelu activations
__device__ float g_act2 [(size_t)6*NB*64];
__device__ float g_uni  [(size_t)NB*ND];
__device__ float g_bi3  [(size_t)NR3*ND];    // [b][p][1024]
__device__ float g_bisum[(size_t)NB*ND];     // sum of 3 planes (NOT /3)
__device__ float g_tri  [(size_t)NB*ND];     // sum of 6 (NOT /6)
__device__ float g_wuni [NB*3];
__device__ float g_wbi  [NB*3];
__device__ float g_sbi  [NB*3];
__device__ float g_wtri [NB*6];

// -------------------------- helpers -----------------------------------------
__device__ __forceinline__ float f2tf_f(float f) {
    unsigned r;
    asm("cvt.rna.tf32.f32 %0, %1;" : "=r"(r) : "f"(f));
    return __uint_as_float(r);
}

__device__ __forceinline__ void mma_tf32(float4& d, const unsigned* a, const unsigned* b) {
    asm volatile(
        "mma.sync.aligned.m16n8k8.row.col.f32.tf32.tf32.f32 "
        "{%0,%1,%2,%3}, {%4,%5,%6,%7}, {%8,%9}, {%0,%1,%2,%3};"
        : "+f"(d.x), "+f"(d.y), "+f"(d.z), "+f"(d.w)
        : "r"(a[0]), "r"(a[1]), "r"(a[2]), "r"(a[3]), "r"(b[0]), "r"(b[1]));
}

__device__ __forceinline__ void cpasync16(float* dst_smem, const float* src) {
    unsigned d = (unsigned)__cvta_generic_to_shared(dst_smem);
    asm volatile("cp.async.cg.shared.global [%0], [%1], 16;" :: "r"(d), "l"(src));
}
#define CP_COMMIT  asm volatile("cp.async.commit_group;")
#define CP_WAIT0   asm volatile("cp.async.wait_group 0;")
#define CP_WAIT1   asm volatile("cp.async.wait_group 1;")

// -------------------------- block reductions (256 thr) ----------------------
template<int NV>
__device__ __forceinline__ void blockReduceSumN(float* v, float* rbuf) {
    int tid = threadIdx.x, lane = tid & 31, w = tid >> 5;
#pragma unroll
    for (int n = 0; n < NV; n++) {
        float x = v[n];
#pragma unroll
        for (int o = 16; o > 0; o >>= 1) x += __shfl_down_sync(0xffffffffu, x, o);
        if (lane == 0) rbuf[n*8 + w] = x;
    }
    __syncthreads();
    if (tid < NV) {
        float s = rbuf[tid*8];
#pragma unroll
        for (int q = 1; q < 8; q++) s += rbuf[tid*8 + q];
        rbuf[tid*8] = s;
    }
    __syncthreads();
#pragma unroll
    for (int n = 0; n < NV; n++) v[n] = rbuf[n*8];
    __syncthreads();
}

template<int NV>
__device__ __forceinline__ void blockReduceMaxN(float* v, float* rbuf) {
    int tid = threadIdx.x, lane = tid & 31, w = tid >> 5;
#pragma unroll
    for (int n = 0; n < NV; n++) {
        float x = v[n];
#pragma unroll
        for (int o = 16; o > 0; o >>= 1) x = fmaxf(x, __shfl_down_sync(0xffffffffu, x, o));
        if (lane == 0) rbuf[n*8 + w] = x;
    }
    __syncthreads();
    if (tid < NV) {
        float s = rbuf[tid*8];
#pragma unroll
        for (int q = 1; q < 8; q++) s = fmaxf(s, rbuf[tid*8 + q]);
        rbuf[tid*8] = s;
    }
    __syncthreads();
#pragma unroll
    for (int n = 0; n < NV; n++) v[n] = rbuf[n*8];
    __syncthreads();
}

// -------------------------- k0x: prep ---------------------------------------
__global__ void k0_prep(const float* __restrict__ W1, const float* __restrict__ W2,
                        const float* __restrict__ l1W, const float* __restrict__ bng)
{
    int i = blockIdx.x * 256 + threadIdx.x;
    if (i < 131072) {                         // W1r
        int k = i >> 7, j = i & 127;
        float v = (j < 64) ? W1[(size_t)k*64 + j] : W1[(size_t)(1024 + k)*64 + (j - 64)];
        g_W1r[i] = f2tf_f(v);
    } else if (i < 196608) {                  // W2r
        int i2 = i - 131072;
        g_W2r[i2] = f2tf_f(W2[i2]);
    } else if (i < 393216) {                  // l1Wp
        int i3 = i - 196608;
        int row = i3 >> 6, c = i3 & 63;
        g_l1Wp[i3] = (c < 50) ? f2tf_f(l1W[(size_t)row*50 + c]) : 0.f;
    } else if (i < 396288) {                  // bnsc
        int j = i - 393216;
        float mult = (j < 1024) ? 1.f : ((j < 2048) ? (1.f/3.f) : (1.f/6.f));
        g_bnsc[j] = bng[j] * rsqrtf(1.0f + 1e-5f) * mult;
    }
}

// -------------------------- k1: attention + stage-1 stats -------------------
__global__ __launch_bounds__(256) void k1_att(
    const float* __restrict__ x, const float* __restrict__ attW,
    const float* __restrict__ attb, float* __restrict__ outW, int wflag)
{
    __shared__ float sm[3072];
    __shared__ float rbuf[6*8];
    __shared__ float bc[4];
    int b = blockIdx.x, tid = threadIdx.x;
    const float4* xr4 = (const float4*)(x + (size_t)b*3072);
    for (int i = tid; i < 768; i += 256) ((float4*)sm)[i] = xr4[i];
    __syncthreads();

    float red[3];
    float a0 = 0.f, a1 = 0.f, a2 = 0.f;
    float m0 = -1e30f, m1 = -1e30f, m2 = -1e30f;
    for (int i = tid; i < 1024; i += 256) {
        float w = attW[i];
        float av = sm[i], vv = sm[1024 + i], lv = sm[2048 + i];
        a0 = fmaf(av, w, a0); a1 = fmaf(vv, w, a1); a2 = fmaf(lv, w, a2);
        m0 = fmaxf(m0, av);  m1 = fmaxf(m1, vv);  m2 = fmaxf(m2, lv);
    }
    red[0] = a0; red[1] = a1; red[2] = a2;
    blockReduceSumN<3>(red, rbuf);
    float att0 = red[0], att1 = red[1], att2 = red[2];
    red[0] = m0; red[1] = m1; red[2] = m2;
    blockReduceMaxN<3>(red, rbuf);
    float Ma = red[0], Mv = red[1], Ml = red[2];

    float red6[6] = {0.f, 0.f, 0.f, 0.f, 0.f, 0.f};
    for (int i = tid; i < 1024; i += 256) {
        float ea = expf(sm[i] - Ma);
        float ev = expf(sm[1024 + i] - Mv);
        float el = expf(sm[2048 + i] - Ml);
        red6[0] += ea; red6[1] += ev; red6[2] += el;
        red6[3] = fmaf(ea, ev, red6[3]);
        red6[4] = fmaf(ea, el, red6[4]);
        red6[5] = fmaf(ev, el, red6[5]);
    }
    blockReduceSumN<6>(red6, rbuf);

    if (tid == 0) {
        float ab = attb[0];
        float t0 = tanhf(att0 + ab), t1 = tanhf(att1 + ab), t2 = tanhf(att2 + ab);
        float mm = fmaxf(t0, fmaxf(t1, t2));
        float e0 = expf(t0 - mm), e1 = expf(t1 - mm), e2 = expf(t2 - mm);
        float inv = 1.f / (e0 + e1 + e2);
        float sa = e0*inv, sv = e1*inv, sl = e2*inv;
        float dav = red6[3] / (red6[0]*red6[1]);
        float dal = red6[4] / (red6[0]*red6[2]);
        float dvl = red6[5] / (red6[1]*red6[2]);
        float sav = (sa + sv) / (dav + 0.5f);
        float sal = (sa + sl) / (dal + 0.5f);
        float svl = (sl + sv) / (dvl + 0.5f);
        g_wuni[b*3+0] = sa; g_wuni[b*3+1] = sv; g_wuni[b*3+2] = sl;
        g_sbi [b*3+0] = sav; g_sbi[b*3+1] = sal; g_sbi[b*3+2] = svl;
        float m3 = fmaxf(sav, fmaxf(sal, svl));
        float f0 = expf(sav - m3), f1 = expf(sal - m3), f2 = expf(svl - m3);
        float fi = 1.f / (f0 + f1 + f2);
        g_wbi[b*3+0] = f0*fi; g_wbi[b*3+1] = f1*fi; g_wbi[b*3+2] = f2*fi;
        if (wflag) {
            float* o = outW + (size_t)b*12;
            o[0] = sa; o[1] = sv; o[2] = sl;
            o[3] = f0*fi; o[4] = f1*fi; o[5] = f2*fi;
        }
        bc[0] = sa; bc[1] = sv; bc[2] = sl;
    }
    __syncthreads();
    float sa = bc[0], sv = bc[1], sl = bc[2];
    float* ur = g_uni + (size_t)b*1024;
    for (int i = tid; i < 1024; i += 256)
        ur[i] = (sa*sm[i] + sv*sm[1024+i] + sl*sm[2048+i]) * (1.0f/3.0f);
}

// -------------------------- kP: projection GEMM (3-stage cp.async) ----------
// C[49152,128] = A[49152,1024] @ g_W1r[1024,128]
// A fed as raw fp32 (tf32 mma ignores low 13 bits); B pre-rounded.
#define KP_STAGE (128*36 + 32*136)   // 8960 floats per stage
#define KP_SMEM  (3*KP_STAGE*4)

__device__ __forceinline__ void kp_issue(const float* __restrict__ A, size_t m0,
                                         float* stage, int t, int tid)
{
    float* As = stage;
    float* Bs = stage + 128*36;
    int kk = t * 32;
#pragma unroll
    for (int j = 0; j < 4; j++) {
        int i = tid + j*256;
        int r = i >> 3, kq = i & 7;
        cpasync16(&As[r*36 + kq*4], &A[(m0 + r)*1024 + kk + kq*4]);
    }
#pragma unroll
    for (int j = 0; j < 4; j++) {
        int i = tid + j*256;
        int k = i >> 5, c4 = i & 31;
        cpasync16(&Bs[k*136 + c4*4], &g_W1r[(size_t)(kk + k)*128 + c4*4]);
    }
    CP_COMMIT;
}

__global__ __launch_bounds__(256) void k_proj_mma(const float* __restrict__ x, int which)
{
    const float* A = which ? g_bi3 : x;
    float* C = which ? g_PQ2 : g_PQ1;
    extern __shared__ float smp[];

    int tid = threadIdx.x;
    size_t m0 = (size_t)blockIdx.x * 128;
    int lane = tid & 31, wid = tid >> 5;
    int g = lane >> 2, t4 = lane & 3;
    int wm = wid >> 1, wn = wid & 1;

    float4 acc[2][8] = {};

    kp_issue(A, m0, smp,              0, tid);
    kp_issue(A, m0, smp + KP_STAGE,   1, tid);

    int s = 0;
    for (int t = 0; t < 32; t++) {
        if (t < 31) { CP_WAIT1; } else { CP_WAIT0; }
        __syncthreads();
        if (t + 2 < 32) {
            int sn = (s + 2 == 3) ? 2 : (s + 2 - 3 < 0 ? s + 2 : s - 1);
            // simpler: (s+2)%3
            kp_issue(A, m0, smp + ((s + 2) % 3)*KP_STAGE, t + 2, tid);
        }
        float* Ac = smp + s*KP_STAGE;
        float* Bc = Ac + 128*36;
#pragma unroll
        for (int ks = 0; ks < 4; ks++) {
            unsigned a[2][4], bf[8][2];
#pragma unroll
            for (int m = 0; m < 2; m++) {
                int r = wm*32 + m*16 + g;
                a[m][0] = __float_as_uint(Ac[r*36 + ks*8 + t4]);
                a[m][1] = __float_as_uint(Ac[(r+8)*36 + ks*8 + t4]);
                a[m][2] = __float_as_uint(Ac[r*36 + ks*8 + t4 + 4]);
                a[m][3] = __float_as_uint(Ac[(r+8)*36 + ks*8 + t4 + 4]);
            }
#pragma unroll
            for (int n = 0; n < 8; n++) {
                int c = wn*64 + n*8 + g;
                bf[n][0] = __float_as_uint(Bc[(ks*8 + t4)*136 + c]);
                bf[n][1] = __float_as_uint(Bc[(ks*8 + t4 + 4)*136 + c]);
            }
#pragma unroll
            for (int m = 0; m < 2; m++)
#pragma unroll
            for (int n = 0; n < 8; n++)
                mma_tf32(acc[m][n], a[m], bf[n]);
        }
        s = (s + 1) % 3;
    }
#pragma unroll
    for (int m = 0; m < 2; m++) {
        size_t r0 = m0 + wm*32 + m*16 + g;
        size_t r1 = r0 + 8;
#pragma unroll
        for (int n = 0; n < 8; n++) {
            int col = wn*64 + n*8 + t4*2;
            float2 o0; o0.x = acc[m][n].x; o0.y = acc[m][n].y;
            float2 o1; o1.x = acc[m][n].z; o1.y = acc[m][n].w;
            *(float2*)&C[r0*128 + col] = o0;
            *(float2*)&C[r1*128 + col] = o1;
        }
    }
}

// -------------------------- kact1: stage-1 activations ----------------------
#define ACT1_SMEM ((96*128 + 64)*4)
__global__ __launch_bounds__(256) void kact1(const float* __restrict__ b1)
{
    extern __shared__ float smA1[];
    float* smP = smA1;            // [96][128]
    float* b1s = smA1 + 96*128;
    int tid = threadIdx.x;
    int b0 = blockIdx.x * 32;
    const float4* src = (const float4*)(g_PQ1 + (size_t)(3*b0)*128);
    for (int i = tid; i < 3072; i += 256) ((float4*)smP)[i] = src[i];
    if (tid < 64) b1s[tid] = b1[tid];
    __syncthreads();
    for (int i = tid; i < 6144; i += 256) {
        int p = i >> 11, r = (i >> 6) & 31, k = i & 63;
        int f = (p == 2) ? 1 : 0;
        int s = (p == 0) ? 1 : 2;
        float tv = smP[(3*r + f)*128 + k] + smP[(3*r + s)*128 + 64 + k] + b1s[k];
        tv = tv > 0.f ? tv : 0.2f*tv;
        g_act1[((size_t)p*NB + b0 + r)*64 + k] = f2tf_f(tv);
    }
}

// -------------------------- kact2: stage-2 activations ----------------------
#define ACT2_SMEM ((2*96*128 + 64)*4)
__global__ __launch_bounds__(256) void kact2(const float* __restrict__ b1)
{
    extern __shared__ float smA2[];
    float* smP2 = smA2;             // [96][128] from PQ2
    float* smP1 = smA2 + 96*128;    // [96][128] from PQ1
    float* b1s  = smA2 + 2*96*128;
    int tid = threadIdx.x;
    int b0 = blockIdx.x * 32;
    const float4* s2 = (const float4*)(g_PQ2 + (size_t)(3*b0)*128);
    const float4* s1 = (const float4*)(g_PQ1 + (size_t)(3*b0)*128);
    for (int i = tid; i < 3072; i += 256) { ((float4*)smP2)[i] = s2[i]; ((float4*)smP1)[i] = s1[i]; }
    if (tid < 64) b1s[tid] = b1[tid];
    __syncthreads();
    const int PR[6] = {0, 0, 2, 0, 1, 2};
    const int QR[6] = {2, 1, 1, 2, 1, 0};
    const int QS[6] = {0, 0, 0, 1, 1, 1};   // 0 -> PQ2, 1 -> PQ1
    for (int i = tid; i < 12288; i += 256) {
        int p = i >> 11, r = (i >> 6) & 31, k = i & 63;
        const float* Qb = QS[p] ? smP1 : smP2;
        float tv = smP2[(3*r + PR[p])*128 + k] + Qb[(3*r + QR[p])*128 + 64 + k] + b1s[k];
        tv = tv > 0.f ? tv : 0.2f*tv;
        g_act2[((size_t)p*NB + b0 + r)*64 + k] = f2tf_f(tv);
    }
}

// -------------------------- k3: stage-1 gf second layer ---------------------
// CTA 128 rows x 64 cols; double-buffered plane loads.
#define K3_SMEM ((2*128*68 + 64*72)*4)
__global__ __launch_bounds__(256) void k3_mma(const float* __restrict__ b2)
{
    extern __shared__ float sm3[];
    float* AsB = sm3;                 // [2][128*68]
    float* Bs  = sm3 + 2*128*68;      // [64][72]
    int tid = threadIdx.x;
    int b0 = blockIdx.x * 128, n0 = blockIdx.y * 64;

    // group 0: B + plane-0 A
    for (int i = tid; i < 1024; i += 256) {
        int k = i >> 4, c4 = i & 15;
        cpasync16(&Bs[k*72 + c4*4], &g_W2r[(size_t)k*1024 + n0 + c4*4]);
    }
    {
        const float* Ap = g_act1 + ((size_t)0*NB + b0)*64;
        for (int i = tid; i < 2048; i += 256) {
            int r = i >> 4, c4 = i & 15;
            cpasync16(&AsB[r*68 + c4*4], &Ap[(size_t)r*64 + c4*4]);
        }
    }
    CP_COMMIT;

    int lane = tid & 31, wid = tid >> 5;
    int g = lane >> 2, t4 = lane & 3;
    int wm = wid >> 1, wn = wid & 1;
    int rw = wm*32, cw = wn*32;

#pragma unroll 1
    for (int p = 0; p < 3; p++) {
        if (p + 1 < 3) {
            const float* Ap = g_act1 + ((size_t)(p+1)*NB + b0)*64;
            float* Ad = AsB + ((p+1) & 1)*128*68;
            for (int i = tid; i < 2048; i += 256) {
                int r = i >> 4, c4 = i & 15;
                cpasync16(&Ad[r*68 + c4*4], &Ap[(size_t)r*64 + c4*4]);
            }
            CP_COMMIT;
            CP_WAIT1;
        } else {
            CP_WAIT0;
        }
        __syncthreads();
        float* As = AsB + (p & 1)*128*68;
        float4 acc[2][4] = {};
#pragma unroll
        for (int ks = 0; ks < 8; ks++) {
            unsigned a[2][4], bf[4][2];
#pragma unroll
            for (int m = 0; m < 2; m++) {
                int r = rw + m*16 + g;
                a[m][0] = __float_as_uint(As[r*68 + ks*8 + t4]);
                a[m][1] = __float_as_uint(As[(r+8)*68 + ks*8 + t4]);
                a[m][2] = __float_as_uint(As[r*68 + ks*8 + t4 + 4]);
                a[m][3] = __float_as_uint(As[(r+8)*68 + ks*8 + t4 + 4]);
            }
#pragma unroll
            for (int n = 0; n < 4; n++) {
                int c = cw + n*8 + g;
                bf[n][0] = __float_as_uint(Bs[(ks*8 + t4)*72 + c]);
                bf[n][1] = __float_as_uint(Bs[(ks*8 + t4 + 4)*72 + c]);
            }
#pragma unroll
            for (int m = 0; m < 2; m++)
#pragma unroll
            for (int n = 0; n < 4; n++)
                mma_tf32(acc[m][n], a[m], bf[n]);
        }
#pragma unroll
        for (int m = 0; m < 2; m++) {
            int r0 = b0 + rw + m*16 + g;
            int r1 = r0 + 8;
            float wb0 = g_wbi[r0*3 + p];
            float wb1 = g_wbi[r1*3 + p];
#pragma unroll
            for (int n = 0; n < 4; n++) {
                int col = n0 + cw + n*8 + t4*2;
                float2 b2v = *(const float2*)&b2[col];
                float q;
                float2 o0, o1;
                q = tanhf(acc[m][n].x + b2v.x)*wb0; o0.x = q > 0.f ? q : 0.01f*q;
                q = tanhf(acc[m][n].y + b2v.y)*wb0; o0.y = q > 0.f ? q : 0.01f*q;
                q = tanhf(acc[m][n].z + b2v.x)*wb1; o1.x = q > 0.f ? q : 0.01f*q;
                q = tanhf(acc[m][n].w + b2v.y)*wb1; o1.y = q > 0.f ? q : 0.01f*q;
                *(float2*)&g_bi3[((size_t)r0*3 + p)*1024 + col] = o0;
                *(float2*)&g_bi3[((size_t)r1*3 + p)*1024 + col] = o1;
            }
        }
        __syncthreads();
    }
}

// -------------------------- k4: stage-2 weights + bisum ---------------------
__global__ __launch_bounds__(256) void k4_tri(
    const float* __restrict__ x, float* __restrict__ outW, int wflag)
{
    __shared__ float sm[6144];       // av, al, vl, a1, v1, l1
    __shared__ float rbuf[12*8];
    int b = blockIdx.x, tid = threadIdx.x;
    const float4* br4 = (const float4*)(g_bi3 + (size_t)b*3072);
    const float4* xr4 = (const float4*)(x + (size_t)b*3072);
    for (int i = tid; i < 768; i += 256) {
        ((float4*)sm)[i] = br4[i];
        ((float4*)sm)[768 + i] = xr4[i];
    }
    __syncthreads();

    for (int i = tid; i < 1024; i += 256)
        g_bisum[(size_t)b*1024 + i] = sm[i] + sm[1024+i] + sm[2048+i];

    float mx[6] = {-1e30f, -1e30f, -1e30f, -1e30f, -1e30f, -1e30f};
    for (int i = tid; i < 1024; i += 256) {
#pragma unroll
        for (int v = 0; v < 6; v++) mx[v] = fmaxf(mx[v], sm[v*1024 + i]);
    }
    blockReduceMaxN<6>(mx, rbuf);

    float zs[12] = {};
    for (int i = tid; i < 1024; i += 256) {
        float e[6];
#pragma unroll
        for (int v = 0; v < 6; v++) { e[v] = expf(sm[v*1024 + i] - mx[v]); zs[v] += e[v]; }
        zs[6]  = fmaf(e[0], e[2], zs[6]);
        zs[7]  = fmaf(e[0], e[1], zs[7]);
        zs[8]  = fmaf(e[1], e[2], zs[8]);
        zs[9]  = fmaf(e[0], e[5], zs[9]);
        zs[10] = fmaf(e[1], e[4], zs[10]);
        zs[11] = fmaf(e[2], e[3], zs[11]);
    }
    blockReduceSumN<12>(zs, rbuf);

    if (tid == 0) {
        float d0 = zs[6]  / (zs[0]*zs[2]);
        float d1 = zs[7]  / (zs[0]*zs[1]);
        float d2 = zs[8]  / (zs[1]*zs[2]);
        float d3 = zs[9]  / (zs[0]*zs[5]);
        float d4 = zs[10] / (zs[1]*zs[4]);
        float d5 = zs[11] / (zs[2]*zs[3]);
        float sa = g_wuni[b*3+0], sv = g_wuni[b*3+1], sl = g_wuni[b*3+2];
        float sav = g_sbi[b*3+0], sal = g_sbi[b*3+1], svl = g_sbi[b*3+2];
        float n[6];
        n[0] = (sav + svl) / (d0 + 0.5f);
        n[1] = (sav + sal) / (d1 + 0.5f);
        n[2] = (sal + svl) / (d2 + 0.5f);
        n[3] = (sav + sl ) / (d3 + 0.5f);
        n[4] = (sal + sv ) / (d4 + 0.5f);
        n[5] = (sa  + svl) / (d5 + 0.5f);
        float m = n[0];
#pragma unroll
        for (int k = 1; k < 6; k++) m = fmaxf(m, n[k]);
        float e[6], ssum = 0.f;
#pragma unroll
        for (int k = 0; k < 6; k++) { e[k] = expf(n[k] - m); ssum += e[k]; }
        float inv = 1.f / ssum;
#pragma unroll
        for (int k = 0; k < 6; k++) {
            g_wtri[b*6 + k] = e[k]*inv;
            if (wflag) outW[(size_t)b*12 + 6 + k] = e[k]*inv;
        }
    }
}

// -------------------------- k6: stage-2 gf second layer ---------------------
__global__ __launch_bounds__(256) void k6_mma(const float* __restrict__ b2)
{
    extern __shared__ float sm6[];
    float* AsB = sm6;                 // [2][128*68]
    float* Bs  = sm6 + 2*128*68;      // [64][72]
    int tid = threadIdx.x;
    int b0 = blockIdx.x * 128, n0 = blockIdx.y * 64;

    for (int i = tid; i < 1024; i += 256) {
        int k = i >> 4, c4 = i & 15;
        cpasync16(&Bs[k*72 + c4*4], &g_W2r[(size_t)k*1024 + n0 + c4*4]);
    }
    {
        const float* Ap = g_act2 + ((size_t)0*NB + b0)*64;
        for (int i = tid; i < 2048; i += 256) {
            int r = i >> 4, c4 = i & 15;
            cpasync16(&AsB[r*68 + c4*4], &Ap[(size_t)r*64 + c4*4]);
        }
    }
    CP_COMMIT;

    int lane = tid & 31, wid = tid >> 5;
    int g = lane >> 2, t4 = lane & 3;
    int wm = wid >> 1, wn = wid & 1;
    int rw = wm*32, cw = wn*32;

    float4 tri[2][4] = {};
#pragma unroll 1
    for (int p = 0; p < 6; p++) {
        if (p + 1 < 6) {
            const float* Ap = g_act2 + ((size_t)(p+1)*NB + b0)*64;
            float* Ad = AsB + ((p+1) & 1)*128*68;
            for (int i = tid; i < 2048; i += 256) {
                int r = i >> 4, c4 = i & 15;
                cpasync16(&Ad[r*68 + c4*4], &Ap[(size_t)r*64 + c4*4]);
            }
            CP_COMMIT;
            CP_WAIT1;
        } else {
            CP_WAIT0;
        }
        __syncthreads();
        float* As = AsB + (p & 1)*128*68;
        float4 acc[2][4] = {};
#pragma unroll
        for (int ks = 0; ks < 8; ks++) {
            unsigned a[2][4], bf[4][2];
#pragma unroll
            for (int m = 0; m < 2; m++) {
                int r = rw + m*16 + g;
                a[m][0] = __float_as_uint(As[r*68 + ks*8 + t4]);
                a[m][1] = __float_as_uint(As[(r+8)*68 + ks*8 + t4]);
                a[m][2] = __float_as_uint(As[r*68 + ks*8 + t4 + 4]);
                a[m][3] = __float_as_uint(As[(r+8)*68 + ks*8 + t4 + 4]);
            }
#pragma unroll
            for (int n = 0; n < 4; n++) {
                int c = cw + n*8 + g;
                bf[n][0] = __float_as_uint(Bs[(ks*8 + t4)*72 + c]);
                bf[n][1] = __float_as_uint(Bs[(ks*8 + t4 + 4)*72 + c]);
            }
#pragma unroll
            for (int m = 0; m < 2; m++)
#pragma unroll
            for (int n = 0; n < 4; n++)
                mma_tf32(acc[m][n], a[m], bf[n]);
        }
#pragma unroll
        for (int m = 0; m < 2; m++) {
            int r0 = b0 + rw + m*16 + g;
            int r1 = r0 + 8;
            float wt0 = g_wtri[(size_t)r0*6 + p];
            float wt1 = g_wtri[(size_t)r1*6 + p];
#pragma unroll
            for (int n = 0; n < 4; n++) {
                int col = n0 + cw + n*8 + t4*2;
                float2 b2v = *(const float2*)&b2[col];
                float q;
                q = tanhf(acc[m][n].x + b2v.x)*wt0; tri[m][n].x += (q > 0.f ? q : 0.01f*q);
                q = tanhf(acc[m][n].y + b2v.y)*wt0; tri[m][n].y += (q > 0.f ? q : 0.01f*q);
                q = tanhf(acc[m][n].z + b2v.x)*wt1; tri[m][n].z += (q > 0.f ? q : 0.01f*q);
                q = tanhf(acc[m][n].w + b2v.y)*wt1; tri[m][n].w += (q > 0.f ? q : 0.01f*q);
            }
        }
        __syncthreads();
    }
#pragma unroll
    for (int m = 0; m < 2; m++) {
        size_t r0 = b0 + rw + m*16 + g, r1 = r0 + 8;
#pragma unroll
        for (int n = 0; n < 4; n++) {
            int col = n0 + cw + n*8 + t4*2;
            float2 o0; o0.x = tri[m][n].x; o0.y = tri[m][n].y;
            float2 o1; o1.x = tri[m][n].z; o1.y = tri[m][n].w;
            *(float2*)&g_tri[r0*1024 + col] = o0;
            *(float2*)&g_tri[r1*1024 + col] = o1;
        }
    }
}

// -------------------------- k7: fused head (tf32 layer1) --------------------
#define K7_SMEM ((64*36 + 32*72 + 64*52*2 + 512 + 3000)*4)
__global__ __launch_bounds__(256) void k7_final(
    const float* __restrict__ bnb,
    const float* __restrict__ l1b,
    const float* __restrict__ l2W, const float* __restrict__ l2b,
    const float* __restrict__ l3W, const float* __restrict__ l3b,
    float* __restrict__ out)
{
    extern __shared__ float pool[];
    float* As  = pool;
    float* Bs  = pool + 2304;
    float* Y1  = pool + 4608;
    float* Y2  = pool + 7936;
    float* Y3  = pool + 11264;
    float* W23 = pool + 11776;
    int tid = threadIdx.x;
    int b0 = blockIdx.x * 64;
    int lane = tid & 31, wid = tid >> 5;
    int g = lane >> 2, t4 = lane & 3;
    int wm = wid >> 2, wn = wid & 3;      // 2 x 4 warps
    int rw = wm*32, cw = wn*16;

    for (int i = tid; i < 2500; i += 256) {
        int k = i / 50, c = i - k*50;
        W23[k*52 + c] = l2W[i];
    }
    for (int i = tid; i < 400; i += 256) W23[2600 + i] = l3W[i];

    float4 acc[2][2] = {};
    for (int t = 0; t < 96; t++) {
        int kk = t * 32;
        int region = kk >> 10;
        const float* src = region == 0 ? g_uni : (region == 1 ? g_bisum : g_tri);
        __syncthreads();
        for (int i = tid; i < 512; i += 256) {
            int r = i >> 3, c4 = i & 7;
            float4 v = *(const float4*)&src[(size_t)(b0 + r)*1024 + (kk & 1023) + c4*4];
            int j = kk + c4*4;
            float* d = &As[r*36 + c4*4];
            d[0] = f2tf_f(fmaf(v.x, g_bnsc[j],   bnb[j]));
            d[1] = f2tf_f(fmaf(v.y, g_bnsc[j+1], bnb[j+1]));
            d[2] = f2tf_f(fmaf(v.z, g_bnsc[j+2], bnb[j+2]));
            d[3] = f2tf_f(fmaf(v.w, g_bnsc[j+3], bnb[j+3]));
        }
        for (int i = tid; i < 512; i += 256) {
            int k = i >> 4, c4 = i & 15;
            cpasync16(&Bs[k*72 + c4*4], &g_l1Wp[(size_t)(kk + k)*64 + c4*4]);
        }
        CP_COMMIT; CP_WAIT0;
        __syncthreads();
#pragma unroll
        for (int ks = 0; ks < 4; ks++) {
            unsigned a[2][4], bf[2][2];
#pragma unroll
            for (int m = 0; m < 2; m++) {
                int r = rw + m*16 + g;
                a[m][0] = __float_as_uint(As[r*36 + ks*8 + t4]);
                a[m][1] = __float_as_uint(As[(r+8)*36 + ks*8 + t4]);
                a[m][2] = __float_as_uint(As[r*36 + ks*8 + t4 + 4]);
                a[m][3] = __float_as_uint(As[(r+8)*36 + ks*8 + t4 + 4]);
            }
#pragma unroll
            for (int n = 0; n < 2; n++) {
                int c = cw + n*8 + g;
                bf[n][0] = __float_as_uint(Bs[(ks*8 + t4)*72 + c]);
                bf[n][1] = __float_as_uint(Bs[(ks*8 + t4 + 4)*72 + c]);
            }
#pragma unroll
            for (int m = 0; m < 2; m++)
#pragma unroll
            for (int n = 0; n < 2; n++)
                mma_tf32(acc[m][n], a[m], bf[n]);
        }
    }
    __syncthreads();
#pragma unroll
    for (int m = 0; m < 2; m++) {
        int r0 = rw + m*16 + g, r1 = r0 + 8;
#pragma unroll
        for (int n = 0; n < 2; n++) {
            int c = cw + n*8 + t4*2;
            if (c < 50)   { Y1[r0*52 + c]   = tanhf(acc[m][n].x + l1b[c]);
                            Y1[r1*52 + c]   = tanhf(acc[m][n].z + l1b[c]); }
            if (c+1 < 50) { Y1[r0*52 + c+1] = tanhf(acc[m][n].y + l1b[c+1]);
                            Y1[r1*52 + c+1] = tanhf(acc[m][n].w + l1b[c+1]); }
        }
    }
    __syncthreads();

    for (int o = tid; o < 3200; o += 256) {
        int r = o / 50, c = o - r*50;
        float a = l2b[c];
        for (int k = 0; k < 50; k++)
            a = fmaf(Y1[r*52 + k], W23[k*52 + c], a);
        Y2[r*52 + c] = tanhf(a);
    }
    __syncthreads();

    for (int o = tid; o < 512; o += 256) {
        int r = o >> 3, c = o & 7;
        float a = l3b[c];
        for (int k = 0; k < 50; k++)
            a = fmaf(Y2[r*52 + k], W23[2600 + k*8 + c], a);
        Y3[r*8 + c] = a;
    }
    __syncthreads();
    if (tid < 64) {
        int r = tid;
        float m = -1e30f;
#pragma unroll
        for (int c = 0; c < 8; c++) m = fmaxf(m, Y3[r*8 + c]);
        float e[8], s = 0.f;
#pragma unroll
        for (int c = 0; c < 8; c++) { e[c] = expf(Y3[r*8 + c] - m); s += e[c]; }
        float inv = 1.f / s;
        float* orow = out + (size_t)(b0 + r)*8;
#pragma unroll
        for (int c = 0; c < 8; c++) orow[c] = e[c]*inv;
    }
}

// -------------------------- launch ------------------------------------------
extern "C" void kernel_launch(void* const* d_in, const int* in_sizes, int n_in,
                              void* d_out, int out_size)
{
    const float* x    = (const float*)d_in[0];
    const float* attW = (const float*)d_in[1];
    const float* attb = (const float*)d_in[2];
    const float* gfW1 = (const float*)d_in[3];
    const float* gfb1 = (const float*)d_in[4];
    const float* gfW2 = (const float*)d_in[5];
    const float* gfb2 = (const float*)d_in[6];
    const float* bng  = (const float*)d_in[7];
    const float* bnb  = (const float*)d_in[8];
    const float* l1W  = (const float*)d_in[9];
    const float* l1b  = (const float*)d_in[10];
    const float* l2W  = (const float*)d_in[11];
    const float* l2b  = (const float*)d_in[12];
    const float* l3W  = (const float*)d_in[13];
    const float* l3b  = (const float*)d_in[14];
    float* out  = (float*)d_out;
    int wflag = (out_size >= NB*20) ? 1 : 0;
    float* outW = out + (size_t)NB*8;

    static int attr_done = 0;
    if (!attr_done) {
        cudaFuncSetAttribute(k_proj_mma, cudaFuncAttributeMaxDynamicSharedMemorySize, KP_SMEM);
        cudaFuncSetAttribute(k3_mma,     cudaFuncAttributeMaxDynamicSharedMemorySize, K3_SMEM);
        cudaFuncSetAttribute(k6_mma,     cudaFuncAttributeMaxDynamicSharedMemorySize, K3_SMEM);
        cudaFuncSetAttribute(k7_final,   cudaFuncAttributeMaxDynamicSharedMemorySize, K7_SMEM);
        cudaFuncSetAttribute(kact1,      cudaFuncAttributeMaxDynamicSharedMemorySize, ACT1_SMEM);
        cudaFuncSetAttribute(kact2,      cudaFuncAttributeMaxDynamicSharedMemorySize, ACT2_SMEM);
        attr_done = 1;
    }

    k0_prep<<<1549, 256>>>(gfW1, gfW2, l1W, bng);
    k1_att<<<NB, 256>>>(x, attW, attb, outW, wflag);
    k_proj_mma<<<NR3/128, 256, KP_SMEM>>>(x, 0);
    kact1<<<NB/32, 256, ACT1_SMEM>>>(gfb1);
    dim3 g3(NB/128, 16);
    k3_mma<<<g3, 256, K3_SMEM>>>(gfb2);
    k4_tri<<<NB, 256>>>(x, outW, wflag);
    k_proj_mma<<<NR3/128, 256, KP_SMEM>>>(x, 1);
    kact2<<<NB/32, 256, ACT2_SMEM>>>(gfb1);
    k6_mma<<<g3, 256, K3_SMEM>>>(gfb2);
    k7_final<<<NB/64, 256, K7_SMEM>>>(bnb, l1b, l2W, l2b, l3W, l3b, out);
}

// round 7
// speedup vs baseline: 2.8729x; 1.0791x over previous
#include <cuda_runtime.h>
#include <cstdint>
#include <cstddef>

// ---------------------------------------------------------------------------
// graph12 — Round 6: stage-2 megafusion. bi3 never touches DRAM.
//  k0:   prep (W1r/W2r/l1Wp tf32, bnsc)
//  k1:   attention + stage-1 stats (fp32)
//  kP:   PQ1 = x @ W1r                     (tf32 mma, 3-stage cp.async)
//  kFuse: act1 -> bi3(chunks, smem) -> {stats/wtri, bisum, PQ2} -> act2
//  k6:   stage-2 second layer               (tf32 mma)
//  k7:   BN + head layer1 tf32 mma + small fp32 layers + softmax
// ---------------------------------------------------------------------------

#define NB    16384
#define ND    1024
#define NR3   (NB*3)          // 49152

__device__ float g_W1r  [1024*128];          // tf32-rounded
__device__ float g_W2r  [64*1024];           // tf32-rounded
__device__ float g_l1Wp [3072*64];           // tf32-rounded, padded 50->64
__device__ float g_bnsc [3072];              // BNS * gamma * region-mult
__device__ float g_PQ1  [(size_t)NR3*128];
__device__ float g_act2 [(size_t)6*NB*64];   // raw fp32 (tf32-truncated in mma)
__device__ float g_uni  [(size_t)NB*ND];
__device__ float g_bisum[(size_t)NB*ND];     // sum of 3 planes (NOT /3)
__device__ float g_tri  [(size_t)NB*ND];     // sum of 6 (NOT /6)
__device__ float g_wuni [NB*3];
__device__ float g_wbi  [NB*3];
__device__ float g_sbi  [NB*3];
__device__ float g_wtri [NB*6];

// -------------------------- helpers -----------------------------------------
__device__ __forceinline__ float f2tf_f(float f) {
    unsigned r;
    asm("cvt.rna.tf32.f32 %0, %1;" : "=r"(r) : "f"(f));
    return __uint_as_float(r);
}

__device__ __forceinline__ void mma_tf32(float4& d, const unsigned* a, const unsigned* b) {
    asm volatile(
        "mma.sync.aligned.m16n8k8.row.col.f32.tf32.tf32.f32 "
        "{%0,%1,%2,%3}, {%4,%5,%6,%7}, {%8,%9}, {%0,%1,%2,%3};"
        : "+f"(d.x), "+f"(d.y), "+f"(d.z), "+f"(d.w)
        : "r"(a[0]), "r"(a[1]), "r"(a[2]), "r"(a[3]), "r"(b[0]), "r"(b[1]));
}

__device__ __forceinline__ void cpasync16(float* dst_smem, const float* src) {
    unsigned d = (unsigned)__cvta_generic_to_shared(dst_smem);
    asm volatile("cp.async.cg.shared.global [%0], [%1], 16;" :: "r"(d), "l"(src));
}
#define CP_COMMIT  asm volatile("cp.async.commit_group;")
#define CP_WAIT0   asm volatile("cp.async.wait_group 0;")
#define CP_WAIT1   asm volatile("cp.async.wait_group 1;")

// -------------------------- block reductions (256 thr) ----------------------
template<int NV>
__device__ __forceinline__ void blockReduceSumN(float* v, float* rbuf) {
    int tid = threadIdx.x, lane = tid & 31, w = tid >> 5;
#pragma unroll
    for (int n = 0; n < NV; n++) {
        float x = v[n];
#pragma unroll
        for (int o = 16; o > 0; o >>= 1) x += __shfl_down_sync(0xffffffffu, x, o);
        if (lane == 0) rbuf[n*8 + w] = x;
    }
    __syncthreads();
    if (tid < NV) {
        float s = rbuf[tid*8];
#pragma unroll
        for (int q = 1; q < 8; q++) s += rbuf[tid*8 + q];
        rbuf[tid*8] = s;
    }
    __syncthreads();
#pragma unroll
    for (int n = 0; n < NV; n++) v[n] = rbuf[n*8];
    __syncthreads();
}

template<int NV>
__device__ __forceinline__ void blockReduceMaxN(float* v, float* rbuf) {
    int tid = threadIdx.x, lane = tid & 31, w = tid >> 5;
#pragma unroll
    for (int n = 0; n < NV; n++) {
        float x = v[n];
#pragma unroll
        for (int o = 16; o > 0; o >>= 1) x = fmaxf(x, __shfl_down_sync(0xffffffffu, x, o));
        if (lane == 0) rbuf[n*8 + w] = x;
    }
    __syncthreads();
    if (tid < NV) {
        float s = rbuf[tid*8];
#pragma unroll
        for (int q = 1; q < 8; q++) s = fmaxf(s, rbuf[tid*8 + q]);
        rbuf[tid*8] = s;
    }
    __syncthreads();
#pragma unroll
    for (int n = 0; n < NV; n++) v[n] = rbuf[n*8];
    __syncthreads();
}

// -------------------------- k0: prep ----------------------------------------
__global__ void k0_prep(const float* __restrict__ W1, const float* __restrict__ W2,
                        const float* __restrict__ l1W, const float* __restrict__ bng)
{
    int i = blockIdx.x * 256 + threadIdx.x;
    if (i < 131072) {                         // W1r
        int k = i >> 7, j = i & 127;
        float v = (j < 64) ? W1[(size_t)k*64 + j] : W1[(size_t)(1024 + k)*64 + (j - 64)];
        g_W1r[i] = f2tf_f(v);
    } else if (i < 196608) {                  // W2r
        int i2 = i - 131072;
        g_W2r[i2] = f2tf_f(W2[i2]);
    } else if (i < 393216) {                  // l1Wp
        int i3 = i - 196608;
        int row = i3 >> 6, c = i3 & 63;
        g_l1Wp[i3] = (c < 50) ? f2tf_f(l1W[(size_t)row*50 + c]) : 0.f;
    } else if (i < 396288) {                  // bnsc
        int j = i - 393216;
        float mult = (j < 1024) ? 1.f : ((j < 2048) ? (1.f/3.f) : (1.f/6.f));
        g_bnsc[j] = bng[j] * rsqrtf(1.0f + 1e-5f) * mult;
    }
}

// -------------------------- k1: attention + stage-1 stats -------------------
__global__ __launch_bounds__(256) void k1_att(
    const float* __restrict__ x, const float* __restrict__ attW,
    const float* __restrict__ attb, float* __restrict__ outW, int wflag)
{
    __shared__ float sm[3072];
    __shared__ float rbuf[6*8];
    __shared__ float bc[4];
    int b = blockIdx.x, tid = threadIdx.x;
    const float4* xr4 = (const float4*)(x + (size_t)b*3072);
    for (int i = tid; i < 768; i += 256) ((float4*)sm)[i] = xr4[i];
    __syncthreads();

    float red[3];
    float a0 = 0.f, a1 = 0.f, a2 = 0.f;
    float m0 = -1e30f, m1 = -1e30f, m2 = -1e30f;
    for (int i = tid; i < 1024; i += 256) {
        float w = attW[i];
        float av = sm[i], vv = sm[1024 + i], lv = sm[2048 + i];
        a0 = fmaf(av, w, a0); a1 = fmaf(vv, w, a1); a2 = fmaf(lv, w, a2);
        m0 = fmaxf(m0, av);  m1 = fmaxf(m1, vv);  m2 = fmaxf(m2, lv);
    }
    red[0] = a0; red[1] = a1; red[2] = a2;
    blockReduceSumN<3>(red, rbuf);
    float att0 = red[0], att1 = red[1], att2 = red[2];
    red[0] = m0; red[1] = m1; red[2] = m2;
    blockReduceMaxN<3>(red, rbuf);
    float Ma = red[0], Mv = red[1], Ml = red[2];

    float red6[6] = {0.f, 0.f, 0.f, 0.f, 0.f, 0.f};
    for (int i = tid; i < 1024; i += 256) {
        float ea = expf(sm[i] - Ma);
        float ev = expf(sm[1024 + i] - Mv);
        float el = expf(sm[2048 + i] - Ml);
        red6[0] += ea; red6[1] += ev; red6[2] += el;
        red6[3] = fmaf(ea, ev, red6[3]);
        red6[4] = fmaf(ea, el, red6[4]);
        red6[5] = fmaf(ev, el, red6[5]);
    }
    blockReduceSumN<6>(red6, rbuf);

    if (tid == 0) {
        float ab = attb[0];
        float t0 = tanhf(att0 + ab), t1 = tanhf(att1 + ab), t2 = tanhf(att2 + ab);
        float mm = fmaxf(t0, fmaxf(t1, t2));
        float e0 = expf(t0 - mm), e1 = expf(t1 - mm), e2 = expf(t2 - mm);
        float inv = 1.f / (e0 + e1 + e2);
        float sa = e0*inv, sv = e1*inv, sl = e2*inv;
        float dav = red6[3] / (red6[0]*red6[1]);
        float dal = red6[4] / (red6[0]*red6[2]);
        float dvl = red6[5] / (red6[1]*red6[2]);
        float sav = (sa + sv) / (dav + 0.5f);
        float sal = (sa + sl) / (dal + 0.5f);
        float svl = (sl + sv) / (dvl + 0.5f);
        g_wuni[b*3+0] = sa; g_wuni[b*3+1] = sv; g_wuni[b*3+2] = sl;
        g_sbi [b*3+0] = sav; g_sbi[b*3+1] = sal; g_sbi[b*3+2] = svl;
        float m3 = fmaxf(sav, fmaxf(sal, svl));
        float f0 = expf(sav - m3), f1 = expf(sal - m3), f2 = expf(svl - m3);
        float fi = 1.f / (f0 + f1 + f2);
        g_wbi[b*3+0] = f0*fi; g_wbi[b*3+1] = f1*fi; g_wbi[b*3+2] = f2*fi;
        if (wflag) {
            float* o = outW + (size_t)b*12;
            o[0] = sa; o[1] = sv; o[2] = sl;
            o[3] = f0*fi; o[4] = f1*fi; o[5] = f2*fi;
        }
        bc[0] = sa; bc[1] = sv; bc[2] = sl;
    }
    __syncthreads();
    float sa = bc[0], sv = bc[1], sl = bc[2];
    float* ur = g_uni + (size_t)b*1024;
    for (int i = tid; i < 1024; i += 256)
        ur[i] = (sa*sm[i] + sv*sm[1024+i] + sl*sm[2048+i]) * (1.0f/3.0f);
}

// -------------------------- kP: PQ1 projection (3-stage cp.async) -----------
#define KP_STAGE (128*36 + 32*136)
#define KP_SMEM  (3*KP_STAGE*4)

__device__ __forceinline__ void kp_issue(const float* __restrict__ A, size_t m0,
                                         float* stage, int t, int tid)
{
    float* As = stage;
    float* Bs = stage + 128*36;
    int kk = t * 32;
#pragma unroll
    for (int j = 0; j < 4; j++) {
        int i = tid + j*256;
        int r = i >> 3, kq = i & 7;
        cpasync16(&As[r*36 + kq*4], &A[(m0 + r)*1024 + kk + kq*4]);
    }
#pragma unroll
    for (int j = 0; j < 4; j++) {
        int i = tid + j*256;
        int k = i >> 5, c4 = i & 31;
        cpasync16(&Bs[k*136 + c4*4], &g_W1r[(size_t)(kk + k)*128 + c4*4]);
    }
    CP_COMMIT;
}

__global__ __launch_bounds__(256) void k_proj_mma(const float* __restrict__ x)
{
    const float* A = x;
    float* C = g_PQ1;
    extern __shared__ float smp[];

    int tid = threadIdx.x;
    size_t m0 = (size_t)blockIdx.x * 128;
    int lane = tid & 31, wid = tid >> 5;
    int g = lane >> 2, t4 = lane & 3;
    int wm = wid >> 1, wn = wid & 1;

    float4 acc[2][8] = {};

    kp_issue(A, m0, smp,            0, tid);
    kp_issue(A, m0, smp + KP_STAGE, 1, tid);

    int s = 0;
    for (int t = 0; t < 32; t++) {
        if (t < 31) { CP_WAIT1; } else { CP_WAIT0; }
        __syncthreads();
        if (t + 2 < 32)
            kp_issue(A, m0, smp + ((s + 2) % 3)*KP_STAGE, t + 2, tid);
        float* Ac = smp + s*KP_STAGE;
        float* Bc = Ac + 128*36;
#pragma unroll
        for (int ks = 0; ks < 4; ks++) {
            unsigned a[2][4], bf[8][2];
#pragma unroll
            for (int m = 0; m < 2; m++) {
                int r = wm*32 + m*16 + g;
                a[m][0] = __float_as_uint(Ac[r*36 + ks*8 + t4]);
                a[m][1] = __float_as_uint(Ac[(r+8)*36 + ks*8 + t4]);
                a[m][2] = __float_as_uint(Ac[r*36 + ks*8 + t4 + 4]);
                a[m][3] = __float_as_uint(Ac[(r+8)*36 + ks*8 + t4 + 4]);
            }
#pragma unroll
            for (int n = 0; n < 8; n++) {
                int c = wn*64 + n*8 + g;
                bf[n][0] = __float_as_uint(Bc[(ks*8 + t4)*136 + c]);
                bf[n][1] = __float_as_uint(Bc[(ks*8 + t4 + 4)*136 + c]);
            }
#pragma unroll
            for (int m = 0; m < 2; m++)
#pragma unroll
            for (int n = 0; n < 8; n++)
                mma_tf32(acc[m][n], a[m], bf[n]);
        }
        s = (s + 1) % 3;
    }
#pragma unroll
    for (int m = 0; m < 2; m++) {
        size_t r0 = m0 + wm*32 + m*16 + g;
        size_t r1 = r0 + 8;
#pragma unroll
        for (int n = 0; n < 8; n++) {
            int col = wn*64 + n*8 + t4*2;
            float2 o0; o0.x = acc[m][n].x; o0.y = acc[m][n].y;
            float2 o1; o1.x = acc[m][n].z; o1.y = acc[m][n].w;
            *(float2*)&C[r0*128 + col] = o0;
            *(float2*)&C[r1*128 + col] = o1;
        }
    }
}

// -------------------------- kFuse: stage-2 megafusion -----------------------
// grid = NB/16 CTAs, 256 threads. rows pb-layout: row = p*16 + b (p plane, b batch).
// smem (floats):
#define KF_PQ1   0                         // [48][132] = 6336
#define KF_ACT1  6336                      // [48][68]  = 3264
#define KF_BI3   (6336+3264)               // [48][68]  = 3264
#define KF_W2    (KF_BI3+3264)             // [64][72]  = 4608
#define KF_W1    (KF_W2+4608)              // [64][136] = 8704  (reused as PQ2s [48][136])
#define KF_B1    (KF_W1+8704)              // 64
#define KF_WBI   (KF_B1+64)                // 48
#define KF_TOTF  (KF_WBI+48+16)
#define KF_SMEM  (KF_TOTF*4)

__global__ __launch_bounds__(256) void kFuse(
    const float* __restrict__ x, const float* __restrict__ b1,
    const float* __restrict__ b2, float* __restrict__ outW, int wflag)
{
    extern __shared__ float sf[];
    float* PQ1s = sf + KF_PQ1;
    float* act1s= sf + KF_ACT1;
    float* bi3c = sf + KF_BI3;
    float* W2s  = sf + KF_W2;
    float* W1s  = sf + KF_W1;
    float* b1s  = sf + KF_B1;
    float* wbis = sf + KF_WBI;

    int tid = threadIdx.x;
    int bb0 = blockIdx.x * 16;
    int lane = tid & 31, wid = tid >> 5;
    int g = lane >> 2, t4 = lane & 3;
    int wm = wid >> 1, wn = wid & 1;         // valid for wid < 6

    // ---- prologue: PQ1 tile (pb-layout), b1, wbi ----
    for (int i = tid; i < 1536; i += 256) {          // 48 rows x 32 float4
        int r = i >> 5, c4 = i & 31;
        int p = r >> 4, b = r & 15;
        cpasync16(&PQ1s[r*132 + c4*4], &g_PQ1[((size_t)(bb0 + b)*3 + p)*128 + c4*4]);
    }
    CP_COMMIT;
    if (tid < 64) b1s[tid] = b1[tid];
    if (tid < 48) { int p = tid >> 4, b = tid & 15; wbis[tid] = g_wbi[(bb0 + b)*3 + p]; }
    CP_WAIT0;
    __syncthreads();
    for (int i = tid; i < 3072; i += 256) {          // act1 (raw fp32)
        int r = i >> 6, k = i & 63;
        int p = r >> 4, b = r & 15;
        int f = (p == 2) ? 1 : 0;
        int s = (p == 0) ? 1 : 2;
        float tv = PQ1s[(f*16+b)*132 + k] + PQ1s[(s*16+b)*132 + 64 + k] + b1s[k];
        act1s[r*68 + k] = tv > 0.f ? tv : 0.2f*tv;
    }
    __syncthreads();

    float sE[2][3] = {}, sX[2][3] = {}, sP[2][3] = {}, sQ[2][3] = {};
    float4 pq2[8] = {};

    for (int n = 0; n < 16; n++) {
        int n0 = n * 64;
        // A) stage W2 chunk + W1 chunk, prefetch x into regs
        for (int i = tid; i < 1024; i += 256) {
            int k = i >> 4, c4 = i & 15;
            cpasync16(&W2s[k*72 + c4*4], &g_W2r[(size_t)k*1024 + n0 + c4*4]);
        }
        for (int i = tid; i < 2048; i += 256) {
            int k = i >> 5, c4 = i & 31;
            cpasync16(&W1s[k*136 + c4*4], &g_W1r[(size_t)(n0 + k)*128 + c4*4]);
        }
        CP_COMMIT;
        float xr[12];
#pragma unroll
        for (int j = 0; j < 2; j++)
#pragma unroll
        for (int m = 0; m < 3; m++)
#pragma unroll
        for (int h = 0; h < 2; h++)
            xr[(j*3+m)*2+h] = x[((size_t)(bb0 + 2*wid + j)*3 + m)*1024 + n0 + lane + h*32];
        CP_WAIT0;
        __syncthreads();

        // C) GEMM1: act1 @ W2 -> bi3 chunk (tanh * wbi, lrelu)
        if (wid < 6) {
            float4 acc[4] = {};
#pragma unroll
            for (int ks = 0; ks < 8; ks++) {
                unsigned a[4], bf[4][2];
                int r = wm*16 + g;
                a[0] = __float_as_uint(act1s[r*68 + ks*8 + t4]);
                a[1] = __float_as_uint(act1s[(r+8)*68 + ks*8 + t4]);
                a[2] = __float_as_uint(act1s[r*68 + ks*8 + t4 + 4]);
                a[3] = __float_as_uint(act1s[(r+8)*68 + ks*8 + t4 + 4]);
#pragma unroll
                for (int q = 0; q < 4; q++) {
                    int c = wn*32 + q*8 + g;
                    bf[q][0] = __float_as_uint(W2s[(ks*8 + t4)*72 + c]);
                    bf[q][1] = __float_as_uint(W2s[(ks*8 + t4 + 4)*72 + c]);
                }
#pragma unroll
                for (int q = 0; q < 4; q++) mma_tf32(acc[q], a, bf[q]);
            }
            int r0 = wm*16 + g, r1 = r0 + 8;
            float w0 = wbis[r0], w1 = wbis[r1];
#pragma unroll
            for (int q = 0; q < 4; q++) {
                int col = wn*32 + q*8 + t4*2;
                float2 b2v = *(const float2*)&b2[n0 + col];
                float t, v;
                t = tanhf(acc[q].x + b2v.x)*w0; v = t > 0.f ? t : 0.01f*t; bi3c[r0*68 + col]   = v;
                t = tanhf(acc[q].y + b2v.y)*w0; v = t > 0.f ? t : 0.01f*t; bi3c[r0*68 + col+1] = v;
                t = tanhf(acc[q].z + b2v.x)*w1; v = t > 0.f ? t : 0.01f*t; bi3c[r1*68 + col]   = v;
                t = tanhf(acc[q].w + b2v.y)*w1; v = t > 0.f ? t : 0.01f*t; bi3c[r1*68 + col+1] = v;
            }
        }
        __syncthreads();

        // D) stats (exp without max — values bounded) + bisum + GEMM2
#pragma unroll
        for (int j = 0; j < 2; j++) {
            int b = 2*wid + j;
#pragma unroll
            for (int h = 0; h < 2; h++) {
                int c = lane + ((h) ? 32 : 0);
                float e0 = __expf(bi3c[b*68 + c]);
                float e1 = __expf(bi3c[(16+b)*68 + c]);
                float e2 = __expf(bi3c[(32+b)*68 + c]);
                float xa = __expf(xr[(j*3+0)*2+h]);
                float xv = __expf(xr[(j*3+1)*2+h]);
                float xl = __expf(xr[(j*3+2)*2+h]);
                sE[j][0] += e0; sE[j][1] += e1; sE[j][2] += e2;
                sX[j][0] += xa; sX[j][1] += xv; sX[j][2] += xl;
                sP[j][0] = fmaf(e0, e2, sP[j][0]);
                sP[j][1] = fmaf(e0, e1, sP[j][1]);
                sP[j][2] = fmaf(e1, e2, sP[j][2]);
                sQ[j][0] = fmaf(e0, xl, sQ[j][0]);
                sQ[j][1] = fmaf(e1, xv, sQ[j][1]);
                sQ[j][2] = fmaf(e2, xa, sQ[j][2]);
            }
        }
        for (int i = tid; i < 1024; i += 256) {
            int b = i >> 6, c = i & 63;
            g_bisum[(size_t)(bb0 + b)*1024 + n0 + c] =
                bi3c[b*68 + c] + bi3c[(16+b)*68 + c] + bi3c[(32+b)*68 + c];
        }
        if (wid < 6) {
#pragma unroll
            for (int ks = 0; ks < 8; ks++) {
                unsigned a[4], bf[8][2];
                int r = wm*16 + g;
                a[0] = __float_as_uint(bi3c[r*68 + ks*8 + t4]);
                a[1] = __float_as_uint(bi3c[(r+8)*68 + ks*8 + t4]);
                a[2] = __float_as_uint(bi3c[r*68 + ks*8 + t4 + 4]);
                a[3] = __float_as_uint(bi3c[(r+8)*68 + ks*8 + t4 + 4]);
#pragma unroll
                for (int q = 0; q < 8; q++) {
                    int c = wn*64 + q*8 + g;
                    bf[q][0] = __float_as_uint(W1s[(ks*8 + t4)*136 + c]);
                    bf[q][1] = __float_as_uint(W1s[(ks*8 + t4 + 4)*136 + c]);
                }
#pragma unroll
                for (int q = 0; q < 8; q++) mma_tf32(pq2[q], a, bf[q]);
            }
        }
        __syncthreads();
    }

    // ---- stats reduce -> w_tri ----
#pragma unroll
    for (int j = 0; j < 2; j++) {
#pragma unroll
        for (int o = 16; o > 0; o >>= 1) {
#pragma unroll
            for (int v = 0; v < 3; v++) {
                sE[j][v] += __shfl_down_sync(0xffffffffu, sE[j][v], o);
                sX[j][v] += __shfl_down_sync(0xffffffffu, sX[j][v], o);
                sP[j][v] += __shfl_down_sync(0xffffffffu, sP[j][v], o);
                sQ[j][v] += __shfl_down_sync(0xffffffffu, sQ[j][v], o);
            }
        }
    }
    if (lane == 0) {
#pragma unroll
        for (int j = 0; j < 2; j++) {
            int b = bb0 + 2*wid + j;
            float d0 = sP[j][0] / (sE[j][0]*sE[j][2]);
            float d1 = sP[j][1] / (sE[j][0]*sE[j][1]);
            float d2 = sP[j][2] / (sE[j][1]*sE[j][2]);
            float d3 = sQ[j][0] / (sE[j][0]*sX[j][2]);
            float d4 = sQ[j][1] / (sE[j][1]*sX[j][1]);
            float d5 = sQ[j][2] / (sE[j][2]*sX[j][0]);
            float sa = g_wuni[b*3+0], sv = g_wuni[b*3+1], sl = g_wuni[b*3+2];
            float sav = g_sbi[b*3+0], sal = g_sbi[b*3+1], svl = g_sbi[b*3+2];
            float nn[6];
            nn[0] = (sav + svl)/(d0 + 0.5f);
            nn[1] = (sav + sal)/(d1 + 0.5f);
            nn[2] = (sal + svl)/(d2 + 0.5f);
            nn[3] = (sav + sl )/(d3 + 0.5f);
            nn[4] = (sal + sv )/(d4 + 0.5f);
            nn[5] = (sa  + svl)/(d5 + 0.5f);
            float m = nn[0];
#pragma unroll
            for (int k = 1; k < 6; k++) m = fmaxf(m, nn[k]);
            float e[6], ss = 0.f;
#pragma unroll
            for (int k = 0; k < 6; k++) { e[k] = expf(nn[k]-m); ss += e[k]; }
            float inv = 1.f/ss;
#pragma unroll
            for (int k = 0; k < 6; k++) {
                g_wtri[(size_t)b*6 + k] = e[k]*inv;
                if (wflag) outW[(size_t)b*12 + 6 + k] = e[k]*inv;
            }
        }
    }

    // ---- PQ2 -> smem (reuse W1s as [48][136]) ----
    __syncthreads();
    if (wid < 6) {
        int r0 = wm*16 + g, r1 = r0 + 8;
#pragma unroll
        for (int q = 0; q < 8; q++) {
            int col = wn*64 + q*8 + t4*2;
            W1s[r0*136 + col]   = pq2[q].x;
            W1s[r0*136 + col+1] = pq2[q].y;
            W1s[r1*136 + col]   = pq2[q].z;
            W1s[r1*136 + col+1] = pq2[q].w;
        }
    }
    __syncthreads();
    // ---- act2 inline ----
    const int PR[6] = {0,0,2,0,1,2};
    const int QR[6] = {2,1,1,2,1,0};
    const int QS[6] = {0,0,0,1,1,1};
    for (int i = tid; i < 6144; i += 256) {
        int p = i >> 10, rem = i & 1023;
        int b = rem >> 6, k = rem & 63;
        float pv = W1s[(PR[p]*16 + b)*136 + k];
        float qv = QS[p] ? PQ1s[(QR[p]*16 + b)*132 + 64 + k]
                         : W1s[(QR[p]*16 + b)*136 + 64 + k];
        float tv = pv + qv + b1s[k];
        g_act2[((size_t)p*NB + bb0 + b)*64 + k] = tv > 0.f ? tv : 0.2f*tv;
    }
}

// -------------------------- k6: stage-2 gf second layer ---------------------
#define K6_SMEM ((2*128*68 + 64*72)*4)
__global__ __launch_bounds__(256) void k6_mma(const float* __restrict__ b2)
{
    extern __shared__ float sm6[];
    float* AsB = sm6;
    float* Bs  = sm6 + 2*128*68;
    int tid = threadIdx.x;
    int b0 = blockIdx.x * 128, n0 = blockIdx.y * 64;

    for (int i = tid; i < 1024; i += 256) {
        int k = i >> 4, c4 = i & 15;
        cpasync16(&Bs[k*72 + c4*4], &g_W2r[(size_t)k*1024 + n0 + c4*4]);
    }
    {
        const float* Ap = g_act2 + ((size_t)0*NB + b0)*64;
        for (int i = tid; i < 2048; i += 256) {
            int r = i >> 4, c4 = i & 15;
            cpasync16(&AsB[r*68 + c4*4], &Ap[(size_t)r*64 + c4*4]);
        }
    }
    CP_COMMIT;

    int lane = tid & 31, wid = tid >> 5;
    int g = lane >> 2, t4 = lane & 3;
    int wm = wid >> 1, wn = wid & 1;
    int rw = wm*32, cw = wn*32;

    float4 tri[2][4] = {};
#pragma unroll 1
    for (int p = 0; p < 6; p++) {
        if (p + 1 < 6) {
            const float* Ap = g_act2 + ((size_t)(p+1)*NB + b0)*64;
            float* Ad = AsB + ((p+1) & 1)*128*68;
            for (int i = tid; i < 2048; i += 256) {
                int r = i >> 4, c4 = i & 15;
                cpasync16(&Ad[r*68 + c4*4], &Ap[(size_t)r*64 + c4*4]);
            }
            CP_COMMIT;
            CP_WAIT1;
        } else {
            CP_WAIT0;
        }
        __syncthreads();
        float* As = AsB + (p & 1)*128*68;
        float4 acc[2][4] = {};
#pragma unroll
        for (int ks = 0; ks < 8; ks++) {
            unsigned a[2][4], bf[4][2];
#pragma unroll
            for (int m = 0; m < 2; m++) {
                int r = rw + m*16 + g;
                a[m][0] = __float_as_uint(As[r*68 + ks*8 + t4]);
                a[m][1] = __float_as_uint(As[(r+8)*68 + ks*8 + t4]);
                a[m][2] = __float_as_uint(As[r*68 + ks*8 + t4 + 4]);
                a[m][3] = __float_as_uint(As[(r+8)*68 + ks*8 + t4 + 4]);
            }
#pragma unroll
            for (int n = 0; n < 4; n++) {
                int c = cw + n*8 + g;
                bf[n][0] = __float_as_uint(Bs[(ks*8 + t4)*72 + c]);
                bf[n][1] = __float_as_uint(Bs[(ks*8 + t4 + 4)*72 + c]);
            }
#pragma unroll
            for (int m = 0; m < 2; m++)
#pragma unroll
            for (int n = 0; n < 4; n++)
                mma_tf32(acc[m][n], a[m], bf[n]);
        }
#pragma unroll
        for (int m = 0; m < 2; m++) {
            int r0 = b0 + rw + m*16 + g;
            int r1 = r0 + 8;
            float wt0 = g_wtri[(size_t)r0*6 + p];
            float wt1 = g_wtri[(size_t)r1*6 + p];
#pragma unroll
            for (int n = 0; n < 4; n++) {
                int col = n0 + cw + n*8 + t4*2;
                float2 b2v = *(const float2*)&b2[col];
                float q;
                q = tanhf(acc[m][n].x + b2v.x)*wt0; tri[m][n].x += (q > 0.f ? q : 0.01f*q);
                q = tanhf(acc[m][n].y + b2v.y)*wt0; tri[m][n].y += (q > 0.f ? q : 0.01f*q);
                q = tanhf(acc[m][n].z + b2v.x)*wt1; tri[m][n].z += (q > 0.f ? q : 0.01f*q);
                q = tanhf(acc[m][n].w + b2v.y)*wt1; tri[m][n].w += (q > 0.f ? q : 0.01f*q);
            }
        }
        __syncthreads();
    }
#pragma unroll
    for (int m = 0; m < 2; m++) {
        size_t r0 = b0 + rw + m*16 + g, r1 = r0 + 8;
#pragma unroll
        for (int n = 0; n < 4; n++) {
            int col = n0 + cw + n*8 + t4*2;
            float2 o0; o0.x = tri[m][n].x; o0.y = tri[m][n].y;
            float2 o1; o1.x = tri[m][n].z; o1.y = tri[m][n].w;
            *(float2*)&g_tri[r0*1024 + col] = o0;
            *(float2*)&g_tri[r1*1024 + col] = o1;
        }
    }
}

// -------------------------- k7: fused head (tf32 layer1) --------------------
#define K7_SMEM ((64*36 + 32*72 + 64*52*2 + 512 + 3000)*4)
__global__ __launch_bounds__(256) void k7_final(
    const float* __restrict__ bnb,
    const float* __restrict__ l1b,
    const float* __restrict__ l2W, const float* __restrict__ l2b,
    const float* __restrict__ l3W, const float* __restrict__ l3b,
    float* __restrict__ out)
{
    extern __shared__ float pool[];
    float* As  = pool;
    float* Bs  = pool + 2304;
    float* Y1  = pool + 4608;
    float* Y2  = pool + 7936;
    float* Y3  = pool + 11264;
    float* W23 = pool + 11776;
    int tid = threadIdx.x;
    int b0 = blockIdx.x * 64;
    int lane = tid & 31, wid = tid >> 5;
    int g = lane >> 2, t4 = lane & 3;
    int wm = wid >> 2, wn = wid & 3;
    int rw = wm*32, cw = wn*16;

    for (int i = tid; i < 2500; i += 256) {
        int k = i / 50, c = i - k*50;
        W23[k*52 + c] = l2W[i];
    }
    for (int i = tid; i < 400; i += 256) W23[2600 + i] = l3W[i];

    float4 acc[2][2] = {};
    for (int t = 0; t < 96; t++) {
        int kk = t * 32;
        int region = kk >> 10;
        const float* src = region == 0 ? g_uni : (region == 1 ? g_bisum : g_tri);
        __syncthreads();
        for (int i = tid; i < 512; i += 256) {
            int r = i >> 3, c4 = i & 7;
            float4 v = *(const float4*)&src[(size_t)(b0 + r)*1024 + (kk & 1023) + c4*4];
            int j = kk + c4*4;
            float* d = &As[r*36 + c4*4];
            d[0] = f2tf_f(fmaf(v.x, g_bnsc[j],   bnb[j]));
            d[1] = f2tf_f(fmaf(v.y, g_bnsc[j+1], bnb[j+1]));
            d[2] = f2tf_f(fmaf(v.z, g_bnsc[j+2], bnb[j+2]));
            d[3] = f2tf_f(fmaf(v.w, g_bnsc[j+3], bnb[j+3]));
        }
        for (int i = tid; i < 512; i += 256) {
            int k = i >> 4, c4 = i & 15;
            cpasync16(&Bs[k*72 + c4*4], &g_l1Wp[(size_t)(kk + k)*64 + c4*4]);
        }
        CP_COMMIT; CP_WAIT0;
        __syncthreads();
#pragma unroll
        for (int ks = 0; ks < 4; ks++) {
            unsigned a[2][4], bf[2][2];
#pragma unroll
            for (int m = 0; m < 2; m++) {
                int r = rw + m*16 + g;
                a[m][0] = __float_as_uint(As[r*36 + ks*8 + t4]);
                a[m][1] = __float_as_uint(As[(r+8)*36 + ks*8 + t4]);
                a[m][2] = __float_as_uint(As[r*36 + ks*8 + t4 + 4]);
                a[m][3] = __float_as_uint(As[(r+8)*36 + ks*8 + t4 + 4]);
            }
#pragma unroll
            for (int n = 0; n < 2; n++) {
                int c = cw + n*8 + g;
                bf[n][0] = __float_as_uint(Bs[(ks*8 + t4)*72 + c]);
                bf[n][1] = __float_as_uint(Bs[(ks*8 + t4 + 4)*72 + c]);
            }
#pragma unroll
            for (int m = 0; m < 2; m++)
#pragma unroll
            for (int n = 0; n < 2; n++)
                mma_tf32(acc[m][n], a[m], bf[n]);
        }
    }
    __syncthreads();
#pragma unroll
    for (int m = 0; m < 2; m++) {
        int r0 = rw + m*16 + g, r1 = r0 + 8;
#pragma unroll
        for (int n = 0; n < 2; n++) {
            int c = cw + n*8 + t4*2;
            if (c < 50)   { Y1[r0*52 + c]   = tanhf(acc[m][n].x + l1b[c]);
                            Y1[r1*52 + c]   = tanhf(acc[m][n].z + l1b[c]); }
            if (c+1 < 50) { Y1[r0*52 + c+1] = tanhf(acc[m][n].y + l1b[c+1]);
                            Y1[r1*52 + c+1] = tanhf(acc[m][n].w + l1b[c+1]); }
        }
    }
    __syncthreads();

    for (int o = tid; o < 3200; o += 256) {
        int r = o / 50, c = o - r*50;
        float a = l2b[c];
        for (int k = 0; k < 50; k++)
            a = fmaf(Y1[r*52 + k], W23[k*52 + c], a);
        Y2[r*52 + c] = tanhf(a);
    }
    __syncthreads();

    for (int o = tid; o < 512; o += 256) {
        int r = o >> 3, c = o & 7;
        float a = l3b[c];
        for (int k = 0; k < 50; k++)
            a = fmaf(Y2[r*52 + k], W23[2600 + k*8 + c], a);
        Y3[r*8 + c] = a;
    }
    __syncthreads();
    if (tid < 64) {
        int r = tid;
        float m = -1e30f;
#pragma unroll
        for (int c = 0; c < 8; c++) m = fmaxf(m, Y3[r*8 + c]);
        float e[8], s = 0.f;
#pragma unroll
        for (int c = 0; c < 8; c++) { e[c] = expf(Y3[r*8 + c] - m); s += e[c]; }
        float inv = 1.f / s;
        float* orow = out + (size_t)(b0 + r)*8;
#pragma unroll
        for (int c = 0; c < 8; c++) orow[c] = e[c]*inv;
    }
}

// -------------------------- launch ------------------------------------------
extern "C" void kernel_launch(void* const* d_in, const int* in_sizes, int n_in,
                              void* d_out, int out_size)
{
    const float* x    = (const float*)d_in[0];
    const float* attW = (const float*)d_in[1];
    const float* attb = (const float*)d_in[2];
    const float* gfW1 = (const float*)d_in[3];
    const float* gfb1 = (const float*)d_in[4];
    const float* gfW2 = (const float*)d_in[5];
    const float* gfb2 = (const float*)d_in[6];
    const float* bng  = (const float*)d_in[7];
    const float* bnb  = (const float*)d_in[8];
    const float* l1W  = (const float*)d_in[9];
    const float* l1b  = (const float*)d_in[10];
    const float* l2W  = (const float*)d_in[11];
    const float* l2b  = (const float*)d_in[12];
    const float* l3W  = (const float*)d_in[13];
    const float* l3b  = (const float*)d_in[14];
    float* out  = (float*)d_out;
    int wflag = (out_size >= NB*20) ? 1 : 0;
    float* outW = out + (size_t)NB*8;

    static int attr_done = 0;
    if (!attr_done) {
        cudaFuncSetAttribute(k_proj_mma, cudaFuncAttributeMaxDynamicSharedMemorySize, KP_SMEM);
        cudaFuncSetAttribute(kFuse,      cudaFuncAttributeMaxDynamicSharedMemorySize, KF_SMEM);
        cudaFuncSetAttribute(k6_mma,     cudaFuncAttributeMaxDynamicSharedMemorySize, K6_SMEM);
        cudaFuncSetAttribute(k7_final,   cudaFuncAttributeMaxDynamicSharedMemorySize, K7_SMEM);
        attr_done = 1;
    }

    k0_prep<<<1549, 256>>>(gfW1, gfW2, l1W, bng);
    k1_att<<<NB, 256>>>(x, attW, attb, outW, wflag);
    k_proj_mma<<<NR3/128, 256, KP_SMEM>>>(x);
    kFuse<<<NB/16, 256, KF_SMEM>>>(x, gfb1, gfb2, outW, wflag);
    dim3 g6(NB/128, 16);
    k6_mma<<<g6, 256, K6_SMEM>>>(gfb2);
    k7_final<<<NB/64, 256, K7_SMEM>>>(bnb, l1b, l2W, l2b, l3W, l3b, out);
}

// round 8
// speedup vs baseline: 2.9387x; 1.0229x over previous
#include <cuda_runtime.h>
#include <cstdint>
#include <cstddef>

// ---------------------------------------------------------------------------
// graph12 — Round 7: ldmatrix operand feeds (b16 x4 trick for tf32) +
//                    transposed weight layouts (g_W1t, g_W2t).
// ---------------------------------------------------------------------------

#define NB    16384
#define ND    1024
#define NR3   (NB*3)

__device__ float g_W1t  [128*1024];          // W1r transposed [n][k], tf32
__device__ float g_W2t  [1024*64];           // W2 transposed [n][k], tf32
__device__ float g_l1Wp [3072*64];           // tf32, padded 50->64
__device__ float g_bnsc [3072];
__device__ float g_PQ1  [(size_t)NR3*128];
__device__ float g_act2 [(size_t)6*NB*64];
__device__ float g_uni  [(size_t)NB*ND];
__device__ float g_bisum[(size_t)NB*ND];
__device__ float g_tri  [(size_t)NB*ND];
__device__ float g_wuni [NB*3];
__device__ float g_wbi  [NB*3];
__device__ float g_sbi  [NB*3];
__device__ float g_wtri [NB*6];

// -------------------------- helpers -----------------------------------------
__device__ __forceinline__ float f2tf_f(float f) {
    unsigned r;
    asm("cvt.rna.tf32.f32 %0, %1;" : "=r"(r) : "f"(f));
    return __uint_as_float(r);
}

__device__ __forceinline__ void mma_t(float4& d, unsigned a0, unsigned a1,
                                      unsigned a2, unsigned a3,
                                      unsigned b0, unsigned b1) {
    asm volatile(
        "mma.sync.aligned.m16n8k8.row.col.f32.tf32.tf32.f32 "
        "{%0,%1,%2,%3}, {%4,%5,%6,%7}, {%8,%9}, {%0,%1,%2,%3};"
        : "+f"(d.x), "+f"(d.y), "+f"(d.z), "+f"(d.w)
        : "r"(a0), "r"(a1), "r"(a2), "r"(a3), "r"(b0), "r"(b1));
}

__device__ __forceinline__ uint4 ldsm4(unsigned addr) {
    uint4 r;
    asm volatile("ldmatrix.sync.aligned.m8n8.x4.shared.b16 {%0,%1,%2,%3}, [%4];"
                 : "=r"(r.x), "=r"(r.y), "=r"(r.z), "=r"(r.w) : "r"(addr));
    return r;
}

// A-frag pointer: thread-invariant part for buffer (u32 base), stride S floats.
__device__ __forceinline__ unsigned a_ptr(unsigned base, int rbase, int S, int lane) {
    return base + ((rbase + (lane & 15))*S + ((lane & 16) >> 2))*4;
}
// B-frag pointer for TRANSPOSED weight buffer [n][k], stride St floats.
__device__ __forceinline__ unsigned b_ptr(unsigned base, int nbase, int St, int lane) {
    return base + ((nbase + (lane & 7) + ((lane & 16) >> 1))*St + ((lane & 8) >> 1))*4;
}

__device__ __forceinline__ void cpasync16(float* dst_smem, const float* src) {
    unsigned d = (unsigned)__cvta_generic_to_shared(dst_smem);
    asm volatile("cp.async.cg.shared.global [%0], [%1], 16;" :: "r"(d), "l"(src));
}
#define CP_COMMIT  asm volatile("cp.async.commit_group;")
#define CP_WAIT0   asm volatile("cp.async.wait_group 0;")
#define CP_WAIT1   asm volatile("cp.async.wait_group 1;")

// -------------------------- block reductions (256 thr) ----------------------
template<int NV>
__device__ __forceinline__ void blockReduceSumN(float* v, float* rbuf) {
    int tid = threadIdx.x, lane = tid & 31, w = tid >> 5;
#pragma unroll
    for (int n = 0; n < NV; n++) {
        float x = v[n];
#pragma unroll
        for (int o = 16; o > 0; o >>= 1) x += __shfl_down_sync(0xffffffffu, x, o);
        if (lane == 0) rbuf[n*8 + w] = x;
    }
    __syncthreads();
    if (tid < NV) {
        float s = rbuf[tid*8];
#pragma unroll
        for (int q = 1; q < 8; q++) s += rbuf[tid*8 + q];
        rbuf[tid*8] = s;
    }
    __syncthreads();
#pragma unroll
    for (int n = 0; n < NV; n++) v[n] = rbuf[n*8];
    __syncthreads();
}

template<int NV>
__device__ __forceinline__ void blockReduceMaxN(float* v, float* rbuf) {
    int tid = threadIdx.x, lane = tid & 31, w = tid >> 5;
#pragma unroll
    for (int n = 0; n < NV; n++) {
        float x = v[n];
#pragma unroll
        for (int o = 16; o > 0; o >>= 1) x = fmaxf(x, __shfl_down_sync(0xffffffffu, x, o));
        if (lane == 0) rbuf[n*8 + w] = x;
    }
    __syncthreads();
    if (tid < NV) {
        float s = rbuf[tid*8];
#pragma unroll
        for (int q = 1; q < 8; q++) s = fmaxf(s, rbuf[tid*8 + q]);
        rbuf[tid*8] = s;
    }
    __syncthreads();
#pragma unroll
    for (int n = 0; n < NV; n++) v[n] = rbuf[n*8];
    __syncthreads();
}

// -------------------------- k0: prep ----------------------------------------
__global__ void k0_prep(const float* __restrict__ W1, const float* __restrict__ W2,
                        const float* __restrict__ l1W, const float* __restrict__ bng)
{
    int i = blockIdx.x * 256 + threadIdx.x;
    if (i < 131072) {                         // g_W1t[n][k] = W1r(k,n)
        int n = i >> 10, k = i & 1023;
        float v = (n < 64) ? W1[(size_t)k*64 + n] : W1[(size_t)(1024 + k)*64 + (n - 64)];
        g_W1t[i] = f2tf_f(v);
    } else if (i < 196608) {                  // g_W2t[n][k] = W2[k][n]
        int i2 = i - 131072;
        int n = i2 >> 6, k = i2 & 63;
        g_W2t[i2] = f2tf_f(W2[(size_t)k*1024 + n]);
    } else if (i < 393216) {                  // l1Wp
        int i3 = i - 196608;
        int row = i3 >> 6, c = i3 & 63;
        g_l1Wp[i3] = (c < 50) ? f2tf_f(l1W[(size_t)row*50 + c]) : 0.f;
    } else if (i < 396288) {                  // bnsc
        int j = i - 393216;
        float mult = (j < 1024) ? 1.f : ((j < 2048) ? (1.f/3.f) : (1.f/6.f));
        g_bnsc[j] = bng[j] * rsqrtf(1.0f + 1e-5f) * mult;
    }
}

// -------------------------- k1: attention + stage-1 stats -------------------
__global__ __launch_bounds__(256) void k1_att(
    const float* __restrict__ x, const float* __restrict__ attW,
    const float* __restrict__ attb, float* __restrict__ outW, int wflag)
{
    __shared__ float sm[3072];
    __shared__ float rbuf[6*8];
    __shared__ float bc[4];
    int b = blockIdx.x, tid = threadIdx.x;
    const float4* xr4 = (const float4*)(x + (size_t)b*3072);
    for (int i = tid; i < 768; i += 256) ((float4*)sm)[i] = xr4[i];
    __syncthreads();

    float red[3];
    float a0 = 0.f, a1 = 0.f, a2 = 0.f;
    float m0 = -1e30f, m1 = -1e30f, m2 = -1e30f;
    for (int i = tid; i < 1024; i += 256) {
        float w = attW[i];
        float av = sm[i], vv = sm[1024 + i], lv = sm[2048 + i];
        a0 = fmaf(av, w, a0); a1 = fmaf(vv, w, a1); a2 = fmaf(lv, w, a2);
        m0 = fmaxf(m0, av);  m1 = fmaxf(m1, vv);  m2 = fmaxf(m2, lv);
    }
    red[0] = a0; red[1] = a1; red[2] = a2;
    blockReduceSumN<3>(red, rbuf);
    float att0 = red[0], att1 = red[1], att2 = red[2];
    red[0] = m0; red[1] = m1; red[2] = m2;
    blockReduceMaxN<3>(red, rbuf);
    float Ma = red[0], Mv = red[1], Ml = red[2];

    float red6[6] = {0.f, 0.f, 0.f, 0.f, 0.f, 0.f};
    for (int i = tid; i < 1024; i += 256) {
        float ea = expf(sm[i] - Ma);
        float ev = expf(sm[1024 + i] - Mv);
        float el = expf(sm[2048 + i] - Ml);
        red6[0] += ea; red6[1] += ev; red6[2] += el;
        red6[3] = fmaf(ea, ev, red6[3]);
        red6[4] = fmaf(ea, el, red6[4]);
        red6[5] = fmaf(ev, el, red6[5]);
    }
    blockReduceSumN<6>(red6, rbuf);

    if (tid == 0) {
        float ab = attb[0];
        float t0 = tanhf(att0 + ab), t1 = tanhf(att1 + ab), t2 = tanhf(att2 + ab);
        float mm = fmaxf(t0, fmaxf(t1, t2));
        float e0 = expf(t0 - mm), e1 = expf(t1 - mm), e2 = expf(t2 - mm);
        float inv = 1.f / (e0 + e1 + e2);
        float sa = e0*inv, sv = e1*inv, sl = e2*inv;
        float dav = red6[3] / (red6[0]*red6[1]);
        float dal = red6[4] / (red6[0]*red6[2]);
        float dvl = red6[5] / (red6[1]*red6[2]);
        float sav = (sa + sv) / (dav + 0.5f);
        float sal = (sa + sl) / (dal + 0.5f);
        float svl = (sl + sv) / (dvl + 0.5f);
        g_wuni[b*3+0] = sa; g_wuni[b*3+1] = sv; g_wuni[b*3+2] = sl;
        g_sbi [b*3+0] = sav; g_sbi[b*3+1] = sal; g_sbi[b*3+2] = svl;
        float m3 = fmaxf(sav, fmaxf(sal, svl));
        float f0 = expf(sav - m3), f1 = expf(sal - m3), f2 = expf(svl - m3);
        float fi = 1.f / (f0 + f1 + f2);
        g_wbi[b*3+0] = f0*fi; g_wbi[b*3+1] = f1*fi; g_wbi[b*3+2] = f2*fi;
        if (wflag) {
            float* o = outW + (size_t)b*12;
            o[0] = sa; o[1] = sv; o[2] = sl;
            o[3] = f0*fi; o[4] = f1*fi; o[5] = f2*fi;
        }
        bc[0] = sa; bc[1] = sv; bc[2] = sl;
    }
    __syncthreads();
    float sa = bc[0], sv = bc[1], sl = bc[2];
    float* ur = g_uni + (size_t)b*1024;
    for (int i = tid; i < 1024; i += 256)
        ur[i] = (sa*sm[i] + sv*sm[1024+i] + sl*sm[2048+i]) * (1.0f/3.0f);
}

// -------------------------- kP: PQ1 projection (ldmatrix, 3-stage) ----------
// C[49152,128] = A[49152,1024] @ W1r;  B staged transposed [128 n][32 k].
#define KP_STAGE (128*36 * 2)
#define KP_SMEM  (3*KP_STAGE*4)

__device__ __forceinline__ void kp_issue(const float* __restrict__ A, size_t m0,
                                         float* stage, int t, int tid)
{
    float* As  = stage;                 // [128][36]
    float* Bts = stage + 128*36;        // [128][36]
    int kk = t * 32;
#pragma unroll
    for (int j = 0; j < 4; j++) {
        int i = tid + j*256;
        int r = i >> 3, kq = i & 7;
        cpasync16(&As[r*36 + kq*4], &A[(m0 + r)*1024 + kk + kq*4]);
    }
#pragma unroll
    for (int j = 0; j < 4; j++) {
        int i = tid + j*256;
        int n = i >> 3, kq = i & 7;
        cpasync16(&Bts[n*36 + kq*4], &g_W1t[(size_t)n*1024 + kk + kq*4]);
    }
    CP_COMMIT;
}

__global__ __launch_bounds__(256) void k_proj_mma(const float* __restrict__ x)
{
    extern __shared__ float smp[];
    int tid = threadIdx.x;
    size_t m0 = (size_t)blockIdx.x * 128;
    int lane = tid & 31, wid = tid >> 5;
    int t4 = lane & 3, g = lane >> 2;
    int wm = wid >> 1, wn = wid & 1;

    float4 acc[2][8] = {};

    kp_issue(x, m0, smp,            0, tid);
    kp_issue(x, m0, smp + KP_STAGE, 1, tid);

    int s = 0;
    for (int t = 0; t < 32; t++) {
        if (t < 31) { CP_WAIT1; } else { CP_WAIT0; }
        __syncthreads();
        if (t + 2 < 32)
            kp_issue(x, m0, smp + ((s + 2) % 3)*KP_STAGE, t + 2, tid);
        float* Ac = smp + s*KP_STAGE;
        unsigned Au = (unsigned)__cvta_generic_to_shared(Ac);
        unsigned Bu = Au + 128*36*4;
        unsigned pA0 = a_ptr(Au, wm*32,      36, lane);
        unsigned pA1 = pA0 + 16*36*4;
        unsigned pB  = b_ptr(Bu, wn*64, 36, lane);
#pragma unroll
        for (int ks = 0; ks < 4; ks++) {
            uint4 a0 = ldsm4(pA0 + ks*32);
            uint4 a1 = ldsm4(pA1 + ks*32);
            uint4 bv[4];
#pragma unroll
            for (int p = 0; p < 4; p++) bv[p] = ldsm4(pB + p*16*36*4 + ks*32);
#pragma unroll
            for (int n = 0; n < 8; n++) {
                unsigned b0 = (n & 1) ? bv[n>>1].z : bv[n>>1].x;
                unsigned b1 = (n & 1) ? bv[n>>1].w : bv[n>>1].y;
                mma_t(acc[0][n], a0.x, a0.y, a0.z, a0.w, b0, b1);
                mma_t(acc[1][n], a1.x, a1.y, a1.z, a1.w, b0, b1);
            }
        }
        s = (s + 1) % 3;
    }
#pragma unroll
    for (int m = 0; m < 2; m++) {
        size_t r0 = m0 + wm*32 + m*16 + g;
        size_t r1 = r0 + 8;
#pragma unroll
        for (int n = 0; n < 8; n++) {
            int col = wn*64 + n*8 + t4*2;
            float2 o0; o0.x = acc[m][n].x; o0.y = acc[m][n].y;
            float2 o1; o1.x = acc[m][n].z; o1.y = acc[m][n].w;
            *(float2*)&g_PQ1[r0*128 + col] = o0;
            *(float2*)&g_PQ1[r1*128 + col] = o1;
        }
    }
}

// -------------------------- kFuse: stage-2 megafusion (ldmatrix) ------------
#define KF_PQ1   0                         // [48][132] = 6336
#define KF_ACT1  6336                      // [48][68]  = 3264
#define KF_BI3   9600                      // [48][68]  = 3264
#define KF_W2    12864                     // W2t chunk [64][68] = 4352
#define KF_W1    17216                     // W1t chunk [128][68] = 8704 (reused PQ2s [48][136])
#define KF_B1    25920
#define KF_WBI   25984
#define KF_TOTF  (25984+48+16)
#define KF_SMEM  (KF_TOTF*4)

__global__ __launch_bounds__(256) void kFuse(
    const float* __restrict__ x, const float* __restrict__ b1,
    const float* __restrict__ b2, float* __restrict__ outW, int wflag)
{
    extern __shared__ float sf[];
    float* PQ1s = sf + KF_PQ1;
    float* act1s= sf + KF_ACT1;
    float* bi3c = sf + KF_BI3;
    float* W2ts = sf + KF_W2;
    float* W1ts = sf + KF_W1;
    float* b1s  = sf + KF_B1;
    float* wbis = sf + KF_WBI;

    int tid = threadIdx.x;
    int bb0 = blockIdx.x * 16;
    int lane = tid & 31, wid = tid >> 5;
    int t4 = lane & 3, g = lane >> 2;
    int wm = wid >> 1, wn = wid & 1;

    for (int i = tid; i < 1536; i += 256) {
        int r = i >> 5, c4 = i & 31;
        int p = r >> 4, b = r & 15;
        cpasync16(&PQ1s[r*132 + c4*4], &g_PQ1[((size_t)(bb0 + b)*3 + p)*128 + c4*4]);
    }
    CP_COMMIT;
    if (tid < 64) b1s[tid] = b1[tid];
    if (tid < 48) { int p = tid >> 4, b = tid & 15; wbis[tid] = g_wbi[(bb0 + b)*3 + p]; }
    CP_WAIT0;
    __syncthreads();
    for (int i = tid; i < 3072; i += 256) {
        int r = i >> 6, k = i & 63;
        int p = r >> 4, b = r & 15;
        int f = (p == 2) ? 1 : 0;
        int s = (p == 0) ? 1 : 2;
        float tv = PQ1s[(f*16+b)*132 + k] + PQ1s[(s*16+b)*132 + 64 + k] + b1s[k];
        act1s[r*68 + k] = tv > 0.f ? tv : 0.2f*tv;
    }
    __syncthreads();

    unsigned act1u = (unsigned)__cvta_generic_to_shared(act1s);
    unsigned bi3u  = (unsigned)__cvta_generic_to_shared(bi3c);
    unsigned w2tu  = (unsigned)__cvta_generic_to_shared(W2ts);
    unsigned w1tu  = (unsigned)__cvta_generic_to_shared(W1ts);
    unsigned pA1 = a_ptr(act1u, wm*16, 68, lane);
    unsigned pA2 = a_ptr(bi3u,  wm*16, 68, lane);
    unsigned pB1 = b_ptr(w2tu, wn*32, 68, lane);
    unsigned pB2 = b_ptr(w1tu, wn*64, 68, lane);

    float sE[2][3] = {}, sX[2][3] = {}, sP[2][3] = {}, sQ[2][3] = {};
    float4 pq2[8] = {};

    for (int n = 0; n < 16; n++) {
        int n0 = n * 64;
        for (int i = tid; i < 1024; i += 256) {
            int r = i >> 4, c4 = i & 15;
            cpasync16(&W2ts[r*68 + c4*4], &g_W2t[(size_t)(n0 + r)*64 + c4*4]);
        }
        for (int i = tid; i < 2048; i += 256) {
            int r = i >> 4, c4 = i & 15;
            cpasync16(&W1ts[r*68 + c4*4], &g_W1t[(size_t)r*1024 + n0 + c4*4]);
        }
        CP_COMMIT;
        float xr[12];
#pragma unroll
        for (int j = 0; j < 2; j++)
#pragma unroll
        for (int m = 0; m < 3; m++)
#pragma unroll
        for (int h = 0; h < 2; h++)
            xr[(j*3+m)*2+h] = x[((size_t)(bb0 + 2*wid + j)*3 + m)*1024 + n0 + lane + h*32];
        CP_WAIT0;
        __syncthreads();

        // GEMM1: act1[48,64k] @ W2 chunk -> bi3c [48][64]
        if (wid < 6) {
            float4 acc[4] = {};
#pragma unroll
            for (int ks = 0; ks < 8; ks++) {
                uint4 a  = ldsm4(pA1 + ks*32);
                uint4 b0 = ldsm4(pB1 + ks*32);
                uint4 b1v= ldsm4(pB1 + 16*68*4 + ks*32);
                mma_t(acc[0], a.x,a.y,a.z,a.w, b0.x, b0.y);
                mma_t(acc[1], a.x,a.y,a.z,a.w, b0.z, b0.w);
                mma_t(acc[2], a.x,a.y,a.z,a.w, b1v.x, b1v.y);
                mma_t(acc[3], a.x,a.y,a.z,a.w, b1v.z, b1v.w);
            }
            int r0 = wm*16 + g, r1 = r0 + 8;
            float w0 = wbis[r0], w1 = wbis[r1];
#pragma unroll
            for (int q = 0; q < 4; q++) {
                int col = wn*32 + q*8 + t4*2;
                float2 b2v = *(const float2*)&b2[n0 + col];
                float t, v;
                t = tanhf(acc[q].x + b2v.x)*w0; v = t > 0.f ? t : 0.01f*t; bi3c[r0*68 + col]   = v;
                t = tanhf(acc[q].y + b2v.y)*w0; v = t > 0.f ? t : 0.01f*t; bi3c[r0*68 + col+1] = v;
                t = tanhf(acc[q].z + b2v.x)*w1; v = t > 0.f ? t : 0.01f*t; bi3c[r1*68 + col]   = v;
                t = tanhf(acc[q].w + b2v.y)*w1; v = t > 0.f ? t : 0.01f*t; bi3c[r1*68 + col+1] = v;
            }
        }
        __syncthreads();

        // stats + bisum + GEMM2
#pragma unroll
        for (int j = 0; j < 2; j++) {
            int b = 2*wid + j;
#pragma unroll
            for (int h = 0; h < 2; h++) {
                int c = lane + (h ? 32 : 0);
                float e0 = __expf(bi3c[b*68 + c]);
                float e1 = __expf(bi3c[(16+b)*68 + c]);
                float e2 = __expf(bi3c[(32+b)*68 + c]);
                float xa = __expf(xr[(j*3+0)*2+h]);
                float xv = __expf(xr[(j*3+1)*2+h]);
                float xl = __expf(xr[(j*3+2)*2+h]);
                sE[j][0] += e0; sE[j][1] += e1; sE[j][2] += e2;
                sX[j][0] += xa; sX[j][1] += xv; sX[j][2] += xl;
                sP[j][0] = fmaf(e0, e2, sP[j][0]);
                sP[j][1] = fmaf(e0, e1, sP[j][1]);
                sP[j][2] = fmaf(e1, e2, sP[j][2]);
                sQ[j][0] = fmaf(e0, xl, sQ[j][0]);
                sQ[j][1] = fmaf(e1, xv, sQ[j][1]);
                sQ[j][2] = fmaf(e2, xa, sQ[j][2]);
            }
        }
        for (int i = tid; i < 1024; i += 256) {
            int b = i >> 6, c = i & 63;
            g_bisum[(size_t)(bb0 + b)*1024 + n0 + c] =
                bi3c[b*68 + c] + bi3c[(16+b)*68 + c] + bi3c[(32+b)*68 + c];
        }
        if (wid < 6) {
#pragma unroll
            for (int ks = 0; ks < 8; ks++) {
                uint4 a = ldsm4(pA2 + ks*32);
                uint4 bv[4];
#pragma unroll
                for (int p = 0; p < 4; p++) bv[p] = ldsm4(pB2 + p*16*68*4 + ks*32);
#pragma unroll
                for (int q = 0; q < 8; q++) {
                    unsigned b0 = (q & 1) ? bv[q>>1].z : bv[q>>1].x;
                    unsigned b1 = (q & 1) ? bv[q>>1].w : bv[q>>1].y;
                    mma_t(pq2[q], a.x,a.y,a.z,a.w, b0, b1);
                }
            }
        }
        __syncthreads();
    }

    // ---- stats reduce -> w_tri ----
#pragma unroll
    for (int j = 0; j < 2; j++) {
#pragma unroll
        for (int o = 16; o > 0; o >>= 1) {
#pragma unroll
            for (int v = 0; v < 3; v++) {
                sE[j][v] += __shfl_down_sync(0xffffffffu, sE[j][v], o);
                sX[j][v] += __shfl_down_sync(0xffffffffu, sX[j][v], o);
                sP[j][v] += __shfl_down_sync(0xffffffffu, sP[j][v], o);
                sQ[j][v] += __shfl_down_sync(0xffffffffu, sQ[j][v], o);
            }
        }
    }
    if (lane == 0) {
#pragma unroll
        for (int j = 0; j < 2; j++) {
            int b = bb0 + 2*wid + j;
            float d0 = sP[j][0] / (sE[j][0]*sE[j][2]);
            float d1 = sP[j][1] / (sE[j][0]*sE[j][1]);
            float d2 = sP[j][2] / (sE[j][1]*sE[j][2]);
            float d3 = sQ[j][0] / (sE[j][0]*sX[j][2]);
            float d4 = sQ[j][1] / (sE[j][1]*sX[j][1]);
            float d5 = sQ[j][2] / (sE[j][2]*sX[j][0]);
            float sa = g_wuni[b*3+0], sv = g_wuni[b*3+1], sl = g_wuni[b*3+2];
            float sav = g_sbi[b*3+0], sal = g_sbi[b*3+1], svl = g_sbi[b*3+2];
            float nn[6];
            nn[0] = (sav + svl)/(d0 + 0.5f);
            nn[1] = (sav + sal)/(d1 + 0.5f);
            nn[2] = (sal + svl)/(d2 + 0.5f);
            nn[3] = (sav + sl )/(d3 + 0.5f);
            nn[4] = (sal + sv )/(d4 + 0.5f);
            nn[5] = (sa  + svl)/(d5 + 0.5f);
            float m = nn[0];
#pragma unroll
            for (int k = 1; k < 6; k++) m = fmaxf(m, nn[k]);
            float e[6], ss = 0.f;
#pragma unroll
            for (int k = 0; k < 6; k++) { e[k] = expf(nn[k]-m); ss += e[k]; }
            float inv = 1.f/ss;
#pragma unroll
            for (int k = 0; k < 6; k++) {
                g_wtri[(size_t)b*6 + k] = e[k]*inv;
                if (wflag) outW[(size_t)b*12 + 6 + k] = e[k]*inv;
            }
        }
    }

    // ---- PQ2 -> smem (reuse W1ts region as [48][136]) ----
    __syncthreads();
    if (wid < 6) {
        int r0 = wm*16 + g, r1 = r0 + 8;
#pragma unroll
        for (int q = 0; q < 8; q++) {
            int col = wn*64 + q*8 + t4*2;
            W1ts[r0*136 + col]   = pq2[q].x;
            W1ts[r0*136 + col+1] = pq2[q].y;
            W1ts[r1*136 + col]   = pq2[q].z;
            W1ts[r1*136 + col+1] = pq2[q].w;
        }
    }
    __syncthreads();
    // ---- act2 ----
    const int PR[6] = {0,0,2,0,1,2};
    const int QR[6] = {2,1,1,2,1,0};
    const int QS[6] = {0,0,0,1,1,1};
    for (int i = tid; i < 6144; i += 256) {
        int p = i >> 10, rem = i & 1023;
        int b = rem >> 6, k = rem & 63;
        float pv = W1ts[(PR[p]*16 + b)*136 + k];
        float qv = QS[p] ? PQ1s[(QR[p]*16 + b)*132 + 64 + k]
                         : W1ts[(QR[p]*16 + b)*136 + 64 + k];
        float tv = pv + qv + b1s[k];
        g_act2[((size_t)p*NB + bb0 + b)*64 + k] = tv > 0.f ? tv : 0.2f*tv;
    }
}

// -------------------------- k6: stage-2 second layer (ldmatrix) -------------
#define K6_SMEM ((2*128*68 + 64*68)*4)
__global__ __launch_bounds__(256) void k6_mma(const float* __restrict__ b2)
{
    extern __shared__ float sm6[];
    float* AsB  = sm6;                  // [2][128*68]
    float* W2ts = sm6 + 2*128*68;       // [64][68]
    int tid = threadIdx.x;
    int b0 = blockIdx.x * 128, n0 = blockIdx.y * 64;

    for (int i = tid; i < 1024; i += 256) {
        int r = i >> 4, c4 = i & 15;
        cpasync16(&W2ts[r*68 + c4*4], &g_W2t[(size_t)(n0 + r)*64 + c4*4]);
    }
    {
        const float* Ap = g_act2 + ((size_t)0*NB + b0)*64;
        for (int i = tid; i < 2048; i += 256) {
            int r = i >> 4, c4 = i & 15;
            cpasync16(&AsB[r*68 + c4*4], &Ap[(size_t)r*64 + c4*4]);
        }
    }
    CP_COMMIT;

    int lane = tid & 31, wid = tid >> 5;
    int t4 = lane & 3, g = lane >> 2;
    int wm = wid >> 1, wn = wid & 1;
    int rw = wm*32, cw = wn*32;

    unsigned w2tu = (unsigned)__cvta_generic_to_shared(W2ts);
    unsigned pB  = b_ptr(w2tu, cw, 68, lane);
    unsigned As0u = (unsigned)__cvta_generic_to_shared(AsB);

    float4 tri[2][4] = {};
#pragma unroll 1
    for (int p = 0; p < 6; p++) {
        if (p + 1 < 6) {
            const float* Ap = g_act2 + ((size_t)(p+1)*NB + b0)*64;
            float* Ad = AsB + ((p+1) & 1)*128*68;
            for (int i = tid; i < 2048; i += 256) {
                int r = i >> 4, c4 = i & 15;
                cpasync16(&Ad[r*68 + c4*4], &Ap[(size_t)r*64 + c4*4]);
            }
            CP_COMMIT;
            CP_WAIT1;
        } else {
            CP_WAIT0;
        }
        __syncthreads();
        unsigned Au = As0u + (unsigned)((p & 1)*128*68*4);
        unsigned pA0 = a_ptr(Au, rw, 68, lane);
        unsigned pA1 = pA0 + 16*68*4;
        float4 acc[2][4] = {};
#pragma unroll
        for (int ks = 0; ks < 8; ks++) {
            uint4 a0 = ldsm4(pA0 + ks*32);
            uint4 a1 = ldsm4(pA1 + ks*32);
            uint4 b0 = ldsm4(pB + ks*32);
            uint4 b1v= ldsm4(pB + 16*68*4 + ks*32);
            mma_t(acc[0][0], a0.x,a0.y,a0.z,a0.w, b0.x, b0.y);
            mma_t(acc[0][1], a0.x,a0.y,a0.z,a0.w, b0.z, b0.w);
            mma_t(acc[0][2], a0.x,a0.y,a0.z,a0.w, b1v.x, b1v.y);
            mma_t(acc[0][3], a0.x,a0.y,a0.z,a0.w, b1v.z, b1v.w);
            mma_t(acc[1][0], a1.x,a1.y,a1.z,a1.w, b0.x, b0.y);
            mma_t(acc[1][1], a1.x,a1.y,a1.z,a1.w, b0.z, b0.w);
            mma_t(acc[1][2], a1.x,a1.y,a1.z,a1.w, b1v.x, b1v.y);
            mma_t(acc[1][3], a1.x,a1.y,a1.z,a1.w, b1v.z, b1v.w);
        }
#pragma unroll
        for (int m = 0; m < 2; m++) {
            int r0 = b0 + rw + m*16 + g;
            int r1 = r0 + 8;
            float wt0 = g_wtri[(size_t)r0*6 + p];
            float wt1 = g_wtri[(size_t)r1*6 + p];
#pragma unroll
            for (int q = 0; q < 4; q++) {
                int col = n0 + cw + q*8 + t4*2;
                float2 b2v = *(const float2*)&b2[col];
                float t;
                t = tanhf(acc[m][q].x + b2v.x)*wt0; tri[m][q].x += (t > 0.f ? t : 0.01f*t);
                t = tanhf(acc[m][q].y + b2v.y)*wt0; tri[m][q].y += (t > 0.f ? t : 0.01f*t);
                t = tanhf(acc[m][q].z + b2v.x)*wt1; tri[m][q].z += (t > 0.f ? t : 0.01f*t);
                t = tanhf(acc[m][q].w + b2v.y)*wt1; tri[m][q].w += (t > 0.f ? t : 0.01f*t);
            }
        }
        __syncthreads();
    }
#pragma unroll
    for (int m = 0; m < 2; m++) {
        size_t r0 = b0 + rw + m*16 + g, r1 = r0 + 8;
#pragma unroll
        for (int q = 0; q < 4; q++) {
            int col = n0 + cw + q*8 + t4*2;
            float2 o0; o0.x = tri[m][q].x; o0.y = tri[m][q].y;
            float2 o1; o1.x = tri[m][q].z; o1.y = tri[m][q].w;
            *(float2*)&g_tri[r0*1024 + col] = o0;
            *(float2*)&g_tri[r1*1024 + col] = o1;
        }
    }
}

// -------------------------- k7: fused head (tf32 layer1) --------------------
#define K7_SMEM ((64*36 + 32*72 + 64*52*2 + 512 + 3000)*4)
__global__ __launch_bounds__(256) void k7_final(
    const float* __restrict__ bnb,
    const float* __restrict__ l1b,
    const float* __restrict__ l2W, const float* __restrict__ l2b,
    const float* __restrict__ l3W, const float* __restrict__ l3b,
    float* __restrict__ out)
{
    extern __shared__ float pool[];
    float* As  = pool;
    float* Bs  = pool + 2304;
    float* Y1  = pool + 4608;
    float* Y2  = pool + 7936;
    float* Y3  = pool + 11264;
    float* W23 = pool + 11776;
    int tid = threadIdx.x;
    int b0 = blockIdx.x * 64;
    int lane = tid & 31, wid = tid >> 5;
    int g = lane >> 2, t4 = lane & 3;
    int wm = wid >> 2, wn = wid & 3;
    int rw = wm*32, cw = wn*16;

    for (int i = tid; i < 2500; i += 256) {
        int k = i / 50, c = i - k*50;
        W23[k*52 + c] = l2W[i];
    }
    for (int i = tid; i < 400; i += 256) W23[2600 + i] = l3W[i];

    float4 acc[2][2] = {};
    for (int t = 0; t < 96; t++) {
        int kk = t * 32;
        int region = kk >> 10;
        const float* src = region == 0 ? g_uni : (region == 1 ? g_bisum : g_tri);
        __syncthreads();
        for (int i = tid; i < 512; i += 256) {
            int r = i >> 3, c4 = i & 7;
            float4 v = *(const float4*)&src[(size_t)(b0 + r)*1024 + (kk & 1023) + c4*4];
            int j = kk + c4*4;
            float* d = &As[r*36 + c4*4];
            d[0] = f2tf_f(fmaf(v.x, g_bnsc[j],   bnb[j]));
            d[1] = f2tf_f(fmaf(v.y, g_bnsc[j+1], bnb[j+1]));
            d[2] = f2tf_f(fmaf(v.z, g_bnsc[j+2], bnb[j+2]));
            d[3] = f2tf_f(fmaf(v.w, g_bnsc[j+3], bnb[j+3]));
        }
        for (int i = tid; i < 512; i += 256) {
            int k = i >> 4, c4 = i & 15;
            cpasync16(&Bs[k*72 + c4*4], &g_l1Wp[(size_t)(kk + k)*64 + c4*4]);
        }
        CP_COMMIT; CP_WAIT0;
        __syncthreads();
#pragma unroll
        for (int ks = 0; ks < 4; ks++) {
            unsigned a[2][4], bf[2][2];
#pragma unroll
            for (int m = 0; m < 2; m++) {
                int r = rw + m*16 + g;
                a[m][0] = __float_as_uint(As[r*36 + ks*8 + t4]);
                a[m][1] = __float_as_uint(As[(r+8)*36 + ks*8 + t4]);
                a[m][2] = __float_as_uint(As[r*36 + ks*8 + t4 + 4]);
                a[m][3] = __float_as_uint(As[(r+8)*36 + ks*8 + t4 + 4]);
            }
#pragma unroll
            for (int n = 0; n < 2; n++) {
                int c = cw + n*8 + g;
                bf[n][0] = __float_as_uint(Bs[(ks*8 + t4)*72 + c]);
                bf[n][1] = __float_as_uint(Bs[(ks*8 + t4 + 4)*72 + c]);
            }
#pragma unroll
            for (int m = 0; m < 2; m++)
#pragma unroll
            for (int n = 0; n < 2; n++)
                mma_t(acc[m][n], a[m][0],a[m][1],a[m][2],a[m][3], bf[n][0], bf[n][1]);
        }
    }
    __syncthreads();
#pragma unroll
    for (int m = 0; m < 2; m++) {
        int r0 = rw + m*16 + g, r1 = r0 + 8;
#pragma unroll
        for (int n = 0; n < 2; n++) {
            int c = cw + n*8 + t4*2;
            if (c < 50)   { Y1[r0*52 + c]   = tanhf(acc[m][n].x + l1b[c]);
                            Y1[r1*52 + c]   = tanhf(acc[m][n].z + l1b[c]); }
            if (c+1 < 50) { Y1[r0*52 + c+1] = tanhf(acc[m][n].y + l1b[c+1]);
                            Y1[r1*52 + c+1] = tanhf(acc[m][n].w + l1b[c+1]); }
        }
    }
    __syncthreads();

    for (int o = tid; o < 3200; o += 256) {
        int r = o / 50, c = o - r*50;
        float a = l2b[c];
        for (int k = 0; k < 50; k++)
            a = fmaf(Y1[r*52 + k], W23[k*52 + c], a);
        Y2[r*52 + c] = tanhf(a);
    }
    __syncthreads();

    for (int o = tid; o < 512; o += 256) {
        int r = o >> 3, c = o & 7;
        float a = l3b[c];
        for (int k = 0; k < 50; k++)
            a = fmaf(Y2[r*52 + k], W23[2600 + k*8 + c], a);
        Y3[r*8 + c] = a;
    }
    __syncthreads();
    if (tid < 64) {
        int r = tid;
        float m = -1e30f;
#pragma unroll
        for (int c = 0; c < 8; c++) m = fmaxf(m, Y3[r*8 + c]);
        float e[8], s = 0.f;
#pragma unroll
        for (int c = 0; c < 8; c++) { e[c] = expf(Y3[r*8 + c] - m); s += e[c]; }
        float inv = 1.f / s;
        float* orow = out + (size_t)(b0 + r)*8;
#pragma unroll
        for (int c = 0; c < 8; c++) orow[c] = e[c]*inv;
    }
}

// -------------------------- launch ------------------------------------------
extern "C" void kernel_launch(void* const* d_in, const int* in_sizes, int n_in,
                              void* d_out, int out_size)
{
    const float* x    = (const float*)d_in[0];
    const float* attW = (const float*)d_in[1];
    const float* attb = (const float*)d_in[2];
    const float* gfW1 = (const float*)d_in[3];
    const float* gfb1 = (const float*)d_in[4];
    const float* gfW2 = (const float*)d_in[5];
    const float* gfb2 = (const float*)d_in[6];
    const float* bng  = (const float*)d_in[7];
    const float* bnb  = (const float*)d_in[8];
    const float* l1W  = (const float*)d_in[9];
    const float* l1b  = (const float*)d_in[10];
    const float* l2W  = (const float*)d_in[11];
    const float* l2b  = (const float*)d_in[12];
    const float* l3W  = (const float*)d_in[13];
    const float* l3b  = (const float*)d_in[14];
    float* out  = (float*)d_out;
    int wflag = (out_size >= NB*20) ? 1 : 0;
    float* outW = out + (size_t)NB*8;

    static int attr_done = 0;
    if (!attr_done) {
        cudaFuncSetAttribute(k_proj_mma, cudaFuncAttributeMaxDynamicSharedMemorySize, KP_SMEM);
        cudaFuncSetAttribute(kFuse,      cudaFuncAttributeMaxDynamicSharedMemorySize, KF_SMEM);
        cudaFuncSetAttribute(k6_mma,     cudaFuncAttributeMaxDynamicSharedMemorySize, K6_SMEM);
        cudaFuncSetAttribute(k7_final,   cudaFuncAttributeMaxDynamicSharedMemorySize, K7_SMEM);
        attr_done = 1;
    }

    k0_prep<<<1549, 256>>>(gfW1, gfW2, l1W, bng);
    k1_att<<<NB, 256>>>(x, attW, attb, outW, wflag);
    k_proj_mma<<<NR3/128, 256, KP_SMEM>>>(x);
    kFuse<<<NB/16, 256, KF_SMEM>>>(x, gfb1, gfb2, outW, wflag);
    dim3 g6(NB/128, 16);
    k6_mma<<<g6, 256, K6_SMEM>>>(gfb2);
    k7_final<<<NB/64, 256, K7_SMEM>>>(bnb, l1b, l2W, l2b, l3W, l3b, out);
}

// round 9
// speedup vs baseline: 3.1455x; 1.0704x over previous
#include <cuda_runtime.h>
#include <cstdint>
#include <cstddef>

// ---------------------------------------------------------------------------
// graph12 — Round 8: HW-approx transcendentals in bulk paths.
//   tanh.approx.f32 for gf epilogues (kFuse GEMM1, k6); __expf in k1 bulk.
// ---------------------------------------------------------------------------

#define NB    16384
#define ND    1024
#define NR3   (NB*3)

__device__ float g_W1t  [128*1024];          // W1r transposed [n][k], tf32
__device__ float g_W2t  [1024*64];           // W2 transposed [n][k], tf32
__device__ float g_l1Wp [3072*64];           // tf32, padded 50->64
__device__ float g_bnsc [3072];
__device__ float g_PQ1  [(size_t)NR3*128];
__device__ float g_act2 [(size_t)6*NB*64];
__device__ float g_uni  [(size_t)NB*ND];
__device__ float g_bisum[(size_t)NB*ND];
__device__ float g_tri  [(size_t)NB*ND];
__device__ float g_wuni [NB*3];
__device__ float g_wbi  [NB*3];
__device__ float g_sbi  [NB*3];
__device__ float g_wtri [NB*6];

// -------------------------- helpers -----------------------------------------
__device__ __forceinline__ float f2tf_f(float f) {
    unsigned r;
    asm("cvt.rna.tf32.f32 %0, %1;" : "=r"(r) : "f"(f));
    return __uint_as_float(r);
}

__device__ __forceinline__ float tanh_fast(float x) {
    float r;
    asm("tanh.approx.f32 %0, %1;" : "=f"(r) : "f"(x));
    return r;
}

__device__ __forceinline__ void mma_t(float4& d, unsigned a0, unsigned a1,
                                      unsigned a2, unsigned a3,
                                      unsigned b0, unsigned b1) {
    asm volatile(
        "mma.sync.aligned.m16n8k8.row.col.f32.tf32.tf32.f32 "
        "{%0,%1,%2,%3}, {%4,%5,%6,%7}, {%8,%9}, {%0,%1,%2,%3};"
        : "+f"(d.x), "+f"(d.y), "+f"(d.z), "+f"(d.w)
        : "r"(a0), "r"(a1), "r"(a2), "r"(a3), "r"(b0), "r"(b1));
}

__device__ __forceinline__ uint4 ldsm4(unsigned addr) {
    uint4 r;
    asm volatile("ldmatrix.sync.aligned.m8n8.x4.shared.b16 {%0,%1,%2,%3}, [%4];"
                 : "=r"(r.x), "=r"(r.y), "=r"(r.z), "=r"(r.w) : "r"(addr));
    return r;
}

__device__ __forceinline__ unsigned a_ptr(unsigned base, int rbase, int S, int lane) {
    return base + ((rbase + (lane & 15))*S + ((lane & 16) >> 2))*4;
}
__device__ __forceinline__ unsigned b_ptr(unsigned base, int nbase, int St, int lane) {
    return base + ((nbase + (lane & 7) + ((lane & 16) >> 1))*St + ((lane & 8) >> 1))*4;
}

__device__ __forceinline__ void cpasync16(float* dst_smem, const float* src) {
    unsigned d = (unsigned)__cvta_generic_to_shared(dst_smem);
    asm volatile("cp.async.cg.shared.global [%0], [%1], 16;" :: "r"(d), "l"(src));
}
#define CP_COMMIT  asm volatile("cp.async.commit_group;")
#define CP_WAIT0   asm volatile("cp.async.wait_group 0;")
#define CP_WAIT1   asm volatile("cp.async.wait_group 1;")

// -------------------------- block reductions (256 thr) ----------------------
template<int NV>
__device__ __forceinline__ void blockReduceSumN(float* v, float* rbuf) {
    int tid = threadIdx.x, lane = tid & 31, w = tid >> 5;
#pragma unroll
    for (int n = 0; n < NV; n++) {
        float x = v[n];
#pragma unroll
        for (int o = 16; o > 0; o >>= 1) x += __shfl_down_sync(0xffffffffu, x, o);
        if (lane == 0) rbuf[n*8 + w] = x;
    }
    __syncthreads();
    if (tid < NV) {
        float s = rbuf[tid*8];
#pragma unroll
        for (int q = 1; q < 8; q++) s += rbuf[tid*8 + q];
        rbuf[tid*8] = s;
    }
    __syncthreads();
#pragma unroll
    for (int n = 0; n < NV; n++) v[n] = rbuf[n*8];
    __syncthreads();
}

template<int NV>
__device__ __forceinline__ void blockReduceMaxN(float* v, float* rbuf) {
    int tid = threadIdx.x, lane = tid & 31, w = tid >> 5;
#pragma unroll
    for (int n = 0; n < NV; n++) {
        float x = v[n];
#pragma unroll
        for (int o = 16; o > 0; o >>= 1) x = fmaxf(x, __shfl_down_sync(0xffffffffu, x, o));
        if (lane == 0) rbuf[n*8 + w] = x;
    }
    __syncthreads();
    if (tid < NV) {
        float s = rbuf[tid*8];
#pragma unroll
        for (int q = 1; q < 8; q++) s = fmaxf(s, rbuf[tid*8 + q]);
        rbuf[tid*8] = s;
    }
    __syncthreads();
#pragma unroll
    for (int n = 0; n < NV; n++) v[n] = rbuf[n*8];
    __syncthreads();
}

// -------------------------- k0: prep ----------------------------------------
__global__ void k0_prep(const float* __restrict__ W1, const float* __restrict__ W2,
                        const float* __restrict__ l1W, const float* __restrict__ bng)
{
    int i = blockIdx.x * 256 + threadIdx.x;
    if (i < 131072) {                         // g_W1t[n][k] = W1r(k,n)
        int n = i >> 10, k = i & 1023;
        float v = (n < 64) ? W1[(size_t)k*64 + n] : W1[(size_t)(1024 + k)*64 + (n - 64)];
        g_W1t[i] = f2tf_f(v);
    } else if (i < 196608) {                  // g_W2t[n][k] = W2[k][n]
        int i2 = i - 131072;
        int n = i2 >> 6, k = i2 & 63;
        g_W2t[i2] = f2tf_f(W2[(size_t)k*1024 + n]);
    } else if (i < 393216) {                  // l1Wp
        int i3 = i - 196608;
        int row = i3 >> 6, c = i3 & 63;
        g_l1Wp[i3] = (c < 50) ? f2tf_f(l1W[(size_t)row*50 + c]) : 0.f;
    } else if (i < 396288) {                  // bnsc
        int j = i - 393216;
        float mult = (j < 1024) ? 1.f : ((j < 2048) ? (1.f/3.f) : (1.f/6.f));
        g_bnsc[j] = bng[j] * rsqrtf(1.0f + 1e-5f) * mult;
    }
}

// -------------------------- k1: attention + stage-1 stats -------------------
__global__ __launch_bounds__(256) void k1_att(
    const float* __restrict__ x, const float* __restrict__ attW,
    const float* __restrict__ attb, float* __restrict__ outW, int wflag)
{
    __shared__ float sm[3072];
    __shared__ float rbuf[6*8];
    __shared__ float bc[4];
    int b = blockIdx.x, tid = threadIdx.x;
    const float4* xr4 = (const float4*)(x + (size_t)b*3072);
    for (int i = tid; i < 768; i += 256) ((float4*)sm)[i] = xr4[i];
    __syncthreads();

    float red[3];
    float a0 = 0.f, a1 = 0.f, a2 = 0.f;
    float m0 = -1e30f, m1 = -1e30f, m2 = -1e30f;
    for (int i = tid; i < 1024; i += 256) {
        float w = attW[i];
        float av = sm[i], vv = sm[1024 + i], lv = sm[2048 + i];
        a0 = fmaf(av, w, a0); a1 = fmaf(vv, w, a1); a2 = fmaf(lv, w, a2);
        m0 = fmaxf(m0, av);  m1 = fmaxf(m1, vv);  m2 = fmaxf(m2, lv);
    }
    red[0] = a0; red[1] = a1; red[2] = a2;
    blockReduceSumN<3>(red, rbuf);
    float att0 = red[0], att1 = red[1], att2 = red[2];
    red[0] = m0; red[1] = m1; red[2] = m2;
    blockReduceMaxN<3>(red, rbuf);
    float Ma = red[0], Mv = red[1], Ml = red[2];

    float red6[6] = {0.f, 0.f, 0.f, 0.f, 0.f, 0.f};
    for (int i = tid; i < 1024; i += 256) {
        float ea = __expf(sm[i] - Ma);
        float ev = __expf(sm[1024 + i] - Mv);
        float el = __expf(sm[2048 + i] - Ml);
        red6[0] += ea; red6[1] += ev; red6[2] += el;
        red6[3] = fmaf(ea, ev, red6[3]);
        red6[4] = fmaf(ea, el, red6[4]);
        red6[5] = fmaf(ev, el, red6[5]);
    }
    blockReduceSumN<6>(red6, rbuf);

    if (tid == 0) {
        float ab = attb[0];
        float t0 = tanhf(att0 + ab), t1 = tanhf(att1 + ab), t2 = tanhf(att2 + ab);
        float mm = fmaxf(t0, fmaxf(t1, t2));
        float e0 = expf(t0 - mm), e1 = expf(t1 - mm), e2 = expf(t2 - mm);
        float inv = 1.f / (e0 + e1 + e2);
        float sa = e0*inv, sv = e1*inv, sl = e2*inv;
        float dav = red6[3] / (red6[0]*red6[1]);
        float dal = red6[4] / (red6[0]*red6[2]);
        float dvl = red6[5] / (red6[1]*red6[2]);
        float sav = (sa + sv) / (dav + 0.5f);
        float sal = (sa + sl) / (dal + 0.5f);
        float svl = (sl + sv) / (dvl + 0.5f);
        g_wuni[b*3+0] = sa; g_wuni[b*3+1] = sv; g_wuni[b*3+2] = sl;
        g_sbi [b*3+0] = sav; g_sbi[b*3+1] = sal; g_sbi[b*3+2] = svl;
        float m3 = fmaxf(sav, fmaxf(sal, svl));
        float f0 = expf(sav - m3), f1 = expf(sal - m3), f2 = expf(svl - m3);
        float fi = 1.f / (f0 + f1 + f2);
        g_wbi[b*3+0] = f0*fi; g_wbi[b*3+1] = f1*fi; g_wbi[b*3+2] = f2*fi;
        if (wflag) {
            float* o = outW + (size_t)b*12;
            o[0] = sa; o[1] = sv; o[2] = sl;
            o[3] = f0*fi; o[4] = f1*fi; o[5] = f2*fi;
        }
        bc[0] = sa; bc[1] = sv; bc[2] = sl;
    }
    __syncthreads();
    float sa = bc[0], sv = bc[1], sl = bc[2];
    float* ur = g_uni + (size_t)b*1024;
    for (int i = tid; i < 1024; i += 256)
        ur[i] = (sa*sm[i] + sv*sm[1024+i] + sl*sm[2048+i]) * (1.0f/3.0f);
}

// -------------------------- kP: PQ1 projection (ldmatrix, 3-stage) ----------
#define KP_STAGE (128*36 * 2)
#define KP_SMEM  (3*KP_STAGE*4)

__device__ __forceinline__ void kp_issue(const float* __restrict__ A, size_t m0,
                                         float* stage, int t, int tid)
{
    float* As  = stage;                 // [128][36]
    float* Bts = stage + 128*36;        // [128][36]
    int kk = t * 32;
#pragma unroll
    for (int j = 0; j < 4; j++) {
        int i = tid + j*256;
        int r = i >> 3, kq = i & 7;
        cpasync16(&As[r*36 + kq*4], &A[(m0 + r)*1024 + kk + kq*4]);
    }
#pragma unroll
    for (int j = 0; j < 4; j++) {
        int i = tid + j*256;
        int n = i >> 3, kq = i & 7;
        cpasync16(&Bts[n*36 + kq*4], &g_W1t[(size_t)n*1024 + kk + kq*4]);
    }
    CP_COMMIT;
}

__global__ __launch_bounds__(256) void k_proj_mma(const float* __restrict__ x)
{
    extern __shared__ float smp[];
    int tid = threadIdx.x;
    size_t m0 = (size_t)blockIdx.x * 128;
    int lane = tid & 31, wid = tid >> 5;
    int t4 = lane & 3, g = lane >> 2;
    int wm = wid >> 1, wn = wid & 1;

    float4 acc[2][8] = {};

    kp_issue(x, m0, smp,            0, tid);
    kp_issue(x, m0, smp + KP_STAGE, 1, tid);

    int s = 0;
    for (int t = 0; t < 32; t++) {
        if (t < 31) { CP_WAIT1; } else { CP_WAIT0; }
        __syncthreads();
        if (t + 2 < 32)
            kp_issue(x, m0, smp + ((s + 2) % 3)*KP_STAGE, t + 2, tid);
        float* Ac = smp + s*KP_STAGE;
        unsigned Au = (unsigned)__cvta_generic_to_shared(Ac);
        unsigned Bu = Au + 128*36*4;
        unsigned pA0 = a_ptr(Au, wm*32,      36, lane);
        unsigned pA1 = pA0 + 16*36*4;
        unsigned pB  = b_ptr(Bu, wn*64, 36, lane);
#pragma unroll
        for (int ks = 0; ks < 4; ks++) {
            uint4 a0 = ldsm4(pA0 + ks*32);
            uint4 a1 = ldsm4(pA1 + ks*32);
            uint4 bv[4];
#pragma unroll
            for (int p = 0; p < 4; p++) bv[p] = ldsm4(pB + p*16*36*4 + ks*32);
#pragma unroll
            for (int n = 0; n < 8; n++) {
                unsigned b0 = (n & 1) ? bv[n>>1].z : bv[n>>1].x;
                unsigned b1 = (n & 1) ? bv[n>>1].w : bv[n>>1].y;
                mma_t(acc[0][n], a0.x, a0.y, a0.z, a0.w, b0, b1);
                mma_t(acc[1][n], a1.x, a1.y, a1.z, a1.w, b0, b1);
            }
        }
        s = (s + 1) % 3;
    }
#pragma unroll
    for (int m = 0; m < 2; m++) {
        size_t r0 = m0 + wm*32 + m*16 + g;
        size_t r1 = r0 + 8;
#pragma unroll
        for (int n = 0; n < 8; n++) {
            int col = wn*64 + n*8 + t4*2;
            float2 o0; o0.x = acc[m][n].x; o0.y = acc[m][n].y;
            float2 o1; o1.x = acc[m][n].z; o1.y = acc[m][n].w;
            *(float2*)&g_PQ1[r0*128 + col] = o0;
            *(float2*)&g_PQ1[r1*128 + col] = o1;
        }
    }
}

// -------------------------- kFuse: stage-2 megafusion -----------------------
#define KF_PQ1   0
#define KF_ACT1  6336
#define KF_BI3   9600
#define KF_W2    12864
#define KF_W1    17216
#define KF_B1    25920
#define KF_WBI   25984
#define KF_TOTF  (25984+48+16)
#define KF_SMEM  (KF_TOTF*4)

__global__ __launch_bounds__(256) void kFuse(
    const float* __restrict__ x, const float* __restrict__ b1,
    const float* __restrict__ b2, float* __restrict__ outW, int wflag)
{
    extern __shared__ float sf[];
    float* PQ1s = sf + KF_PQ1;
    float* act1s= sf + KF_ACT1;
    float* bi3c = sf + KF_BI3;
    float* W2ts = sf + KF_W2;
    float* W1ts = sf + KF_W1;
    float* b1s  = sf + KF_B1;
    float* wbis = sf + KF_WBI;

    int tid = threadIdx.x;
    int bb0 = blockIdx.x * 16;
    int lane = tid & 31, wid = tid >> 5;
    int t4 = lane & 3, g = lane >> 2;
    int wm = wid >> 1, wn = wid & 1;

    for (int i = tid; i < 1536; i += 256) {
        int r = i >> 5, c4 = i & 31;
        int p = r >> 4, b = r & 15;
        cpasync16(&PQ1s[r*132 + c4*4], &g_PQ1[((size_t)(bb0 + b)*3 + p)*128 + c4*4]);
    }
    CP_COMMIT;
    if (tid < 64) b1s[tid] = b1[tid];
    if (tid < 48) { int p = tid >> 4, b = tid & 15; wbis[tid] = g_wbi[(bb0 + b)*3 + p]; }
    CP_WAIT0;
    __syncthreads();
    for (int i = tid; i < 3072; i += 256) {
        int r = i >> 6, k = i & 63;
        int p = r >> 4, b = r & 15;
        int f = (p == 2) ? 1 : 0;
        int s = (p == 0) ? 1 : 2;
        float tv = PQ1s[(f*16+b)*132 + k] + PQ1s[(s*16+b)*132 + 64 + k] + b1s[k];
        act1s[r*68 + k] = tv > 0.f ? tv : 0.2f*tv;
    }
    __syncthreads();

    unsigned act1u = (unsigned)__cvta_generic_to_shared(act1s);
    unsigned bi3u  = (unsigned)__cvta_generic_to_shared(bi3c);
    unsigned w2tu  = (unsigned)__cvta_generic_to_shared(W2ts);
    unsigned w1tu  = (unsigned)__cvta_generic_to_shared(W1ts);
    unsigned pA1 = a_ptr(act1u, wm*16, 68, lane);
    unsigned pA2 = a_ptr(bi3u,  wm*16, 68, lane);
    unsigned pB1 = b_ptr(w2tu, wn*32, 68, lane);
    unsigned pB2 = b_ptr(w1tu, wn*64, 68, lane);

    float sE[2][3] = {}, sX[2][3] = {}, sP[2][3] = {}, sQ[2][3] = {};
    float4 pq2[8] = {};

    for (int n = 0; n < 16; n++) {
        int n0 = n * 64;
        for (int i = tid; i < 1024; i += 256) {
            int r = i >> 4, c4 = i & 15;
            cpasync16(&W2ts[r*68 + c4*4], &g_W2t[(size_t)(n0 + r)*64 + c4*4]);
        }
        for (int i = tid; i < 2048; i += 256) {
            int r = i >> 4, c4 = i & 15;
            cpasync16(&W1ts[r*68 + c4*4], &g_W1t[(size_t)r*1024 + n0 + c4*4]);
        }
        CP_COMMIT;
        float xr[12];
#pragma unroll
        for (int j = 0; j < 2; j++)
#pragma unroll
        for (int m = 0; m < 3; m++)
#pragma unroll
        for (int h = 0; h < 2; h++)
            xr[(j*3+m)*2+h] = x[((size_t)(bb0 + 2*wid + j)*3 + m)*1024 + n0 + lane + h*32];
        CP_WAIT0;
        __syncthreads();

        // GEMM1: act1 @ W2 chunk -> bi3c (tanh.approx * wbi, lrelu)
        if (wid < 6) {
            float4 acc[4] = {};
#pragma unroll
            for (int ks = 0; ks < 8; ks++) {
                uint4 a  = ldsm4(pA1 + ks*32);
                uint4 b0 = ldsm4(pB1 + ks*32);
                uint4 b1v= ldsm4(pB1 + 16*68*4 + ks*32);
                mma_t(acc[0], a.x,a.y,a.z,a.w, b0.x, b0.y);
                mma_t(acc[1], a.x,a.y,a.z,a.w, b0.z, b0.w);
                mma_t(acc[2], a.x,a.y,a.z,a.w, b1v.x, b1v.y);
                mma_t(acc[3], a.x,a.y,a.z,a.w, b1v.z, b1v.w);
            }
            int r0 = wm*16 + g, r1 = r0 + 8;
            float w0 = wbis[r0], w1 = wbis[r1];
#pragma unroll
            for (int q = 0; q < 4; q++) {
                int col = wn*32 + q*8 + t4*2;
                float2 b2v = *(const float2*)&b2[n0 + col];
                float t, v;
                t = tanh_fast(acc[q].x + b2v.x)*w0; v = t > 0.f ? t : 0.01f*t; bi3c[r0*68 + col]   = v;
                t = tanh_fast(acc[q].y + b2v.y)*w0; v = t > 0.f ? t : 0.01f*t; bi3c[r0*68 + col+1] = v;
                t = tanh_fast(acc[q].z + b2v.x)*w1; v = t > 0.f ? t : 0.01f*t; bi3c[r1*68 + col]   = v;
                t = tanh_fast(acc[q].w + b2v.y)*w1; v = t > 0.f ? t : 0.01f*t; bi3c[r1*68 + col+1] = v;
            }
        }
        __syncthreads();

        // stats + bisum + GEMM2
#pragma unroll
        for (int j = 0; j < 2; j++) {
            int b = 2*wid + j;
#pragma unroll
            for (int h = 0; h < 2; h++) {
                int c = lane + (h ? 32 : 0);
                float e0 = __expf(bi3c[b*68 + c]);
                float e1 = __expf(bi3c[(16+b)*68 + c]);
                float e2 = __expf(bi3c[(32+b)*68 + c]);
                float xa = __expf(xr[(j*3+0)*2+h]);
                float xv = __expf(xr[(j*3+1)*2+h]);
                float xl = __expf(xr[(j*3+2)*2+h]);
                sE[j][0] += e0; sE[j][1] += e1; sE[j][2] += e2;
                sX[j][0] += xa; sX[j][1] += xv; sX[j][2] += xl;
                sP[j][0] = fmaf(e0, e2, sP[j][0]);
                sP[j][1] = fmaf(e0, e1, sP[j][1]);
                sP[j][2] = fmaf(e1, e2, sP[j][2]);
                sQ[j][0] = fmaf(e0, xl, sQ[j][0]);
                sQ[j][1] = fmaf(e1, xv, sQ[j][1]);
                sQ[j][2] = fmaf(e2, xa, sQ[j][2]);
            }
        }
        for (int i = tid; i < 1024; i += 256) {
            int b = i >> 6, c = i & 63;
            g_bisum[(size_t)(bb0 + b)*1024 + n0 + c] =
                bi3c[b*68 + c] + bi3c[(16+b)*68 + c] + bi3c[(32+b)*68 + c];
        }
        if (wid < 6) {
#pragma unroll
            for (int ks = 0; ks < 8; ks++) {
                uint4 a = ldsm4(pA2 + ks*32);
                uint4 bv[4];
#pragma unroll
                for (int p = 0; p < 4; p++) bv[p] = ldsm4(pB2 + p*16*68*4 + ks*32);
#pragma unroll
                for (int q = 0; q < 8; q++) {
                    unsigned b0 = (q & 1) ? bv[q>>1].z : bv[q>>1].x;
                    unsigned b1 = (q & 1) ? bv[q>>1].w : bv[q>>1].y;
                    mma_t(pq2[q], a.x,a.y,a.z,a.w, b0, b1);
                }
            }
        }
        __syncthreads();
    }

    // ---- stats reduce -> w_tri ----
#pragma unroll
    for (int j = 0; j < 2; j++) {
#pragma unroll
        for (int o = 16; o > 0; o >>= 1) {
#pragma unroll
            for (int v = 0; v < 3; v++) {
                sE[j][v] += __shfl_down_sync(0xffffffffu, sE[j][v], o);
                sX[j][v] += __shfl_down_sync(0xffffffffu, sX[j][v], o);
                sP[j][v] += __shfl_down_sync(0xffffffffu, sP[j][v], o);
                sQ[j][v] += __shfl_down_sync(0xffffffffu, sQ[j][v], o);
            }
        }
    }
    if (lane == 0) {
#pragma unroll
        for (int j = 0; j < 2; j++) {
            int b = bb0 + 2*wid + j;
            float d0 = sP[j][0] / (sE[j][0]*sE[j][2]);
            float d1 = sP[j][1] / (sE[j][0]*sE[j][1]);
            float d2 = sP[j][2] / (sE[j][1]*sE[j][2]);
            float d3 = sQ[j][0] / (sE[j][0]*sX[j][2]);
            float d4 = sQ[j][1] / (sE[j][1]*sX[j][1]);
            float d5 = sQ[j][2] / (sE[j][2]*sX[j][0]);
            float sa = g_wuni[b*3+0], sv = g_wuni[b*3+1], sl = g_wuni[b*3+2];
            float sav = g_sbi[b*3+0], sal = g_sbi[b*3+1], svl = g_sbi[b*3+2];
            float nn[6];
            nn[0] = (sav + svl)/(d0 + 0.5f);
            nn[1] = (sav + sal)/(d1 + 0.5f);
            nn[2] = (sal + svl)/(d2 + 0.5f);
            nn[3] = (sav + sl )/(d3 + 0.5f);
            nn[4] = (sal + sv )/(d4 + 0.5f);
            nn[5] = (sa  + svl)/(d5 + 0.5f);
            float m = nn[0];
#pragma unroll
            for (int k = 1; k < 6; k++) m = fmaxf(m, nn[k]);
            float e[6], ss = 0.f;
#pragma unroll
            for (int k = 0; k < 6; k++) { e[k] = expf(nn[k]-m); ss += e[k]; }
            float inv = 1.f/ss;
#pragma unroll
            for (int k = 0; k < 6; k++) {
                g_wtri[(size_t)b*6 + k] = e[k]*inv;
                if (wflag) outW[(size_t)b*12 + 6 + k] = e[k]*inv;
            }
        }
    }

    // ---- PQ2 -> smem (reuse W1ts region as [48][136]) ----
    __syncthreads();
    if (wid < 6) {
        int r0 = wm*16 + g, r1 = r0 + 8;
#pragma unroll
        for (int q = 0; q < 8; q++) {
            int col = wn*64 + q*8 + t4*2;
            W1ts[r0*136 + col]   = pq2[q].x;
            W1ts[r0*136 + col+1] = pq2[q].y;
            W1ts[r1*136 + col]   = pq2[q].z;
            W1ts[r1*136 + col+1] = pq2[q].w;
        }
    }
    __syncthreads();
    // ---- act2 ----
    const int PR[6] = {0,0,2,0,1,2};
    const int QR[6] = {2,1,1,2,1,0};
    const int QS[6] = {0,0,0,1,1,1};
    for (int i = tid; i < 6144; i += 256) {
        int p = i >> 10, rem = i & 1023;
        int b = rem >> 6, k = rem & 63;
        float pv = W1ts[(PR[p]*16 + b)*136 + k];
        float qv = QS[p] ? PQ1s[(QR[p]*16 + b)*132 + 64 + k]
                         : W1ts[(QR[p]*16 + b)*136 + 64 + k];
        float tv = pv + qv + b1s[k];
        g_act2[((size_t)p*NB + bb0 + b)*64 + k] = tv > 0.f ? tv : 0.2f*tv;
    }
}

// -------------------------- k6: stage-2 second layer ------------------------
#define K6_SMEM ((2*128*68 + 64*68)*4)
__global__ __launch_bounds__(256) void k6_mma(const float* __restrict__ b2)
{
    extern __shared__ float sm6[];
    float* AsB  = sm6;
    float* W2ts = sm6 + 2*128*68;
    int tid = threadIdx.x;
    int b0 = blockIdx.x * 128, n0 = blockIdx.y * 64;

    for (int i = tid; i < 1024; i += 256) {
        int r = i >> 4, c4 = i & 15;
        cpasync16(&W2ts[r*68 + c4*4], &g_W2t[(size_t)(n0 + r)*64 + c4*4]);
    }
    {
        const float* Ap = g_act2 + ((size_t)0*NB + b0)*64;
        for (int i = tid; i < 2048; i += 256) {
            int r = i >> 4, c4 = i & 15;
            cpasync16(&AsB[r*68 + c4*4], &Ap[(size_t)r*64 + c4*4]);
        }
    }
    CP_COMMIT;

    int lane = tid & 31, wid = tid >> 5;
    int t4 = lane & 3, g = lane >> 2;
    int wm = wid >> 1, wn = wid & 1;
    int rw = wm*32, cw = wn*32;

    unsigned w2tu = (unsigned)__cvta_generic_to_shared(W2ts);
    unsigned pB  = b_ptr(w2tu, cw, 68, lane);
    unsigned As0u = (unsigned)__cvta_generic_to_shared(AsB);

    float4 tri[2][4] = {};
#pragma unroll 1
    for (int p = 0; p < 6; p++) {
        if (p + 1 < 6) {
            const float* Ap = g_act2 + ((size_t)(p+1)*NB + b0)*64;
            float* Ad = AsB + ((p+1) & 1)*128*68;
            for (int i = tid; i < 2048; i += 256) {
                int r = i >> 4, c4 = i & 15;
                cpasync16(&Ad[r*68 + c4*4], &Ap[(size_t)r*64 + c4*4]);
            }
            CP_COMMIT;
            CP_WAIT1;
        } else {
            CP_WAIT0;
        }
        __syncthreads();
        unsigned Au = As0u + (unsigned)((p & 1)*128*68*4);
        unsigned pA0 = a_ptr(Au, rw, 68, lane);
        unsigned pA1 = pA0 + 16*68*4;
        float4 acc[2][4] = {};
#pragma unroll
        for (int ks = 0; ks < 8; ks++) {
            uint4 a0 = ldsm4(pA0 + ks*32);
            uint4 a1 = ldsm4(pA1 + ks*32);
            uint4 b0 = ldsm4(pB + ks*32);
            uint4 b1v= ldsm4(pB + 16*68*4 + ks*32);
            mma_t(acc[0][0], a0.x,a0.y,a0.z,a0.w, b0.x, b0.y);
            mma_t(acc[0][1], a0.x,a0.y,a0.z,a0.w, b0.z, b0.w);
            mma_t(acc[0][2], a0.x,a0.y,a0.z,a0.w, b1v.x, b1v.y);
            mma_t(acc[0][3], a0.x,a0.y,a0.z,a0.w, b1v.z, b1v.w);
            mma_t(acc[1][0], a1.x,a1.y,a1.z,a1.w, b0.x, b0.y);
            mma_t(acc[1][1], a1.x,a1.y,a1.z,a1.w, b0.z, b0.w);
            mma_t(acc[1][2], a1.x,a1.y,a1.z,a1.w, b1v.x, b1v.y);
            mma_t(acc[1][3], a1.x,a1.y,a1.z,a1.w, b1v.z, b1v.w);
        }
#pragma unroll
        for (int m = 0; m < 2; m++) {
            int r0 = b0 + rw + m*16 + g;
            int r1 = r0 + 8;
            float wt0 = g_wtri[(size_t)r0*6 + p];
            float wt1 = g_wtri[(size_t)r1*6 + p];
#pragma unroll
            for (int q = 0; q < 4; q++) {
                int col = n0 + cw + q*8 + t4*2;
                float2 b2v = *(const float2*)&b2[col];
                float t;
                t = tanh_fast(acc[m][q].x + b2v.x)*wt0; tri[m][q].x += (t > 0.f ? t : 0.01f*t);
                t = tanh_fast(acc[m][q].y + b2v.y)*wt0; tri[m][q].y += (t > 0.f ? t : 0.01f*t);
                t = tanh_fast(acc[m][q].z + b2v.x)*wt1; tri[m][q].z += (t > 0.f ? t : 0.01f*t);
                t = tanh_fast(acc[m][q].w + b2v.y)*wt1; tri[m][q].w += (t > 0.f ? t : 0.01f*t);
            }
        }
        __syncthreads();
    }
#pragma unroll
    for (int m = 0; m < 2; m++) {
        size_t r0 = b0 + rw + m*16 + g, r1 = r0 + 8;
#pragma unroll
        for (int q = 0; q < 4; q++) {
            int col = n0 + cw + q*8 + t4*2;
            float2 o0; o0.x = tri[m][q].x; o0.y = tri[m][q].y;
            float2 o1; o1.x = tri[m][q].z; o1.y = tri[m][q].w;
            *(float2*)&g_tri[r0*1024 + col] = o0;
            *(float2*)&g_tri[r1*1024 + col] = o1;
        }
    }
}

// -------------------------- k7: fused head (tf32 layer1) --------------------
#define K7_SMEM ((64*36 + 32*72 + 64*52*2 + 512 + 3000)*4)
__global__ __launch_bounds__(256) void k7_final(
    const float* __restrict__ bnb,
    const float* __restrict__ l1b,
    const float* __restrict__ l2W, const float* __restrict__ l2b,
    const float* __restrict__ l3W, const float* __restrict__ l3b,
    float* __restrict__ out)
{
    extern __shared__ float pool[];
    float* As  = pool;
    float* Bs  = pool + 2304;
    float* Y1  = pool + 4608;
    float* Y2  = pool + 7936;
    float* Y3  = pool + 11264;
    float* W23 = pool + 11776;
    int tid = threadIdx.x;
    int b0 = blockIdx.x * 64;
    int lane = tid & 31, wid = tid >> 5;
    int g = lane >> 2, t4 = lane & 3;
    int wm = wid >> 2, wn = wid & 3;
    int rw = wm*32, cw = wn*16;

    for (int i = tid; i < 2500; i += 256) {
        int k = i / 50, c = i - k*50;
        W23[k*52 + c] = l2W[i];
    }
    for (int i = tid; i < 400; i += 256) W23[2600 + i] = l3W[i];

    float4 acc[2][2] = {};
    for (int t = 0; t < 96; t++) {
        int kk = t * 32;
        int region = kk >> 10;
        const float* src = region == 0 ? g_uni : (region == 1 ? g_bisum : g_tri);
        __syncthreads();
        for (int i = tid; i < 512; i += 256) {
            int r = i >> 3, c4 = i & 7;
            float4 v = *(const float4*)&src[(size_t)(b0 + r)*1024 + (kk & 1023) + c4*4];
            int j = kk + c4*4;
            float* d = &As[r*36 + c4*4];
            d[0] = f2tf_f(fmaf(v.x, g_bnsc[j],   bnb[j]));
            d[1] = f2tf_f(fmaf(v.y, g_bnsc[j+1], bnb[j+1]));
            d[2] = f2tf_f(fmaf(v.z, g_bnsc[j+2], bnb[j+2]));
            d[3] = f2tf_f(fmaf(v.w, g_bnsc[j+3], bnb[j+3]));
        }
        for (int i = tid; i < 512; i += 256) {
            int k = i >> 4, c4 = i & 15;
            cpasync16(&Bs[k*72 + c4*4], &g_l1Wp[(size_t)(kk + k)*64 + c4*4]);
        }
        CP_COMMIT; CP_WAIT0;
        __syncthreads();
#pragma unroll
        for (int ks = 0; ks < 4; ks++) {
            unsigned a[2][4], bf[2][2];
#pragma unroll
            for (int m = 0; m < 2; m++) {
                int r = rw + m*16 + g;
                a[m][0] = __float_as_uint(As[r*36 + ks*8 + t4]);
                a[m][1] = __float_as_uint(As[(r+8)*36 + ks*8 + t4]);
                a[m][2] = __float_as_uint(As[r*36 + ks*8 + t4 + 4]);
                a[m][3] = __float_as_uint(As[(r+8)*36 + ks*8 + t4 + 4]);
            }
#pragma unroll
            for (int n = 0; n < 2; n++) {
                int c = cw + n*8 + g;
                bf[n][0] = __float_as_uint(Bs[(ks*8 + t4)*72 + c]);
                bf[n][1] = __float_as_uint(Bs[(ks*8 + t4 + 4)*72 + c]);
            }
#pragma unroll
            for (int m = 0; m < 2; m++)
#pragma unroll
            for (int n = 0; n < 2; n++)
                mma_t(acc[m][n], a[m][0],a[m][1],a[m][2],a[m][3], bf[n][0], bf[n][1]);
        }
    }
    __syncthreads();
#pragma unroll
    for (int m = 0; m < 2; m++) {
        int r0 = rw + m*16 + g, r1 = r0 + 8;
#pragma unroll
        for (int n = 0; n < 2; n++) {
            int c = cw + n*8 + t4*2;
            if (c < 50)   { Y1[r0*52 + c]   = tanhf(acc[m][n].x + l1b[c]);
                            Y1[r1*52 + c]   = tanhf(acc[m][n].z + l1b[c]); }
            if (c+1 < 50) { Y1[r0*52 + c+1] = tanhf(acc[m][n].y + l1b[c+1]);
                            Y1[r1*52 + c+1] = tanhf(acc[m][n].w + l1b[c+1]); }
        }
    }
    __syncthreads();

    for (int o = tid; o < 3200; o += 256) {
        int r = o / 50, c = o - r*50;
        float a = l2b[c];
        for (int k = 0; k < 50; k++)
            a = fmaf(Y1[r*52 + k], W23[k*52 + c], a);
        Y2[r*52 + c] = tanhf(a);
    }
    __syncthreads();

    for (int o = tid; o < 512; o += 256) {
        int r = o >> 3, c = o & 7;
        float a = l3b[c];
        for (int k = 0; k < 50; k++)
            a = fmaf(Y2[r*52 + k], W23[2600 + k*8 + c], a);
        Y3[r*8 + c] = a;
    }
    __syncthreads();
    if (tid < 64) {
        int r = tid;
        float m = -1e30f;
#pragma unroll
        for (int c = 0; c < 8; c++) m = fmaxf(m, Y3[r*8 + c]);
        float e[8], s = 0.f;
#pragma unroll
        for (int c = 0; c < 8; c++) { e[c] = expf(Y3[r*8 + c] - m); s += e[c]; }
        float inv = 1.f / s;
        float* orow = out + (size_t)(b0 + r)*8;
#pragma unroll
        for (int c = 0; c < 8; c++) orow[c] = e[c]*inv;
    }
}

// -------------------------- launch ------------------------------------------
extern "C" void kernel_launch(void* const* d_in, const int* in_sizes, int n_in,
                              void* d_out, int out_size)
{
    const float* x    = (const float*)d_in[0];
    const float* attW = (const float*)d_in[1];
    const float* attb = (const float*)d_in[2];
    const float* gfW1 = (const float*)d_in[3];
    const float* gfb1 = (const float*)d_in[4];
    const float* gfW2 = (const float*)d_in[5];
    const float* gfb2 = (const float*)d_in[6];
    const float* bng  = (const float*)d_in[7];
    const float* bnb  = (const float*)d_in[8];
    const float* l1W  = (const float*)d_in[9];
    const float* l1b  = (const float*)d_in[10];
    const float* l2W  = (const float*)d_in[11];
    const float* l2b  = (const float*)d_in[12];
    const float* l3W  = (const float*)d_in[13];
    const float* l3b  = (const float*)d_in[14];
    float* out  = (float*)d_out;
    int wflag = (out_size >= NB*20) ? 1 : 0;
    float* outW = out + (size_t)NB*8;

    static int attr_done = 0;
    if (!attr_done) {
        cudaFuncSetAttribute(k_proj_mma, cudaFuncAttributeMaxDynamicSharedMemorySize, KP_SMEM);
        cudaFuncSetAttribute(kFuse,      cudaFuncAttributeMaxDynamicSharedMemorySize, KF_SMEM);
        cudaFuncSetAttribute(k6_mma,     cudaFuncAttributeMaxDynamicSharedMemorySize, K6_SMEM);
        cudaFuncSetAttribute(k7_final,   cudaFuncAttributeMaxDynamicSharedMemorySize, K7_SMEM);
        attr_done = 1;
    }

    k0_prep<<<1549, 256>>>(gfW1, gfW2, l1W, bng);
    k1_att<<<NB, 256>>>(x, attW, attb, outW, wflag);
    k_proj_mma<<<NR3/128, 256, KP_SMEM>>>(x);
    kFuse<<<NB/16, 256, KF_SMEM>>>(x, gfb1, gfb2, outW, wflag);
    dim3 g6(NB/128, 16);
    k6_mma<<<g6, 256, K6_SMEM>>>(gfb2);
    k7_final<<<NB/64, 256, K7_SMEM>>>(bnb, l1b, l2W, l2b, l3W, l3b, out);
}

// round 11
// speedup vs baseline: 3.1634x; 1.0057x over previous
#include <cuda_runtime.h>
#include <cstdint>
#include <cstddef>

// ---------------------------------------------------------------------------
// graph12 — Round 9: FMA-poly exp for bounded bi3 exponentials (MUFU offload)
//                    + bisum folded into stats loop.
// ---------------------------------------------------------------------------

#define NB    16384
#define ND    1024
#define NR3   (NB*3)

__device__ float g_W1t  [128*1024];          // W1r transposed [n][k], tf32
__device__ float g_W2t  [1024*64];           // W2 transposed [n][k], tf32
__device__ float g_l1Wp [3072*64];           // tf32, padded 50->64
__device__ float g_bnsc [3072];
__device__ float g_PQ1  [(size_t)NR3*128];
__device__ float g_act2 [(size_t)6*NB*64];
__device__ float g_uni  [(size_t)NB*ND];
__device__ float g_bisum[(size_t)NB*ND];
__device__ float g_tri  [(size_t)NB*ND];
__device__ float g_wuni [NB*3];
__device__ float g_wbi  [NB*3];
__device__ float g_sbi  [NB*3];
__device__ float g_wtri [NB*6];

// -------------------------- helpers -----------------------------------------
__device__ __forceinline__ float f2tf_f(float f) {
    unsigned r;
    asm("cvt.rna.tf32.f32 %0, %1;" : "=r"(r) : "f"(f));
    return __uint_as_float(r);
}

__device__ __forceinline__ float tanh_fast(float x) {
    float r;
    asm("tanh.approx.f32 %0, %1;" : "=f"(r) : "f"(x));
    return r;
}

// exp(v) for v in [-0.02, 1.01]: degree-7 Taylor (Horner), rel err <= ~7e-5.
__device__ __forceinline__ float exp_poly(float v) {
    float p = 1.984127e-4f;                  // 1/5040
    p = fmaf(p, v, 1.3888889e-3f);           // 1/720
    p = fmaf(p, v, 8.3333333e-3f);           // 1/120
    p = fmaf(p, v, 4.1666667e-2f);           // 1/24
    p = fmaf(p, v, 1.6666667e-1f);           // 1/6
    p = fmaf(p, v, 0.5f);
    p = fmaf(p, v, 1.0f);
    p = fmaf(p, v, 1.0f);
    return p;
}

__device__ __forceinline__ void mma_t(float4& d, unsigned a0, unsigned a1,
                                      unsigned a2, unsigned a3,
                                      unsigned b0, unsigned b1) {
    asm volatile(
        "mma.sync.aligned.m16n8k8.row.col.f32.tf32.tf32.f32 "
        "{%0,%1,%2,%3}, {%4,%5,%6,%7}, {%8,%9}, {%0,%1,%2,%3};"
        : "+f"(d.x), "+f"(d.y), "+f"(d.z), "+f"(d.w)
        : "r"(a0), "r"(a1), "r"(a2), "r"(a3), "r"(b0), "r"(b1));
}

__device__ __forceinline__ uint4 ldsm4(unsigned addr) {
    uint4 r;
    asm volatile("ldmatrix.sync.aligned.m8n8.x4.shared.b16 {%0,%1,%2,%3}, [%4];"
                 : "=r"(r.x), "=r"(r.y), "=r"(r.z), "=r"(r.w) : "r"(addr));
    return r;
}

__device__ __forceinline__ unsigned a_ptr(unsigned base, int rbase, int S, int lane) {
    return base + ((rbase + (lane & 15))*S + ((lane & 16) >> 2))*4;
}
__device__ __forceinline__ unsigned b_ptr(unsigned base, int nbase, int St, int lane) {
    return base + ((nbase + (lane & 7) + ((lane & 16) >> 1))*St + ((lane & 8) >> 1))*4;
}

__device__ __forceinline__ void cpasync16(float* dst_smem, const float* src) {
    unsigned d = (unsigned)__cvta_generic_to_shared(dst_smem);
    asm volatile("cp.async.cg.shared.global [%0], [%1], 16;" :: "r"(d), "l"(src));
}
#define CP_COMMIT  asm volatile("cp.async.commit_group;")
#define CP_WAIT0   asm volatile("cp.async.wait_group 0;")
#define CP_WAIT1   asm volatile("cp.async.wait_group 1;")

// -------------------------- block reductions (256 thr) ----------------------
template<int NV>
__device__ __forceinline__ void blockReduceSumN(float* v, float* rbuf) {
    int tid = threadIdx.x, lane = tid & 31, w = tid >> 5;
#pragma unroll
    for (int n = 0; n < NV; n++) {
        float x = v[n];
#pragma unroll
        for (int o = 16; o > 0; o >>= 1) x += __shfl_down_sync(0xffffffffu, x, o);
        if (lane == 0) rbuf[n*8 + w] = x;
    }
    __syncthreads();
    if (tid < NV) {
        float s = rbuf[tid*8];
#pragma unroll
        for (int q = 1; q < 8; q++) s += rbuf[tid*8 + q];
        rbuf[tid*8] = s;
    }
    __syncthreads();
#pragma unroll
    for (int n = 0; n < NV; n++) v[n] = rbuf[n*8];
    __syncthreads();
}

template<int NV>
__device__ __forceinline__ void blockReduceMaxN(float* v, float* rbuf) {
    int tid = threadIdx.x, lane = tid & 31, w = tid >> 5;
#pragma unroll
    for (int n = 0; n < NV; n++) {
        float x = v[n];
#pragma unroll
        for (int o = 16; o > 0; o >>= 1) x = fmaxf(x, __shfl_down_sync(0xffffffffu, x, o));
        if (lane == 0) rbuf[n*8 + w] = x;
    }
    __syncthreads();
    if (tid < NV) {
        float s = rbuf[tid*8];
#pragma unroll
        for (int q = 1; q < 8; q++) s = fmaxf(s, rbuf[tid*8 + q]);
        rbuf[tid*8] = s;
    }
    __syncthreads();
#pragma unroll
    for (int n = 0; n < NV; n++) v[n] = rbuf[n*8];
    __syncthreads();
}

// -------------------------- k0: prep ----------------------------------------
__global__ void k0_prep(const float* __restrict__ W1, const float* __restrict__ W2,
                        const float* __restrict__ l1W, const float* __restrict__ bng)
{
    int i = blockIdx.x * 256 + threadIdx.x;
    if (i < 131072) {
        int n = i >> 10, k = i & 1023;
        float v = (n < 64) ? W1[(size_t)k*64 + n] : W1[(size_t)(1024 + k)*64 + (n - 64)];
        g_W1t[i] = f2tf_f(v);
    } else if (i < 196608) {
        int i2 = i - 131072;
        int n = i2 >> 6, k = i2 & 63;
        g_W2t[i2] = f2tf_f(W2[(size_t)k*1024 + n]);
    } else if (i < 393216) {
        int i3 = i - 196608;
        int row = i3 >> 6, c = i3 & 63;
        g_l1Wp[i3] = (c < 50) ? f2tf_f(l1W[(size_t)row*50 + c]) : 0.f;
    } else if (i < 396288) {
        int j = i - 393216;
        float mult = (j < 1024) ? 1.f : ((j < 2048) ? (1.f/3.f) : (1.f/6.f));
        g_bnsc[j] = bng[j] * rsqrtf(1.0f + 1e-5f) * mult;
    }
}

// -------------------------- k1: attention + stage-1 stats -------------------
__global__ __launch_bounds__(256) void k1_att(
    const float* __restrict__ x, const float* __restrict__ attW,
    const float* __restrict__ attb, float* __restrict__ outW, int wflag)
{
    __shared__ float sm[3072];
    __shared__ float rbuf[6*8];
    __shared__ float bc[4];
    int b = blockIdx.x, tid = threadIdx.x;
    const float4* xr4 = (const float4*)(x + (size_t)b*3072);
    for (int i = tid; i < 768; i += 256) ((float4*)sm)[i] = xr4[i];
    __syncthreads();

    float red[3];
    float a0 = 0.f, a1 = 0.f, a2 = 0.f;
    float m0 = -1e30f, m1 = -1e30f, m2 = -1e30f;
    for (int i = tid; i < 1024; i += 256) {
        float w = attW[i];
        float av = sm[i], vv = sm[1024 + i], lv = sm[2048 + i];
        a0 = fmaf(av, w, a0); a1 = fmaf(vv, w, a1); a2 = fmaf(lv, w, a2);
        m0 = fmaxf(m0, av);  m1 = fmaxf(m1, vv);  m2 = fmaxf(m2, lv);
    }
    red[0] = a0; red[1] = a1; red[2] = a2;
    blockReduceSumN<3>(red, rbuf);
    float att0 = red[0], att1 = red[1], att2 = red[2];
    red[0] = m0; red[1] = m1; red[2] = m2;
    blockReduceMaxN<3>(red, rbuf);
    float Ma = red[0], Mv = red[1], Ml = red[2];

    float red6[6] = {0.f, 0.f, 0.f, 0.f, 0.f, 0.f};
    for (int i = tid; i < 1024; i += 256) {
        float ea = __expf(sm[i] - Ma);
        float ev = __expf(sm[1024 + i] - Mv);
        float el = __expf(sm[2048 + i] - Ml);
        red6[0] += ea; red6[1] += ev; red6[2] += el;
        red6[3] = fmaf(ea, ev, red6[3]);
        red6[4] = fmaf(ea, el, red6[4]);
        red6[5] = fmaf(ev, el, red6[5]);
    }
    blockReduceSumN<6>(red6, rbuf);

    if (tid == 0) {
        float ab = attb[0];
        float t0 = tanhf(att0 + ab), t1 = tanhf(att1 + ab), t2 = tanhf(att2 + ab);
        float mm = fmaxf(t0, fmaxf(t1, t2));
        float e0 = expf(t0 - mm), e1 = expf(t1 - mm), e2 = expf(t2 - mm);
        float inv = 1.f / (e0 + e1 + e2);
        float sa = e0*inv, sv = e1*inv, sl = e2*inv;
        float dav = red6[3] / (red6[0]*red6[1]);
        float dal = red6[4] / (red6[0]*red6[2]);
        float dvl = red6[5] / (red6[1]*red6[2]);
        float sav = (sa + sv) / (dav + 0.5f);
        float sal = (sa + sl) / (dal + 0.5f);
        float svl = (sl + sv) / (dvl + 0.5f);
        g_wuni[b*3+0] = sa; g_wuni[b*3+1] = sv; g_wuni[b*3+2] = sl;
        g_sbi [b*3+0] = sav; g_sbi[b*3+1] = sal; g_sbi[b*3+2] = svl;
        float m3 = fmaxf(sav, fmaxf(sal, svl));
        float f0 = expf(sav - m3), f1 = expf(sal - m3), f2 = expf(svl - m3);
        float fi = 1.f / (f0 + f1 + f2);
        g_wbi[b*3+0] = f0*fi; g_wbi[b*3+1] = f1*fi; g_wbi[b*3+2] = f2*fi;
        if (wflag) {
            float* o = outW + (size_t)b*12;
            o[0] = sa; o[1] = sv; o[2] = sl;
            o[3] = f0*fi; o[4] = f1*fi; o[5] = f2*fi;
        }
        bc[0] = sa; bc[1] = sv; bc[2] = sl;
    }
    __syncthreads();
    float sa = bc[0], sv = bc[1], sl = bc[2];
    float* ur = g_uni + (size_t)b*1024;
    for (int i = tid; i < 1024; i += 256)
        ur[i] = (sa*sm[i] + sv*sm[1024+i] + sl*sm[2048+i]) * (1.0f/3.0f);
}

// -------------------------- kP: PQ1 projection (ldmatrix, 3-stage) ----------
#define KP_STAGE (128*36 * 2)
#define KP_SMEM  (3*KP_STAGE*4)

__device__ __forceinline__ void kp_issue(const float* __restrict__ A, size_t m0,
                                         float* stage, int t, int tid)
{
    float* As  = stage;                 // [128][36]
    float* Bts = stage + 128*36;        // [128][36]
    int kk = t * 32;
#pragma unroll
    for (int j = 0; j < 4; j++) {
        int i = tid + j*256;
        int r = i >> 3, kq = i & 7;
        cpasync16(&As[r*36 + kq*4], &A[(m0 + r)*1024 + kk + kq*4]);
    }
#pragma unroll
    for (int j = 0; j < 4; j++) {
        int i = tid + j*256;
        int n = i >> 3, kq = i & 7;
        cpasync16(&Bts[n*36 + kq*4], &g_W1t[(size_t)n*1024 + kk + kq*4]);
    }
    CP_COMMIT;
}

__global__ __launch_bounds__(256) void k_proj_mma(const float* __restrict__ x)
{
    extern __shared__ float smp[];
    int tid = threadIdx.x;
    size_t m0 = (size_t)blockIdx.x * 128;
    int lane = tid & 31, wid = tid >> 5;
    int t4 = lane & 3, g = lane >> 2;
    int wm = wid >> 1, wn = wid & 1;

    float4 acc[2][8] = {};

    kp_issue(x, m0, smp,            0, tid);
    kp_issue(x, m0, smp + KP_STAGE, 1, tid);

    int s = 0;
    for (int t = 0; t < 32; t++) {
        if (t < 31) { CP_WAIT1; } else { CP_WAIT0; }
        __syncthreads();
        if (t + 2 < 32)
            kp_issue(x, m0, smp + ((s + 2) % 3)*KP_STAGE, t + 2, tid);
        float* Ac = smp + s*KP_STAGE;
        unsigned Au = (unsigned)__cvta_generic_to_shared(Ac);
        unsigned Bu = Au + 128*36*4;
        unsigned pA0 = a_ptr(Au, wm*32,      36, lane);
        unsigned pA1 = pA0 + 16*36*4;
        unsigned pB  = b_ptr(Bu, wn*64, 36, lane);
#pragma unroll
        for (int ks = 0; ks < 4; ks++) {
            uint4 a0 = ldsm4(pA0 + ks*32);
            uint4 a1 = ldsm4(pA1 + ks*32);
            uint4 bv[4];
#pragma unroll
            for (int p = 0; p < 4; p++) bv[p] = ldsm4(pB + p*16*36*4 + ks*32);
#pragma unroll
            for (int n = 0; n < 8; n++) {
                unsigned b0 = (n & 1) ? bv[n>>1].z : bv[n>>1].x;
                unsigned b1 = (n & 1) ? bv[n>>1].w : bv[n>>1].y;
                mma_t(acc[0][n], a0.x, a0.y, a0.z, a0.w, b0, b1);
                mma_t(acc[1][n], a1.x, a1.y, a1.z, a1.w, b0, b1);
            }
        }
        s = (s + 1) % 3;
    }
#pragma unroll
    for (int m = 0; m < 2; m++) {
        size_t r0 = m0 + wm*32 + m*16 + g;
        size_t r1 = r0 + 8;
#pragma unroll
        for (int n = 0; n < 8; n++) {
            int col = wn*64 + n*8 + t4*2;
            float2 o0; o0.x = acc[m][n].x; o0.y = acc[m][n].y;
            float2 o1; o1.x = acc[m][n].z; o1.y = acc[m][n].w;
            *(float2*)&g_PQ1[r0*128 + col] = o0;
            *(float2*)&g_PQ1[r1*128 + col] = o1;
        }
    }
}

// -------------------------- kFuse: stage-2 megafusion -----------------------
#define KF_PQ1   0
#define KF_ACT1  6336
#define KF_BI3   9600
#define KF_W2    12864
#define KF_W1    17216
#define KF_B1    25920
#define KF_WBI   25984
#define KF_TOTF  (25984+48+16)
#define KF_SMEM  (KF_TOTF*4)

__global__ __launch_bounds__(256) void kFuse(
    const float* __restrict__ x, const float* __restrict__ b1,
    const float* __restrict__ b2, float* __restrict__ outW, int wflag)
{
    extern __shared__ float sf[];
    float* PQ1s = sf + KF_PQ1;
    float* act1s= sf + KF_ACT1;
    float* bi3c = sf + KF_BI3;
    float* W2ts = sf + KF_W2;
    float* W1ts = sf + KF_W1;
    float* b1s  = sf + KF_B1;
    float* wbis = sf + KF_WBI;

    int tid = threadIdx.x;
    int bb0 = blockIdx.x * 16;
    int lane = tid & 31, wid = tid >> 5;
    int t4 = lane & 3, g = lane >> 2;
    int wm = wid >> 1, wn = wid & 1;

    for (int i = tid; i < 1536; i += 256) {
        int r = i >> 5, c4 = i & 31;
        int p = r >> 4, b = r & 15;
        cpasync16(&PQ1s[r*132 + c4*4], &g_PQ1[((size_t)(bb0 + b)*3 + p)*128 + c4*4]);
    }
    CP_COMMIT;
    if (tid < 64) b1s[tid] = b1[tid];
    if (tid < 48) { int p = tid >> 4, b = tid & 15; wbis[tid] = g_wbi[(bb0 + b)*3 + p]; }
    CP_WAIT0;
    __syncthreads();
    for (int i = tid; i < 3072; i += 256) {
        int r = i >> 6, k = i & 63;
        int p = r >> 4, b = r & 15;
        int f = (p == 2) ? 1 : 0;
        int s = (p == 0) ? 1 : 2;
        float tv = PQ1s[(f*16+b)*132 + k] + PQ1s[(s*16+b)*132 + 64 + k] + b1s[k];
        act1s[r*68 + k] = tv > 0.f ? tv : 0.2f*tv;
    }
    __syncthreads();

    unsigned act1u = (unsigned)__cvta_generic_to_shared(act1s);
    unsigned bi3u  = (unsigned)__cvta_generic_to_shared(bi3c);
    unsigned w2tu  = (unsigned)__cvta_generic_to_shared(W2ts);
    unsigned w1tu  = (unsigned)__cvta_generic_to_shared(W1ts);
    unsigned pA1 = a_ptr(act1u, wm*16, 68, lane);
    unsigned pA2 = a_ptr(bi3u,  wm*16, 68, lane);
    unsigned pB1 = b_ptr(w2tu, wn*32, 68, lane);
    unsigned pB2 = b_ptr(w1tu, wn*64, 68, lane);

    float sE[2][3] = {}, sX[2][3] = {}, sP[2][3] = {}, sQ[2][3] = {};
    float4 pq2[8] = {};

    for (int n = 0; n < 16; n++) {
        int n0 = n * 64;
        for (int i = tid; i < 1024; i += 256) {
            int r = i >> 4, c4 = i & 15;
            cpasync16(&W2ts[r*68 + c4*4], &g_W2t[(size_t)(n0 + r)*64 + c4*4]);
        }
        for (int i = tid; i < 2048; i += 256) {
            int r = i >> 4, c4 = i & 15;
            cpasync16(&W1ts[r*68 + c4*4], &g_W1t[(size_t)r*1024 + n0 + c4*4]);
        }
        CP_COMMIT;
        float xr[12];
#pragma unroll
        for (int j = 0; j < 2; j++)
#pragma unroll
        for (int m = 0; m < 3; m++)
#pragma unroll
        for (int h = 0; h < 2; h++)
            xr[(j*3+m)*2+h] = x[((size_t)(bb0 + 2*wid + j)*3 + m)*1024 + n0 + lane + h*32];
        CP_WAIT0;
        __syncthreads();

        // GEMM1: act1 @ W2 chunk -> bi3c (tanh.approx * wbi, lrelu)
        if (wid < 6) {
            float4 acc[4] = {};
#pragma unroll
            for (int ks = 0; ks < 8; ks++) {
                uint4 a  = ldsm4(pA1 + ks*32);
                uint4 b0 = ldsm4(pB1 + ks*32);
                uint4 b1v= ldsm4(pB1 + 16*68*4 + ks*32);
                mma_t(acc[0], a.x,a.y,a.z,a.w, b0.x, b0.y);
                mma_t(acc[1], a.x,a.y,a.z,a.w, b0.z, b0.w);
                mma_t(acc[2], a.x,a.y,a.z,a.w, b1v.x, b1v.y);
                mma_t(acc[3], a.x,a.y,a.z,a.w, b1v.z, b1v.w);
            }
            int r0 = wm*16 + g, r1 = r0 + 8;
            float w0 = wbis[r0], w1 = wbis[r1];
#pragma unroll
            for (int q = 0; q < 4; q++) {
                int col = wn*32 + q*8 + t4*2;
                float2 b2v = *(const float2*)&b2[n0 + col];
                float t, v;
                t = tanh_fast(acc[q].x + b2v.x)*w0; v = t > 0.f ? t : 0.01f*t; bi3c[r0*68 + col]   = v;
                t = tanh_fast(acc[q].y + b2v.y)*w0; v = t > 0.f ? t : 0.01f*t; bi3c[r0*68 + col+1] = v;
                t = tanh_fast(acc[q].z + b2v.x)*w1; v = t > 0.f ? t : 0.01f*t; bi3c[r1*68 + col]   = v;
                t = tanh_fast(acc[q].w + b2v.y)*w1; v = t > 0.f ? t : 0.01f*t; bi3c[r1*68 + col+1] = v;
            }
        }
        __syncthreads();

        // stats + bisum (fused) + GEMM2.  bi3 values bounded -> poly exp.
#pragma unroll
        for (int j = 0; j < 2; j++) {
            int b = 2*wid + j;
            float* bsrow = &g_bisum[(size_t)(bb0 + b)*1024 + n0];
#pragma unroll
            for (int h = 0; h < 2; h++) {
                int c = lane + (h ? 32 : 0);
                float v0 = bi3c[b*68 + c];
                float v1 = bi3c[(16+b)*68 + c];
                float v2 = bi3c[(32+b)*68 + c];
                bsrow[c] = v0 + v1 + v2;
                float e0 = exp_poly(v0);
                float e1 = exp_poly(v1);
                float e2 = exp_poly(v2);
                float xa = __expf(xr[(j*3+0)*2+h]);
                float xv = __expf(xr[(j*3+1)*2+h]);
                float xl = __expf(xr[(j*3+2)*2+h]);
                sE[j][0] += e0; sE[j][1] += e1; sE[j][2] += e2;
                sX[j][0] += xa; sX[j][1] += xv; sX[j][2] += xl;
                sP[j][0] = fmaf(e0, e2, sP[j][0]);
                sP[j][1] = fmaf(e0, e1, sP[j][1]);
                sP[j][2] = fmaf(e1, e2, sP[j][2]);
                sQ[j][0] = fmaf(e0, xl, sQ[j][0]);
                sQ[j][1] = fmaf(e1, xv, sQ[j][1]);
                sQ[j][2] = fmaf(e2, xa, sQ[j][2]);
            }
        }
        if (wid < 6) {
#pragma unroll
            for (int ks = 0; ks < 8; ks++) {
                uint4 a = ldsm4(pA2 + ks*32);
                uint4 bv[4];
#pragma unroll
                for (int p = 0; p < 4; p++) bv[p] = ldsm4(pB2 + p*16*68*4 + ks*32);
#pragma unroll
                for (int q = 0; q < 8; q++) {
                    unsigned b0 = (q & 1) ? bv[q>>1].z : bv[q>>1].x;
                    unsigned b1 = (q & 1) ? bv[q>>1].w : bv[q>>1].y;
                    mma_t(pq2[q], a.x,a.y,a.z,a.w, b0, b1);
                }
            }
        }
        __syncthreads();
    }

    // ---- stats reduce -> w_tri ----
#pragma unroll
    for (int j = 0; j < 2; j++) {
#pragma unroll
        for (int o = 16; o > 0; o >>= 1) {
#pragma unroll
            for (int v = 0; v < 3; v++) {
                sE[j][v] += __shfl_down_sync(0xffffffffu, sE[j][v], o);
                sX[j][v] += __shfl_down_sync(0xffffffffu, sX[j][v], o);
                sP[j][v] += __shfl_down_sync(0xffffffffu, sP[j][v], o);
                sQ[j][v] += __shfl_down_sync(0xffffffffu, sQ[j][v], o);
            }
        }
    }
    if (lane == 0) {
#pragma unroll
        for (int j = 0; j < 2; j++) {
            int b = bb0 + 2*wid + j;
            float d0 = sP[j][0] / (sE[j][0]*sE[j][2]);
            float d1 = sP[j][1] / (sE[j][0]*sE[j][1]);
            float d2 = sP[j][2] / (sE[j][1]*sE[j][2]);
            float d3 = sQ[j][0] / (sE[j][0]*sX[j][2]);
            float d4 = sQ[j][1] / (sE[j][1]*sX[j][1]);
            float d5 = sQ[j][2] / (sE[j][2]*sX[j][0]);
            float sa = g_wuni[b*3+0], sv = g_wuni[b*3+1], sl = g_wuni[b*3+2];
            float sav = g_sbi[b*3+0], sal = g_sbi[b*3+1], svl = g_sbi[b*3+2];
            float nn[6];
            nn[0] = (sav + svl)/(d0 + 0.5f);
            nn[1] = (sav + sal)/(d1 + 0.5f);
            nn[2] = (sal + svl)/(d2 + 0.5f);
            nn[3] = (sav + sl )/(d3 + 0.5f);
            nn[4] = (sal + sv )/(d4 + 0.5f);
            nn[5] = (sa  + svl)/(d5 + 0.5f);
            float m = nn[0];
#pragma unroll
            for (int k = 1; k < 6; k++) m = fmaxf(m, nn[k]);
            float e[6], ss = 0.f;
#pragma unroll
            for (int k = 0; k < 6; k++) { e[k] = expf(nn[k]-m); ss += e[k]; }
            float inv = 1.f/ss;
#pragma unroll
            for (int k = 0; k < 6; k++) {
                g_wtri[(size_t)b*6 + k] = e[k]*inv;
                if (wflag) outW[(size_t)b*12 + 6 + k] = e[k]*inv;
            }
        }
    }

    // ---- PQ2 -> smem (reuse W1ts region as [48][136]) ----
    __syncthreads();
    if (wid < 6) {
        int r0 = wm*16 + g, r1 = r0 + 8;
#pragma unroll
        for (int q = 0; q < 8; q++) {
            int col = wn*64 + q*8 + t4*2;
            W1ts[r0*136 + col]   = pq2[q].x;
            W1ts[r0*136 + col+1] = pq2[q].y;
            W1ts[r1*136 + col]   = pq2[q].z;
            W1ts[r1*136 + col+1] = pq2[q].w;
        }
    }
    __syncthreads();
    // ---- act2 ----
    const int PR[6] = {0,0,2,0,1,2};
    const int QR[6] = {2,1,1,2,1,0};
    const int QS[6] = {0,0,0,1,1,1};
    for (int i = tid; i < 6144; i += 256) {
        int p = i >> 10, rem = i & 1023;
        int b = rem >> 6, k = rem & 63;
        float pv = W1ts[(PR[p]*16 + b)*136 + k];
        float qv = QS[p] ? PQ1s[(QR[p]*16 + b)*132 + 64 + k]
                         : W1ts[(QR[p]*16 + b)*136 + 64 + k];
        float tv = pv + qv + b1s[k];
        g_act2[((size_t)p*NB + bb0 + b)*64 + k] = tv > 0.f ? tv : 0.2f*tv;
    }
}

// -------------------------- k6: stage-2 second layer ------------------------
#define K6_SMEM ((2*128*68 + 64*68)*4)
__global__ __launch_bounds__(256) void k6_mma(const float* __restrict__ b2)
{
    extern __shared__ float sm6[];
    float* AsB  = sm6;
    float* W2ts = sm6 + 2*128*68;
    int tid = threadIdx.x;
    int b0 = blockIdx.x * 128, n0 = blockIdx.y * 64;

    for (int i = tid; i < 1024; i += 256) {
        int r = i >> 4, c4 = i & 15;
        cpasync16(&W2ts[r*68 + c4*4], &g_W2t[(size_t)(n0 + r)*64 + c4*4]);
    }
    {
        const float* Ap = g_act2 + ((size_t)0*NB + b0)*64;
        for (int i = tid; i < 2048; i += 256) {
            int r = i >> 4, c4 = i & 15;
            cpasync16(&AsB[r*68 + c4*4], &Ap[(size_t)r*64 + c4*4]);
        }
    }
    CP_COMMIT;

    int lane = tid & 31, wid = tid >> 5;
    int t4 = lane & 3, g = lane >> 2;
    int wm = wid >> 1, wn = wid & 1;
    int rw = wm*32, cw = wn*32;

    unsigned w2tu = (unsigned)__cvta_generic_to_shared(W2ts);
    unsigned pB  = b_ptr(w2tu, cw, 68, lane);
    unsigned As0u = (unsigned)__cvta_generic_to_shared(AsB);

    float4 tri[2][4] = {};
#pragma unroll 1
    for (int p = 0; p < 6; p++) {
        if (p + 1 < 6) {
            const float* Ap = g_act2 + ((size_t)(p+1)*NB + b0)*64;
            float* Ad = AsB + ((p+1) & 1)*128*68;
            for (int i = tid; i < 2048; i += 256) {
                int r = i >> 4, c4 = i & 15;
                cpasync16(&Ad[r*68 + c4*4], &Ap[(size_t)r*64 + c4*4]);
            }
            CP_COMMIT;
            CP_WAIT1;
        } else {
            CP_WAIT0;
        }
        __syncthreads();
        unsigned Au = As0u + (unsigned)((p & 1)*128*68*4);
        unsigned pA0 = a_ptr(Au, rw, 68, lane);
        unsigned pA1 = pA0 + 16*68*4;
        float4 acc[2][4] = {};
#pragma unroll
        for (int ks = 0; ks < 8; ks++) {
            uint4 a0 = ldsm4(pA0 + ks*32);
            uint4 a1 = ldsm4(pA1 + ks*32);
            uint4 b0 = ldsm4(pB + ks*32);
            uint4 b1v= ldsm4(pB + 16*68*4 + ks*32);
            mma_t(acc[0][0], a0.x,a0.y,a0.z,a0.w, b0.x, b0.y);
            mma_t(acc[0][1], a0.x,a0.y,a0.z,a0.w, b0.z, b0.w);
            mma_t(acc[0][2], a0.x,a0.y,a0.z,a0.w, b1v.x, b1v.y);
            mma_t(acc[0][3], a0.x,a0.y,a0.z,a0.w, b1v.z, b1v.w);
            mma_t(acc[1][0], a1.x,a1.y,a1.z,a1.w, b0.x, b0.y);
            mma_t(acc[1][1], a1.x,a1.y,a1.z,a1.w, b0.z, b0.w);
            mma_t(acc[1][2], a1.x,a1.y,a1.z,a1.w, b1v.x, b1v.y);
            mma_t(acc[1][3], a1.x,a1.y,a1.z,a1.w, b1v.z, b1v.w);
        }
#pragma unroll
        for (int m = 0; m < 2; m++) {
            int r0 = b0 + rw + m*16 + g;
            int r1 = r0 + 8;
            float wt0 = g_wtri[(size_t)r0*6 + p];
            float wt1 = g_wtri[(size_t)r1*6 + p];
#pragma unroll
            for (int q = 0; q < 4; q++) {
                int col = n0 + cw + q*8 + t4*2;
                float2 b2v = *(const float2*)&b2[col];
                float t;
                t = tanh_fast(acc[m][q].x + b2v.x)*wt0; tri[m][q].x += (t > 0.f ? t : 0.01f*t);
                t = tanh_fast(acc[m][q].y + b2v.y)*wt0; tri[m][q].y += (t > 0.f ? t : 0.01f*t);
                t = tanh_fast(acc[m][q].z + b2v.x)*wt1; tri[m][q].z += (t > 0.f ? t : 0.01f*t);
                t = tanh_fast(acc[m][q].w + b2v.y)*wt1; tri[m][q].w += (t > 0.f ? t : 0.01f*t);
            }
        }
        __syncthreads();
    }
#pragma unroll
    for (int m = 0; m < 2; m++) {
        size_t r0 = b0 + rw + m*16 + g, r1 = r0 + 8;
#pragma unroll
        for (int q = 0; q < 4; q++) {
            int col = n0 + cw + q*8 + t4*2;
            float2 o0; o0.x = tri[m][q].x; o0.y = tri[m][q].y;
            float2 o1; o1.x = tri[m][q].z; o1.y = tri[m][q].w;
            *(float2*)&g_tri[r0*1024 + col] = o0;
            *(float2*)&g_tri[r1*1024 + col] = o1;
        }
    }
}

// -------------------------- k7: fused head (tf32 layer1) --------------------
#define K7_SMEM ((64*36 + 32*72 + 64*52*2 + 512 + 3000)*4)
__global__ __launch_bounds__(256) void k7_final(
    const float* __restrict__ bnb,
    const float* __restrict__ l1b,
    const float* __restrict__ l2W, const float* __restrict__ l2b,
    const float* __restrict__ l3W, const float* __restrict__ l3b,
    float* __restrict__ out)
{
    extern __shared__ float pool[];
    float* As  = pool;
    float* Bs  = pool + 2304;
    float* Y1  = pool + 4608;
    float* Y2  = pool + 7936;
    float* Y3  = pool + 11264;
    float* W23 = pool + 11776;
    int tid = threadIdx.x;
    int b0 = blockIdx.x * 64;
    int lane = tid & 31, wid = tid >> 5;
    int g = lane >> 2, t4 = lane & 3;
    int wm = wid >> 2, wn = wid & 3;
    int rw = wm*32, cw = wn*16;

    for (int i = tid; i < 2500; i += 256) {
        int k = i / 50, c = i - k*50;
        W23[k*52 + c] = l2W[i];
    }
    for (int i = tid; i < 400; i += 256) W23[2600 + i] = l3W[i];

    float4 acc[2][2] = {};
    for (int t = 0; t < 96; t++) {
        int kk = t * 32;
        int region = kk >> 10;
        const float* src = region == 0 ? g_uni : (region == 1 ? g_bisum : g_tri);
        __syncthreads();
        for (int i = tid; i < 512; i += 256) {
            int r = i >> 3, c4 = i & 7;
            float4 v = *(const float4*)&src[(size_t)(b0 + r)*1024 + (kk & 1023) + c4*4];
            int j = kk + c4*4;
            float* d = &As[r*36 + c4*4];
            d[0] = f2tf_f(fmaf(v.x, g_bnsc[j],   bnb[j]));
            d[1] = f2tf_f(fmaf(v.y, g_bnsc[j+1], bnb[j+1]));
            d[2] = f2tf_f(fmaf(v.z, g_bnsc[j+2], bnb[j+2]));
            d[3] = f2tf_f(fmaf(v.w, g_bnsc[j+3], bnb[j+3]));
        }
        for (int i = tid; i < 512; i += 256) {
            int k = i >> 4, c4 = i & 15;
            cpasync16(&Bs[k*72 + c4*4], &g_l1Wp[(size_t)(kk + k)*64 + c4*4]);
        }
        CP_COMMIT; CP_WAIT0;
        __syncthreads();
#pragma unroll
        for (int ks = 0; ks < 4; ks++) {
            unsigned a[2][4], bf[2][2];
#pragma unroll
            for (int m = 0; m < 2; m++) {
                int r = rw + m*16 + g;
                a[m][0] = __float_as_uint(As[r*36 + ks*8 + t4]);
                a[m][1] = __float_as_uint(As[(r+8)*36 + ks*8 + t4]);
                a[m][2] = __float_as_uint(As[r*36 + ks*8 + t4 + 4]);
                a[m][3] = __float_as_uint(As[(r+8)*36 + ks*8 + t4 + 4]);
            }
#pragma unroll
            for (int n = 0; n < 2; n++) {
                int c = cw + n*8 + g;
                bf[n][0] = __float_as_uint(Bs[(ks*8 + t4)*72 + c]);
                bf[n][1] = __float_as_uint(Bs[(ks*8 + t4 + 4)*72 + c]);
            }
#pragma unroll
            for (int m = 0; m < 2; m++)
#pragma unroll
            for (int n = 0; n < 2; n++)
                mma_t(acc[m][n], a[m][0],a[m][1],a[m][2],a[m][3], bf[n][0], bf[n][1]);
        }
    }
    __syncthreads();
#pragma unroll
    for (int m = 0; m < 2; m++) {
        int r0 = rw + m*16 + g, r1 = r0 + 8;
#pragma unroll
        for (int n = 0; n < 2; n++) {
            int c = cw + n*8 + t4*2;
            if (c < 50)   { Y1[r0*52 + c]   = tanhf(acc[m][n].x + l1b[c]);
                            Y1[r1*52 + c]   = tanhf(acc[m][n].z + l1b[c]); }
            if (c+1 < 50) { Y1[r0*52 + c+1] = tanhf(acc[m][n].y + l1b[c+1]);
                            Y1[r1*52 + c+1] = tanhf(acc[m][n].w + l1b[c+1]); }
        }
    }
    __syncthreads();

    for (int o = tid; o < 3200; o += 256) {
        int r = o / 50, c = o - r*50;
        float a = l2b[c];
        for (int k = 0; k < 50; k++)
            a = fmaf(Y1[r*52 + k], W23[k*52 + c], a);
        Y2[r*52 + c] = tanhf(a);
    }
    __syncthreads();

    for (int o = tid; o < 512; o += 256) {
        int r = o >> 3, c = o & 7;
        float a = l3b[c];
        for (int k = 0; k < 50; k++)
            a = fmaf(Y2[r*52 + k], W23[2600 + k*8 + c], a);
        Y3[r*8 + c] = a;
    }
    __syncthreads();
    if (tid < 64) {
        int r = tid;
        float m = -1e30f;
#pragma unroll
        for (int c = 0; c < 8; c++) m = fmaxf(m, Y3[r*8 + c]);
        float e[8], s = 0.f;
#pragma unroll
        for (int c = 0; c < 8; c++) { e[c] = expf(Y3[r*8 + c] - m); s += e[c]; }
        float inv = 1.f / s;
        float* orow = out + (size_t)(b0 + r)*8;
#pragma unroll
        for (int c = 0; c < 8; c++) orow[c] = e[c]*inv;
    }
}

// -------------------------- launch ------------------------------------------
extern "C" void kernel_launch(void* const* d_in, const int* in_sizes, int n_in,
                              void* d_out, int out_size)
{
    const float* x    = (const float*)d_in[0];
    const float* attW = (const float*)d_in[1];
    const float* attb = (const float*)d_in[2];
    const float* gfW1 = (const float*)d_in[3];
    const float* gfb1 = (const float*)d_in[4];
    const float* gfW2 = (const float*)d_in[5];
    const float* gfb2 = (const float*)d_in[6];
    const float* bng  = (const float*)d_in[7];
    const float* bnb  = (const float*)d_in[8];
    const float* l1W  = (const float*)d_in[9];
    const float* l1b  = (const float*)d_in[10];
    const float* l2W  = (const float*)d_in[11];
    const float* l2b  = (const float*)d_in[12];
    const float* l3W  = (const float*)d_in[13];
    const float* l3b  = (const float*)d_in[14];
    float* out  = (float*)d_out;
    int wflag = (out_size >= NB*20) ? 1 : 0;
    float* outW = out + (size_t)NB*8;

    static int attr_done = 0;
    if (!attr_done) {
        cudaFuncSetAttribute(k_proj_mma, cudaFuncAttributeMaxDynamicSharedMemorySize, KP_SMEM);
        cudaFuncSetAttribute(kFuse,      cudaFuncAttributeMaxDynamicSharedMemorySize, KF_SMEM);
        cudaFuncSetAttribute(k6_mma,     cudaFuncAttributeMaxDynamicSharedMemorySize, K6_SMEM);
        cudaFuncSetAttribute(k7_final,   cudaFuncAttributeMaxDynamicSharedMemorySize, K7_SMEM);
        attr_done = 1;
    }

    k0_prep<<<1549, 256>>>(gfW1, gfW2, l1W, bng);
    k1_att<<<NB, 256>>>(x, attW, attb, outW, wflag);
    k_proj_mma<<<NR3/128, 256, KP_SMEM>>>(x);
    kFuse<<<NB/16, 256, KF_SMEM>>>(x, gfb1, gfb2, outW, wflag);
    dim3 g6(NB/128, 16);
    k6_mma<<<g6, 256, K6_SMEM>>>(gfb2);
    k7_final<<<NB/64, 256, K7_SMEM>>>(bnb, l1b, l2W, l2b, l3W, l3b, out);
}

// round 14
// speedup vs baseline: 3.3237x; 1.0507x over previous
#include <cuda_runtime.h>
#include <cstdint>
#include <cstddef>

// ---------------------------------------------------------------------------
// graph12 — Round 13 (= Round 11 kernel, third bench attempt; prior two
//   benches died on broker-level container failures, kernel never executed).
//   k1 eliminated: attention/softmax stats fused into kP (96-row tiles,
//   6 MMA warps + 2 stat warps); unimodal written by kFuse.
// ---------------------------------------------------------------------------

#define NB    16384
#define ND    1024
#define NR3   (NB*3)

__device__ float g_W1t  [128*1024];          // W1r transposed [n][k], tf32
__device__ float g_W2t  [1024*64];           // W2 transposed [n][k], tf32
__device__ float g_l1Wp [3072*64];           // tf32, padded 50->64
__device__ float g_bnsc [3072];
__device__ float g_PQ1  [(size_t)NR3*128];
__device__ float g_act2 [(size_t)6*NB*64];
__device__ float g_uni  [(size_t)NB*ND];
__device__ float g_bisum[(size_t)NB*ND];
__device__ float g_tri  [(size_t)NB*ND];
__device__ float g_wuni [NB*3];
__device__ float g_wbi  [NB*3];
__device__ float g_sbi  [NB*3];
__device__ float g_wtri [NB*6];

// -------------------------- helpers -----------------------------------------
__device__ __forceinline__ float f2tf_f(float f) {
    unsigned r;
    asm("cvt.rna.tf32.f32 %0, %1;" : "=r"(r) : "f"(f));
    return __uint_as_float(r);
}

__device__ __forceinline__ float tanh_fast(float x) {
    float r;
    asm("tanh.approx.f32 %0, %1;" : "=f"(r) : "f"(x));
    return r;
}

// exp(v) for v in [-0.02, 1.01]: degree-7 Taylor (Horner), rel err <= ~7e-5.
__device__ __forceinline__ float exp_poly(float v) {
    float p = 1.984127e-4f;
    p = fmaf(p, v, 1.3888889e-3f);
    p = fmaf(p, v, 8.3333333e-3f);
    p = fmaf(p, v, 4.1666667e-2f);
    p = fmaf(p, v, 1.6666667e-1f);
    p = fmaf(p, v, 0.5f);
    p = fmaf(p, v, 1.0f);
    p = fmaf(p, v, 1.0f);
    return p;
}

__device__ __forceinline__ void mma_t(float4& d, unsigned a0, unsigned a1,
                                      unsigned a2, unsigned a3,
                                      unsigned b0, unsigned b1) {
    asm volatile(
        "mma.sync.aligned.m16n8k8.row.col.f32.tf32.tf32.f32 "
        "{%0,%1,%2,%3}, {%4,%5,%6,%7}, {%8,%9}, {%0,%1,%2,%3};"
        : "+f"(d.x), "+f"(d.y), "+f"(d.z), "+f"(d.w)
        : "r"(a0), "r"(a1), "r"(a2), "r"(a3), "r"(b0), "r"(b1));
}

__device__ __forceinline__ uint4 ldsm4(unsigned addr) {
    uint4 r;
    asm volatile("ldmatrix.sync.aligned.m8n8.x4.shared.b16 {%0,%1,%2,%3}, [%4];"
                 : "=r"(r.x), "=r"(r.y), "=r"(r.z), "=r"(r.w) : "r"(addr));
    return r;
}

__device__ __forceinline__ unsigned a_ptr(unsigned base, int rbase, int S, int lane) {
    return base + ((rbase + (lane & 15))*S + ((lane & 16) >> 2))*4;
}
__device__ __forceinline__ unsigned b_ptr(unsigned base, int nbase, int St, int lane) {
    return base + ((nbase + (lane & 7) + ((lane & 16) >> 1))*St + ((lane & 8) >> 1))*4;
}

__device__ __forceinline__ void cpasync16(float* dst_smem, const float* src) {
    unsigned d = (unsigned)__cvta_generic_to_shared(dst_smem);
    asm volatile("cp.async.cg.shared.global [%0], [%1], 16;" :: "r"(d), "l"(src));
}
#define CP_COMMIT  asm volatile("cp.async.commit_group;")
#define CP_WAIT0   asm volatile("cp.async.wait_group 0;")
#define CP_WAIT1   asm volatile("cp.async.wait_group 1;")

// -------------------------- k0: prep ----------------------------------------
__global__ void k0_prep(const float* __restrict__ W1, const float* __restrict__ W2,
                        const float* __restrict__ l1W, const float* __restrict__ bng)
{
    int i = blockIdx.x * 256 + threadIdx.x;
    if (i < 131072) {
        int n = i >> 10, k = i & 1023;
        float v = (n < 64) ? W1[(size_t)k*64 + n] : W1[(size_t)(1024 + k)*64 + (n - 64)];
        g_W1t[i] = f2tf_f(v);
    } else if (i < 196608) {
        int i2 = i - 131072;
        int n = i2 >> 6, k = i2 & 63;
        g_W2t[i2] = f2tf_f(W2[(size_t)k*1024 + n]);
    } else if (i < 393216) {
        int i3 = i - 196608;
        int row = i3 >> 6, c = i3 & 63;
        g_l1Wp[i3] = (c < 50) ? f2tf_f(l1W[(size_t)row*50 + c]) : 0.f;
    } else if (i < 396288) {
        int j = i - 393216;
        float mult = (j < 1024) ? 1.f : ((j < 2048) ? (1.f/3.f) : (1.f/6.f));
        g_bnsc[j] = bng[j] * rsqrtf(1.0f + 1e-5f) * mult;
    }
}

// -------------------------- kP: PQ1 projection + attention stats ------------
// 96-row tiles (= 32 whole batches). Warps 0-5: tf32 MMA 96x128.
// Warps 6-7: per-batch attention/softmax stats (k1 replacement).
#define KPA_STAGE (96*36 + 128*36)            // 8064 floats
#define KPA_SMEM  ((3*KPA_STAGE + 1024)*4)

__device__ __forceinline__ void kpa_issue(const float* __restrict__ x, size_t m0,
                                          float* stage, int t, int tid)
{
    float* As  = stage;                 // [96][36]  raw x
    float* Bts = stage + 96*36;         // [128][36] W1t chunk
    int kk = t * 32;
#pragma unroll
    for (int j = 0; j < 3; j++) {
        int i = tid + j*256;
        int r = i >> 3, kq = i & 7;
        cpasync16(&As[r*36 + kq*4], &x[(m0 + r)*1024 + kk + kq*4]);
    }
#pragma unroll
    for (int j = 0; j < 4; j++) {
        int i = tid + j*256;
        int n = i >> 3, kq = i & 7;
        cpasync16(&Bts[n*36 + kq*4], &g_W1t[(size_t)n*1024 + kk + kq*4]);
    }
    CP_COMMIT;
}

__global__ __launch_bounds__(256) void k_projA(
    const float* __restrict__ x, const float* __restrict__ attW,
    const float* __restrict__ attb, float* __restrict__ outW, int wflag)
{
    extern __shared__ float smp[];
    float* attWs = smp + 3*KPA_STAGE;
    int tid = threadIdx.x;
    int bid = blockIdx.x;
    size_t m0 = (size_t)bid * 96;
    int bb0 = bid * 32;
    int lane = tid & 31, wid = tid >> 5;
    int t4 = lane & 3, g = lane >> 2;

    for (int i = tid; i < 1024; i += 256) attWs[i] = attW[i];

    float4 acc[2][8] = {};              // MMA warps
    float sAtt[3] = {}, sE[3] = {}, sPP[3] = {};   // stat warps

    kpa_issue(x, m0, smp,             0, tid);
    kpa_issue(x, m0, smp + KPA_STAGE, 1, tid);

    int s = 0;
    for (int t = 0; t < 32; t++) {
        if (t < 31) { CP_WAIT1; } else { CP_WAIT0; }
        __syncthreads();
        if (t + 2 < 32)
            kpa_issue(x, m0, smp + ((s + 2) % 3)*KPA_STAGE, t + 2, tid);
        float* Ac = smp + s*KPA_STAGE;
        if (wid < 6) {
            int wm = wid >> 1, wn = wid & 1;
            unsigned Au = (unsigned)__cvta_generic_to_shared(Ac);
            unsigned Bu = Au + 96*36*4;
            unsigned pA0 = a_ptr(Au, wm*32, 36, lane);
            unsigned pA1 = pA0 + 16*36*4;
            unsigned pB  = b_ptr(Bu, wn*64, 36, lane);
#pragma unroll
            for (int ks = 0; ks < 4; ks++) {
                uint4 a0 = ldsm4(pA0 + ks*32);
                uint4 a1 = ldsm4(pA1 + ks*32);
                uint4 bv[4];
#pragma unroll
                for (int p = 0; p < 4; p++) bv[p] = ldsm4(pB + p*16*36*4 + ks*32);
#pragma unroll
                for (int n = 0; n < 8; n++) {
                    unsigned b0 = (n & 1) ? bv[n>>1].z : bv[n>>1].x;
                    unsigned b1 = (n & 1) ? bv[n>>1].w : bv[n>>1].y;
                    mma_t(acc[0][n], a0.x, a0.y, a0.z, a0.w, b0, b1);
                    mma_t(acc[1][n], a1.x, a1.y, a1.z, a1.w, b0, b1);
                }
            }
        } else {
            // stat warps: 64 threads, 2 per batch (16-col halves)
            int st = tid - 192;
            int b = st >> 1, half = st & 1;
            const float* Ar = Ac + (3*b)*36 + half*16;
            const float* ws = attWs + t*32 + half*16;
#pragma unroll
            for (int c = 0; c < 16; c++) {
                float xa = Ar[c], xv = Ar[36 + c], xl = Ar[72 + c];
                float w = ws[c];
                sAtt[0] = fmaf(xa, w, sAtt[0]);
                sAtt[1] = fmaf(xv, w, sAtt[1]);
                sAtt[2] = fmaf(xl, w, sAtt[2]);
                float e0 = __expf(xa), e1 = __expf(xv), e2 = __expf(xl);
                sE[0] += e0; sE[1] += e1; sE[2] += e2;
                sPP[0] = fmaf(e0, e1, sPP[0]);     // a.v
                sPP[1] = fmaf(e0, e2, sPP[1]);     // a.l
                sPP[2] = fmaf(e1, e2, sPP[2]);     // v.l
            }
        }
        s = (s + 1) % 3;
    }

    if (wid < 6) {
        int wm = wid >> 1, wn = wid & 1;
#pragma unroll
        for (int m = 0; m < 2; m++) {
            size_t r0 = m0 + wm*32 + m*16 + g;
            size_t r1 = r0 + 8;
#pragma unroll
            for (int n = 0; n < 8; n++) {
                int col = wn*64 + n*8 + t4*2;
                float2 o0; o0.x = acc[m][n].x; o0.y = acc[m][n].y;
                float2 o1; o1.x = acc[m][n].z; o1.y = acc[m][n].w;
                *(float2*)&g_PQ1[r0*128 + col] = o0;
                *(float2*)&g_PQ1[r1*128 + col] = o1;
            }
        }
    } else {
        // combine the two halves of each batch
#pragma unroll
        for (int m = 0; m < 3; m++) {
            sAtt[m] += __shfl_xor_sync(0xffffffffu, sAtt[m], 1);
            sE[m]   += __shfl_xor_sync(0xffffffffu, sE[m],   1);
            sPP[m]  += __shfl_xor_sync(0xffffffffu, sPP[m],  1);
        }
        int st = tid - 192;
        int b = st >> 1, half = st & 1;
        if (half == 0) {
            int gb = bb0 + b;
            float ab = attb[0];
            float t0 = tanhf(sAtt[0] + ab), t1 = tanhf(sAtt[1] + ab), t2 = tanhf(sAtt[2] + ab);
            float mm = fmaxf(t0, fmaxf(t1, t2));
            float e0 = expf(t0 - mm), e1 = expf(t1 - mm), e2 = expf(t2 - mm);
            float inv = 1.f / (e0 + e1 + e2);
            float sa = e0*inv, sv = e1*inv, sl = e2*inv;
            float dav = sPP[0] / (sE[0]*sE[1]);
            float dal = sPP[1] / (sE[0]*sE[2]);
            float dvl = sPP[2] / (sE[1]*sE[2]);
            float sav = (sa + sv) / (dav + 0.5f);
            float sal = (sa + sl) / (dal + 0.5f);
            float svl = (sl + sv) / (dvl + 0.5f);
            g_wuni[gb*3+0] = sa; g_wuni[gb*3+1] = sv; g_wuni[gb*3+2] = sl;
            g_sbi [gb*3+0] = sav; g_sbi[gb*3+1] = sal; g_sbi[gb*3+2] = svl;
            float m3 = fmaxf(sav, fmaxf(sal, svl));
            float f0 = expf(sav - m3), f1 = expf(sal - m3), f2 = expf(svl - m3);
            float fi = 1.f / (f0 + f1 + f2);
            g_wbi[gb*3+0] = f0*fi; g_wbi[gb*3+1] = f1*fi; g_wbi[gb*3+2] = f2*fi;
            if (wflag) {
                float* o = outW + (size_t)gb*12;
                o[0] = sa; o[1] = sv; o[2] = sl;
                o[3] = f0*fi; o[4] = f1*fi; o[5] = f2*fi;
            }
        }
    }
}

// -------------------------- kFuse: stage-2 megafusion -----------------------
#define KF_PQ1   0
#define KF_ACT1  6336
#define KF_BI3   9600
#define KF_W2    12864
#define KF_W1    17216
#define KF_B1    25920
#define KF_WBI   25984
#define KF_TOTF  (25984+48+16)
#define KF_SMEM  (KF_TOTF*4)

__global__ __launch_bounds__(256) void kFuse(
    const float* __restrict__ x, const float* __restrict__ b1,
    const float* __restrict__ b2, float* __restrict__ outW, int wflag)
{
    extern __shared__ float sf[];
    float* PQ1s = sf + KF_PQ1;
    float* act1s= sf + KF_ACT1;
    float* bi3c = sf + KF_BI3;
    float* W2ts = sf + KF_W2;
    float* W1ts = sf + KF_W1;
    float* b1s  = sf + KF_B1;
    float* wbis = sf + KF_WBI;

    int tid = threadIdx.x;
    int bb0 = blockIdx.x * 16;
    int lane = tid & 31, wid = tid >> 5;
    int t4 = lane & 3, g = lane >> 2;
    int wm = wid >> 1, wn = wid & 1;

    for (int i = tid; i < 1536; i += 256) {
        int r = i >> 5, c4 = i & 31;
        int p = r >> 4, b = r & 15;
        cpasync16(&PQ1s[r*132 + c4*4], &g_PQ1[((size_t)(bb0 + b)*3 + p)*128 + c4*4]);
    }
    CP_COMMIT;
    if (tid < 64) b1s[tid] = b1[tid];
    if (tid < 48) { int p = tid >> 4, b = tid & 15; wbis[tid] = g_wbi[(bb0 + b)*3 + p]; }
    // per-warp unimodal weights for this CTA's two batches
    float su[2][3];
#pragma unroll
    for (int j = 0; j < 2; j++)
#pragma unroll
    for (int m = 0; m < 3; m++)
        su[j][m] = g_wuni[(size_t)(bb0 + 2*wid + j)*3 + m];
    CP_WAIT0;
    __syncthreads();
    for (int i = tid; i < 3072; i += 256) {
        int r = i >> 6, k = i & 63;
        int p = r >> 4, b = r & 15;
        int f = (p == 2) ? 1 : 0;
        int s = (p == 0) ? 1 : 2;
        float tv = PQ1s[(f*16+b)*132 + k] + PQ1s[(s*16+b)*132 + 64 + k] + b1s[k];
        act1s[r*68 + k] = tv > 0.f ? tv : 0.2f*tv;
    }
    __syncthreads();

    unsigned act1u = (unsigned)__cvta_generic_to_shared(act1s);
    unsigned bi3u  = (unsigned)__cvta_generic_to_shared(bi3c);
    unsigned w2tu  = (unsigned)__cvta_generic_to_shared(W2ts);
    unsigned w1tu  = (unsigned)__cvta_generic_to_shared(W1ts);
    unsigned pA1 = a_ptr(act1u, wm*16, 68, lane);
    unsigned pA2 = a_ptr(bi3u,  wm*16, 68, lane);
    unsigned pB1 = b_ptr(w2tu, wn*32, 68, lane);
    unsigned pB2 = b_ptr(w1tu, wn*64, 68, lane);

    float sE[2][3] = {}, sX[2][3] = {}, sP[2][3] = {}, sQ[2][3] = {};
    float4 pq2[8] = {};

    for (int n = 0; n < 16; n++) {
        int n0 = n * 64;
        for (int i = tid; i < 1024; i += 256) {
            int r = i >> 4, c4 = i & 15;
            cpasync16(&W2ts[r*68 + c4*4], &g_W2t[(size_t)(n0 + r)*64 + c4*4]);
        }
        for (int i = tid; i < 2048; i += 256) {
            int r = i >> 4, c4 = i & 15;
            cpasync16(&W1ts[r*68 + c4*4], &g_W1t[(size_t)r*1024 + n0 + c4*4]);
        }
        CP_COMMIT;
        float xr[12];
#pragma unroll
        for (int j = 0; j < 2; j++)
#pragma unroll
        for (int m = 0; m < 3; m++)
#pragma unroll
        for (int h = 0; h < 2; h++)
            xr[(j*3+m)*2+h] = x[((size_t)(bb0 + 2*wid + j)*3 + m)*1024 + n0 + lane + h*32];
        CP_WAIT0;
        __syncthreads();

        // GEMM1: act1 @ W2 chunk -> bi3c (tanh.approx * wbi, lrelu)
        if (wid < 6) {
            float4 acc[4] = {};
#pragma unroll
            for (int ks = 0; ks < 8; ks++) {
                uint4 a  = ldsm4(pA1 + ks*32);
                uint4 b0 = ldsm4(pB1 + ks*32);
                uint4 b1v= ldsm4(pB1 + 16*68*4 + ks*32);
                mma_t(acc[0], a.x,a.y,a.z,a.w, b0.x, b0.y);
                mma_t(acc[1], a.x,a.y,a.z,a.w, b0.z, b0.w);
                mma_t(acc[2], a.x,a.y,a.z,a.w, b1v.x, b1v.y);
                mma_t(acc[3], a.x,a.y,a.z,a.w, b1v.z, b1v.w);
            }
            int r0 = wm*16 + g, r1 = r0 + 8;
            float w0 = wbis[r0], w1 = wbis[r1];
#pragma unroll
            for (int q = 0; q < 4; q++) {
                int col = wn*32 + q*8 + t4*2;
                float2 b2v = *(const float2*)&b2[n0 + col];
                float t, v;
                t = tanh_fast(acc[q].x + b2v.x)*w0; v = t > 0.f ? t : 0.01f*t; bi3c[r0*68 + col]   = v;
                t = tanh_fast(acc[q].y + b2v.y)*w0; v = t > 0.f ? t : 0.01f*t; bi3c[r0*68 + col+1] = v;
                t = tanh_fast(acc[q].z + b2v.x)*w1; v = t > 0.f ? t : 0.01f*t; bi3c[r1*68 + col]   = v;
                t = tanh_fast(acc[q].w + b2v.y)*w1; v = t > 0.f ? t : 0.01f*t; bi3c[r1*68 + col+1] = v;
            }
        }
        __syncthreads();

        // stats + bisum + unimodal + GEMM2
#pragma unroll
        for (int j = 0; j < 2; j++) {
            int b = 2*wid + j;
            float* bsrow = &g_bisum[(size_t)(bb0 + b)*1024 + n0];
            float* unrow = &g_uni  [(size_t)(bb0 + b)*1024 + n0];
#pragma unroll
            for (int h = 0; h < 2; h++) {
                int c = lane + (h ? 32 : 0);
                float v0 = bi3c[b*68 + c];
                float v1 = bi3c[(16+b)*68 + c];
                float v2 = bi3c[(32+b)*68 + c];
                bsrow[c] = v0 + v1 + v2;
                float xa_r = xr[(j*3+0)*2+h];
                float xv_r = xr[(j*3+1)*2+h];
                float xl_r = xr[(j*3+2)*2+h];
                unrow[c] = (su[j][0]*xa_r + su[j][1]*xv_r + su[j][2]*xl_r) * (1.0f/3.0f);
                float e0 = exp_poly(v0);
                float e1 = exp_poly(v1);
                float e2 = exp_poly(v2);
                float xa = __expf(xa_r);
                float xv = __expf(xv_r);
                float xl = __expf(xl_r);
                sE[j][0] += e0; sE[j][1] += e1; sE[j][2] += e2;
                sX[j][0] += xa; sX[j][1] += xv; sX[j][2] += xl;
                sP[j][0] = fmaf(e0, e2, sP[j][0]);
                sP[j][1] = fmaf(e0, e1, sP[j][1]);
                sP[j][2] = fmaf(e1, e2, sP[j][2]);
                sQ[j][0] = fmaf(e0, xl, sQ[j][0]);
                sQ[j][1] = fmaf(e1, xv, sQ[j][1]);
                sQ[j][2] = fmaf(e2, xa, sQ[j][2]);
            }
        }
        if (wid < 6) {
#pragma unroll
            for (int ks = 0; ks < 8; ks++) {
                uint4 a = ldsm4(pA2 + ks*32);
                uint4 bv[4];
#pragma unroll
                for (int p = 0; p < 4; p++) bv[p] = ldsm4(pB2 + p*16*68*4 + ks*32);
#pragma unroll
                for (int q = 0; q < 8; q++) {
                    unsigned b0 = (q & 1) ? bv[q>>1].z : bv[q>>1].x;
                    unsigned b1 = (q & 1) ? bv[q>>1].w : bv[q>>1].y;
                    mma_t(pq2[q], a.x,a.y,a.z,a.w, b0, b1);
                }
            }
        }
        __syncthreads();
    }

    // ---- stats reduce -> w_tri ----
#pragma unroll
    for (int j = 0; j < 2; j++) {
#pragma unroll
        for (int o = 16; o > 0; o >>= 1) {
#pragma unroll
            for (int v = 0; v < 3; v++) {
                sE[j][v] += __shfl_down_sync(0xffffffffu, sE[j][v], o);
                sX[j][v] += __shfl_down_sync(0xffffffffu, sX[j][v], o);
                sP[j][v] += __shfl_down_sync(0xffffffffu, sP[j][v], o);
                sQ[j][v] += __shfl_down_sync(0xffffffffu, sQ[j][v], o);
            }
        }
    }
    if (lane == 0) {
#pragma unroll
        for (int j = 0; j < 2; j++) {
            int b = bb0 + 2*wid + j;
            float d0 = sP[j][0] / (sE[j][0]*sE[j][2]);
            float d1 = sP[j][1] / (sE[j][0]*sE[j][1]);
            float d2 = sP[j][2] / (sE[j][1]*sE[j][2]);
            float d3 = sQ[j][0] / (sE[j][0]*sX[j][2]);
            float d4 = sQ[j][1] / (sE[j][1]*sX[j][1]);
            float d5 = sQ[j][2] / (sE[j][2]*sX[j][0]);
            float sa = g_wuni[b*3+0], sv = g_wuni[b*3+1], sl = g_wuni[b*3+2];
            float sav = g_sbi[b*3+0], sal = g_sbi[b*3+1], svl = g_sbi[b*3+2];
            float nn[6];
            nn[0] = (sav + svl)/(d0 + 0.5f);
            nn[1] = (sav + sal)/(d1 + 0.5f);
            nn[2] = (sal + svl)/(d2 + 0.5f);
            nn[3] = (sav + sl )/(d3 + 0.5f);
            nn[4] = (sal + sv )/(d4 + 0.5f);
            nn[5] = (sa  + svl)/(d5 + 0.5f);
            float m = nn[0];
#pragma unroll
            for (int k = 1; k < 6; k++) m = fmaxf(m, nn[k]);
            float e[6], ss = 0.f;
#pragma unroll
            for (int k = 0; k < 6; k++) { e[k] = expf(nn[k]-m); ss += e[k]; }
            float inv = 1.f/ss;
#pragma unroll
            for (int k = 0; k < 6; k++) {
                g_wtri[(size_t)b*6 + k] = e[k]*inv;
                if (wflag) outW[(size_t)b*12 + 6 + k] = e[k]*inv;
            }
        }
    }

    // ---- PQ2 -> smem (reuse W1ts region as [48][136]) ----
    __syncthreads();
    if (wid < 6) {
        int r0 = wm*16 + g, r1 = r0 + 8;
#pragma unroll
        for (int q = 0; q < 8; q++) {
            int col = wn*64 + q*8 + t4*2;
            W1ts[r0*136 + col]   = pq2[q].x;
            W1ts[r0*136 + col+1] = pq2[q].y;
            W1ts[r1*136 + col]   = pq2[q].z;
            W1ts[r1*136 + col+1] = pq2[q].w;
        }
    }
    __syncthreads();
    // ---- act2 ----
    const int PR[6] = {0,0,2,0,1,2};
    const int QR[6] = {2,1,1,2,1,0};
    const int QS[6] = {0,0,0,1,1,1};
    for (int i = tid; i < 6144; i += 256) {
        int p = i >> 10, rem = i & 1023;
        int b = rem >> 6, k = rem & 63;
        float pv = W1ts[(PR[p]*16 + b)*136 + k];
        float qv = QS[p] ? PQ1s[(QR[p]*16 + b)*132 + 64 + k]
                         : W1ts[(QR[p]*16 + b)*136 + 64 + k];
        float tv = pv + qv + b1s[k];
        g_act2[((size_t)p*NB + bb0 + b)*64 + k] = tv > 0.f ? tv : 0.2f*tv;
    }
}

// -------------------------- k6: stage-2 second layer ------------------------
#define K6_SMEM ((2*128*68 + 64*68)*4)
__global__ __launch_bounds__(256) void k6_mma(const float* __restrict__ b2)
{
    extern __shared__ float sm6[];
    float* AsB  = sm6;
    float* W2ts = sm6 + 2*128*68;
    int tid = threadIdx.x;
    int b0 = blockIdx.x * 128, n0 = blockIdx.y * 64;

    for (int i = tid; i < 1024; i += 256) {
        int r = i >> 4, c4 = i & 15;
        cpasync16(&W2ts[r*68 + c4*4], &g_W2t[(size_t)(n0 + r)*64 + c4*4]);
    }
    {
        const float* Ap = g_act2 + ((size_t)0*NB + b0)*64;
        for (int i = tid; i < 2048; i += 256) {
            int r = i >> 4, c4 = i & 15;
            cpasync16(&AsB[r*68 + c4*4], &Ap[(size_t)r*64 + c4*4]);
        }
    }
    CP_COMMIT;

    int lane = tid & 31, wid = tid >> 5;
    int t4 = lane & 3, g = lane >> 2;
    int wm = wid >> 1, wn = wid & 1;
    int rw = wm*32, cw = wn*32;

    unsigned w2tu = (unsigned)__cvta_generic_to_shared(W2ts);
    unsigned pB  = b_ptr(w2tu, cw, 68, lane);
    unsigned As0u = (unsigned)__cvta_generic_to_shared(AsB);

    float4 tri[2][4] = {};
#pragma unroll 1
    for (int p = 0; p < 6; p++) {
        if (p + 1 < 6) {
            const float* Ap = g_act2 + ((size_t)(p+1)*NB + b0)*64;
            float* Ad = AsB + ((p+1) & 1)*128*68;
            for (int i = tid; i < 2048; i += 256) {
                int r = i >> 4, c4 = i & 15;
                cpasync16(&Ad[r*68 + c4*4], &Ap[(size_t)r*64 + c4*4]);
            }
            CP_COMMIT;
            CP_WAIT1;
        } else {
            CP_WAIT0;
        }
        __syncthreads();
        unsigned Au = As0u + (unsigned)((p & 1)*128*68*4);
        unsigned pA0 = a_ptr(Au, rw, 68, lane);
        unsigned pA1 = pA0 + 16*68*4;
        float4 acc[2][4] = {};
#pragma unroll
        for (int ks = 0; ks < 8; ks++) {
            uint4 a0 = ldsm4(pA0 + ks*32);
            uint4 a1 = ldsm4(pA1 + ks*32);
            uint4 b0 = ldsm4(pB + ks*32);
            uint4 b1v= ldsm4(pB + 16*68*4 + ks*32);
            mma_t(acc[0][0], a0.x,a0.y,a0.z,a0.w, b0.x, b0.y);
            mma_t(acc[0][1], a0.x,a0.y,a0.z,a0.w, b0.z, b0.w);
            mma_t(acc[0][2], a0.x,a0.y,a0.z,a0.w, b1v.x, b1v.y);
            mma_t(acc[0][3], a0.x,a0.y,a0.z,a0.w, b1v.z, b1v.w);
            mma_t(acc[1][0], a1.x,a1.y,a1.z,a1.w, b0.x, b0.y);
            mma_t(acc[1][1], a1.x,a1.y,a1.z,a1.w, b0.z, b0.w);
            mma_t(acc[1][2], a1.x,a1.y,a1.z,a1.w, b1v.x, b1v.y);
            mma_t(acc[1][3], a1.x,a1.y,a1.z,a1.w, b1v.z, b1v.w);
        }
#pragma unroll
        for (int m = 0; m < 2; m++) {
            int r0 = b0 + rw + m*16 + g;
            int r1 = r0 + 8;
            float wt0 = g_wtri[(size_t)r0*6 + p];
            float wt1 = g_wtri[(size_t)r1*6 + p];
#pragma unroll
            for (int q = 0; q < 4; q++) {
                int col = n0 + cw + q*8 + t4*2;
                float2 b2v = *(const float2*)&b2[col];
                float t;
                t = tanh_fast(acc[m][q].x + b2v.x)*wt0; tri[m][q].x += (t > 0.f ? t : 0.01f*t);
                t = tanh_fast(acc[m][q].y + b2v.y)*wt0; tri[m][q].y += (t > 0.f ? t : 0.01f*t);
                t = tanh_fast(acc[m][q].z + b2v.x)*wt1; tri[m][q].z += (t > 0.f ? t : 0.01f*t);
                t = tanh_fast(acc[m][q].w + b2v.y)*wt1; tri[m][q].w += (t > 0.f ? t : 0.01f*t);
            }
        }
        __syncthreads();
    }
#pragma unroll
    for (int m = 0; m < 2; m++) {
        size_t r0 = b0 + rw + m*16 + g, r1 = r0 + 8;
#pragma unroll
        for (int q = 0; q < 4; q++) {
            int col = n0 + cw + q*8 + t4*2;
            float2 o0; o0.x = tri[m][q].x; o0.y = tri[m][q].y;
            float2 o1; o1.x = tri[m][q].z; o1.y = tri[m][q].w;
            *(float2*)&g_tri[r0*1024 + col] = o0;
            *(float2*)&g_tri[r1*1024 + col] = o1;
        }
    }
}

// -------------------------- k7: fused head (tf32 layer1) --------------------
#define K7_SMEM ((64*36 + 32*72 + 64*52*2 + 512 + 3000)*4)
__global__ __launch_bounds__(256) void k7_final(
    const float* __restrict__ bnb,
    const float* __restrict__ l1b,
    const float* __restrict__ l2W, const float* __restrict__ l2b,
    const float* __restrict__ l3W, const float* __restrict__ l3b,
    float* __restrict__ out)
{
    extern __shared__ float pool[];
    float* As  = pool;
    float* Bs  = pool + 2304;
    float* Y1  = pool + 4608;
    float* Y2  = pool + 7936;
    float* Y3  = pool + 11264;
    float* W23 = pool + 11776;
    int tid = threadIdx.x;
    int b0 = blockIdx.x * 64;
    int lane = tid & 31, wid = tid >> 5;
    int g = lane >> 2, t4 = lane & 3;
    int wm = wid >> 2, wn = wid & 3;
    int rw = wm*32, cw = wn*16;

    for (int i = tid; i < 2500; i += 256) {
        int k = i / 50, c = i - k*50;
        W23[k*52 + c] = l2W[i];
    }
    for (int i = tid; i < 400; i += 256) W23[2600 + i] = l3W[i];

    float4 acc[2][2] = {};
    for (int t = 0; t < 96; t++) {
        int kk = t * 32;
        int region = kk >> 10;
        const float* src = region == 0 ? g_uni : (region == 1 ? g_bisum : g_tri);
        __syncthreads();
        for (int i = tid; i < 512; i += 256) {
            int r = i >> 3, c4 = i & 7;
            float4 v = *(const float4*)&src[(size_t)(b0 + r)*1024 + (kk & 1023) + c4*4];
            int j = kk + c4*4;
            float* d = &As[r*36 + c4*4];
            d[0] = f2tf_f(fmaf(v.x, g_bnsc[j],   bnb[j]));
            d[1] = f2tf_f(fmaf(v.y, g_bnsc[j+1], bnb[j+1]));
            d[2] = f2tf_f(fmaf(v.z, g_bnsc[j+2], bnb[j+2]));
            d[3] = f2tf_f(fmaf(v.w, g_bnsc[j+3], bnb[j+3]));
        }
        for (int i = tid; i < 512; i += 256) {
            int k = i >> 4, c4 = i & 15;
            cpasync16(&Bs[k*72 + c4*4], &g_l1Wp[(size_t)(kk + k)*64 + c4*4]);
        }
        CP_COMMIT; CP_WAIT0;
        __syncthreads();
#pragma unroll
        for (int ks = 0; ks < 4; ks++) {
            unsigned a[2][4], bf[2][2];
#pragma unroll
            for (int m = 0; m < 2; m++) {
                int r = rw + m*16 + g;
                a[m][0] = __float_as_uint(As[r*36 + ks*8 + t4]);
                a[m][1] = __float_as_uint(As[(r+8)*36 + ks*8 + t4]);
                a[m][2] = __float_as_uint(As[r*36 + ks*8 + t4 + 4]);
                a[m][3] = __float_as_uint(As[(r+8)*36 + ks*8 + t4 + 4]);
            }
#pragma unroll
            for (int n = 0; n < 2; n++) {
                int c = cw + n*8 + g;
                bf[n][0] = __float_as_uint(Bs[(ks*8 + t4)*72 + c]);
                bf[n][1] = __float_as_uint(Bs[(ks*8 + t4 + 4)*72 + c]);
            }
#pragma unroll
            for (int m = 0; m < 2; m++)
#pragma unroll
            for (int n = 0; n < 2; n++)
                mma_t(acc[m][n], a[m][0],a[m][1],a[m][2],a[m][3], bf[n][0], bf[n][1]);
        }
    }
    __syncthreads();
#pragma unroll
    for (int m = 0; m < 2; m++) {
        int r0 = rw + m*16 + g, r1 = r0 + 8;
#pragma unroll
        for (int n = 0; n < 2; n++) {
            int c = cw + n*8 + t4*2;
            if (c < 50)   { Y1[r0*52 + c]   = tanhf(acc[m][n].x + l1b[c]);
                            Y1[r1*52 + c]   = tanhf(acc[m][n].z + l1b[c]); }
            if (c+1 < 50) { Y1[r0*52 + c+1] = tanhf(acc[m][n].y + l1b[c+1]);
                            Y1[r1*52 + c+1] = tanhf(acc[m][n].w + l1b[c+1]); }
        }
    }
    __syncthreads();

    for (int o = tid; o < 3200; o += 256) {
        int r = o / 50, c = o - r*50;
        float a = l2b[c];
        for (int k = 0; k < 50; k++)
            a = fmaf(Y1[r*52 + k], W23[k*52 + c], a);
        Y2[r*52 + c] = tanhf(a);
    }
    __syncthreads();

    for (int o = tid; o < 512; o += 256) {
        int r = o >> 3, c = o & 7;
        float a = l3b[c];
        for (int k = 0; k < 50; k++)
            a = fmaf(Y2[r*52 + k], W23[2600 + k*8 + c], a);
        Y3[r*8 + c] = a;
    }
    __syncthreads();
    if (tid < 64) {
        int r = tid;
        float m = -1e30f;
#pragma unroll
        for (int c = 0; c < 8; c++) m = fmaxf(m, Y3[r*8 + c]);
        float e[8], s = 0.f;
#pragma unroll
        for (int c = 0; c < 8; c++) { e[c] = expf(Y3[r*8 + c] - m); s += e[c]; }
        float inv = 1.f / s;
        float* orow = out + (size_t)(b0 + r)*8;
#pragma unroll
        for (int c = 0; c < 8; c++) orow[c] = e[c]*inv;
    }
}

// -------------------------- launch ------------------------------------------
extern "C" void kernel_launch(void* const* d_in, const int* in_sizes, int n_in,
                              void* d_out, int out_size)
{
    const float* x    = (const float*)d_in[0];
    const float* attW = (const float*)d_in[1];
    const float* attb = (const float*)d_in[2];
    const float* gfW1 = (const float*)d_in[3];
    const float* gfb1 = (const float*)d_in[4];
    const float* gfW2 = (const float*)d_in[5];
    const float* gfb2 = (const float*)d_in[6];
    const float* bng  = (const float*)d_in[7];
    const float* bnb  = (const float*)d_in[8];
    const float* l1W  = (const float*)d_in[9];
    const float* l1b  = (const float*)d_in[10];
    const float* l2W  = (const float*)d_in[11];
    const float* l2b  = (const float*)d_in[12];
    const float* l3W  = (const float*)d_in[13];
    const float* l3b  = (const float*)d_in[14];
    float* out  = (float*)d_out;
    int wflag = (out_size >= NB*20) ? 1 : 0;
    float* outW = out + (size_t)NB*8;

    static int attr_done = 0;
    if (!attr_done) {
        cudaFuncSetAttribute(k_projA, cudaFuncAttributeMaxDynamicSharedMemorySize, KPA_SMEM);
        cudaFuncSetAttribute(kFuse,   cudaFuncAttributeMaxDynamicSharedMemorySize, KF_SMEM);
        cudaFuncSetAttribute(k6_mma,  cudaFuncAttributeMaxDynamicSharedMemorySize, K6_SMEM);
        cudaFuncSetAttribute(k7_final,cudaFuncAttributeMaxDynamicSharedMemorySize, K7_SMEM);
        attr_done = 1;
    }

    k0_prep<<<1549, 256>>>(gfW1, gfW2, l1W, bng);
    k_projA<<<NR3/96, 256, KPA_SMEM>>>(x, attW, attb, outW, wflag);
    kFuse<<<NB/16, 256, KF_SMEM>>>(x, gfb1, gfb2, outW, wflag);
    dim3 g6(NB/128, 16);
    k6_mma<<<g6, 256, K6_SMEM>>>(gfb2);
    k7_final<<<NB/64, 256, K7_SMEM>>>(bnb, l1b, l2W, l2b, l3W, l3b, out);
}

// round 16
// speedup vs baseline: 3.5673x; 1.0733x over previous
#include <cuda_runtime.h>
#include <cstdint>
#include <cstddef>

// ---------------------------------------------------------------------------
// graph12 — Round 16 (= Round 15 kernel, re-bench; prior bench died on
//   broker-level container failure, kernel never executed).
//   kFuse split-commit weight overlap; k7 wide-K chunks; k6 wtri in smem.
// ---------------------------------------------------------------------------

#define NB    16384
#define ND    1024
#define NR3   (NB*3)

__device__ float g_W1t  [128*1024];          // W1r transposed [n][k], tf32
__device__ float g_W2t  [1024*64];           // W2 transposed [n][k], tf32
__device__ float g_l1Wp [3072*64];           // tf32, padded 50->64
__device__ float g_bnsc [3072];
__device__ float g_PQ1  [(size_t)NR3*128];
__device__ float g_act2 [(size_t)6*NB*64];
__device__ float g_uni  [(size_t)NB*ND];
__device__ float g_bisum[(size_t)NB*ND];
__device__ float g_tri  [(size_t)NB*ND];
__device__ float g_wuni [NB*3];
__device__ float g_wbi  [NB*3];
__device__ float g_sbi  [NB*3];
__device__ float g_wtri [NB*6];

// -------------------------- helpers -----------------------------------------
__device__ __forceinline__ float f2tf_f(float f) {
    unsigned r;
    asm("cvt.rna.tf32.f32 %0, %1;" : "=r"(r) : "f"(f));
    return __uint_as_float(r);
}

__device__ __forceinline__ float tanh_fast(float x) {
    float r;
    asm("tanh.approx.f32 %0, %1;" : "=f"(r) : "f"(x));
    return r;
}

// exp(v) for v in [-0.02, 1.01]: degree-7 Taylor (Horner), rel err <= ~7e-5.
__device__ __forceinline__ float exp_poly(float v) {
    float p = 1.984127e-4f;
    p = fmaf(p, v, 1.3888889e-3f);
    p = fmaf(p, v, 8.3333333e-3f);
    p = fmaf(p, v, 4.1666667e-2f);
    p = fmaf(p, v, 1.6666667e-1f);
    p = fmaf(p, v, 0.5f);
    p = fmaf(p, v, 1.0f);
    p = fmaf(p, v, 1.0f);
    return p;
}

__device__ __forceinline__ void mma_t(float4& d, unsigned a0, unsigned a1,
                                      unsigned a2, unsigned a3,
                                      unsigned b0, unsigned b1) {
    asm volatile(
        "mma.sync.aligned.m16n8k8.row.col.f32.tf32.tf32.f32 "
        "{%0,%1,%2,%3}, {%4,%5,%6,%7}, {%8,%9}, {%0,%1,%2,%3};"
        : "+f"(d.x), "+f"(d.y), "+f"(d.z), "+f"(d.w)
        : "r"(a0), "r"(a1), "r"(a2), "r"(a3), "r"(b0), "r"(b1));
}

__device__ __forceinline__ uint4 ldsm4(unsigned addr) {
    uint4 r;
    asm volatile("ldmatrix.sync.aligned.m8n8.x4.shared.b16 {%0,%1,%2,%3}, [%4];"
                 : "=r"(r.x), "=r"(r.y), "=r"(r.z), "=r"(r.w) : "r"(addr));
    return r;
}

__device__ __forceinline__ unsigned a_ptr(unsigned base, int rbase, int S, int lane) {
    return base + ((rbase + (lane & 15))*S + ((lane & 16) >> 2))*4;
}
__device__ __forceinline__ unsigned b_ptr(unsigned base, int nbase, int St, int lane) {
    return base + ((nbase + (lane & 7) + ((lane & 16) >> 1))*St + ((lane & 8) >> 1))*4;
}

__device__ __forceinline__ void cpasync16(float* dst_smem, const float* src) {
    unsigned d = (unsigned)__cvta_generic_to_shared(dst_smem);
    asm volatile("cp.async.cg.shared.global [%0], [%1], 16;" :: "r"(d), "l"(src));
}
#define CP_COMMIT  asm volatile("cp.async.commit_group;")
#define CP_WAIT0   asm volatile("cp.async.wait_group 0;")
#define CP_WAIT1   asm volatile("cp.async.wait_group 1;")

// -------------------------- k0: prep ----------------------------------------
__global__ void k0_prep(const float* __restrict__ W1, const float* __restrict__ W2,
                        const float* __restrict__ l1W, const float* __restrict__ bng)
{
    int i = blockIdx.x * 256 + threadIdx.x;
    if (i < 131072) {
        int n = i >> 10, k = i & 1023;
        float v = (n < 64) ? W1[(size_t)k*64 + n] : W1[(size_t)(1024 + k)*64 + (n - 64)];
        g_W1t[i] = f2tf_f(v);
    } else if (i < 196608) {
        int i2 = i - 131072;
        int n = i2 >> 6, k = i2 & 63;
        g_W2t[i2] = f2tf_f(W2[(size_t)k*1024 + n]);
    } else if (i < 393216) {
        int i3 = i - 196608;
        int row = i3 >> 6, c = i3 & 63;
        g_l1Wp[i3] = (c < 50) ? f2tf_f(l1W[(size_t)row*50 + c]) : 0.f;
    } else if (i < 396288) {
        int j = i - 393216;
        float mult = (j < 1024) ? 1.f : ((j < 2048) ? (1.f/3.f) : (1.f/6.f));
        g_bnsc[j] = bng[j] * rsqrtf(1.0f + 1e-5f) * mult;
    }
}

// -------------------------- kP: PQ1 projection + attention stats ------------
#define KPA_STAGE (96*36 + 128*36)            // 8064 floats
#define KPA_SMEM  ((3*KPA_STAGE + 1024)*4)

__device__ __forceinline__ void kpa_issue(const float* __restrict__ x, size_t m0,
                                          float* stage, int t, int tid)
{
    float* As  = stage;                 // [96][36]  raw x
    float* Bts = stage + 96*36;         // [128][36] W1t chunk
    int kk = t * 32;
#pragma unroll
    for (int j = 0; j < 3; j++) {
        int i = tid + j*256;
        int r = i >> 3, kq = i & 7;
        cpasync16(&As[r*36 + kq*4], &x[(m0 + r)*1024 + kk + kq*4]);
    }
#pragma unroll
    for (int j = 0; j < 4; j++) {
        int i = tid + j*256;
        int n = i >> 3, kq = i & 7;
        cpasync16(&Bts[n*36 + kq*4], &g_W1t[(size_t)n*1024 + kk + kq*4]);
    }
    CP_COMMIT;
}

__global__ __launch_bounds__(256) void k_projA(
    const float* __restrict__ x, const float* __restrict__ attW,
    const float* __restrict__ attb, float* __restrict__ outW, int wflag)
{
    extern __shared__ float smp[];
    float* attWs = smp + 3*KPA_STAGE;
    int tid = threadIdx.x;
    int bid = blockIdx.x;
    size_t m0 = (size_t)bid * 96;
    int bb0 = bid * 32;
    int lane = tid & 31, wid = tid >> 5;
    int t4 = lane & 3, g = lane >> 2;

    for (int i = tid; i < 1024; i += 256) attWs[i] = attW[i];

    float4 acc[2][8] = {};              // MMA warps
    float sAtt[3] = {}, sE[3] = {}, sPP[3] = {};   // stat warps

    kpa_issue(x, m0, smp,             0, tid);
    kpa_issue(x, m0, smp + KPA_STAGE, 1, tid);

    int s = 0;
    for (int t = 0; t < 32; t++) {
        if (t < 31) { CP_WAIT1; } else { CP_WAIT0; }
        __syncthreads();
        if (t + 2 < 32)
            kpa_issue(x, m0, smp + ((s + 2) % 3)*KPA_STAGE, t + 2, tid);
        float* Ac = smp + s*KPA_STAGE;
        if (wid < 6) {
            int wm = wid >> 1, wn = wid & 1;
            unsigned Au = (unsigned)__cvta_generic_to_shared(Ac);
            unsigned Bu = Au + 96*36*4;
            unsigned pA0 = a_ptr(Au, wm*32, 36, lane);
            unsigned pA1 = pA0 + 16*36*4;
            unsigned pB  = b_ptr(Bu, wn*64, 36, lane);
#pragma unroll
            for (int ks = 0; ks < 4; ks++) {
                uint4 a0 = ldsm4(pA0 + ks*32);
                uint4 a1 = ldsm4(pA1 + ks*32);
                uint4 bv[4];
#pragma unroll
                for (int p = 0; p < 4; p++) bv[p] = ldsm4(pB + p*16*36*4 + ks*32);
#pragma unroll
                for (int n = 0; n < 8; n++) {
                    unsigned b0 = (n & 1) ? bv[n>>1].z : bv[n>>1].x;
                    unsigned b1 = (n & 1) ? bv[n>>1].w : bv[n>>1].y;
                    mma_t(acc[0][n], a0.x, a0.y, a0.z, a0.w, b0, b1);
                    mma_t(acc[1][n], a1.x, a1.y, a1.z, a1.w, b0, b1);
                }
            }
        } else {
            int st = tid - 192;
            int b = st >> 1, half = st & 1;
            const float* Ar = Ac + (3*b)*36 + half*16;
            const float* ws = attWs + t*32 + half*16;
#pragma unroll
            for (int c = 0; c < 16; c++) {
                float xa = Ar[c], xv = Ar[36 + c], xl = Ar[72 + c];
                float w = ws[c];
                sAtt[0] = fmaf(xa, w, sAtt[0]);
                sAtt[1] = fmaf(xv, w, sAtt[1]);
                sAtt[2] = fmaf(xl, w, sAtt[2]);
                float e0 = __expf(xa), e1 = __expf(xv), e2 = __expf(xl);
                sE[0] += e0; sE[1] += e1; sE[2] += e2;
                sPP[0] = fmaf(e0, e1, sPP[0]);
                sPP[1] = fmaf(e0, e2, sPP[1]);
                sPP[2] = fmaf(e1, e2, sPP[2]);
            }
        }
        s = (s + 1) % 3;
    }

    if (wid < 6) {
        int wm = wid >> 1, wn = wid & 1;
#pragma unroll
        for (int m = 0; m < 2; m++) {
            size_t r0 = m0 + wm*32 + m*16 + g;
            size_t r1 = r0 + 8;
#pragma unroll
            for (int n = 0; n < 8; n++) {
                int col = wn*64 + n*8 + t4*2;
                float2 o0; o0.x = acc[m][n].x; o0.y = acc[m][n].y;
                float2 o1; o1.x = acc[m][n].z; o1.y = acc[m][n].w;
                *(float2*)&g_PQ1[r0*128 + col] = o0;
                *(float2*)&g_PQ1[r1*128 + col] = o1;
            }
        }
    } else {
#pragma unroll
        for (int m = 0; m < 3; m++) {
            sAtt[m] += __shfl_xor_sync(0xffffffffu, sAtt[m], 1);
            sE[m]   += __shfl_xor_sync(0xffffffffu, sE[m],   1);
            sPP[m]  += __shfl_xor_sync(0xffffffffu, sPP[m],  1);
        }
        int st = tid - 192;
        int b = st >> 1, half = st & 1;
        if (half == 0) {
            int gb = bb0 + b;
            float ab = attb[0];
            float t0 = tanhf(sAtt[0] + ab), t1 = tanhf(sAtt[1] + ab), t2 = tanhf(sAtt[2] + ab);
            float mm = fmaxf(t0, fmaxf(t1, t2));
            float e0 = expf(t0 - mm), e1 = expf(t1 - mm), e2 = expf(t2 - mm);
            float inv = 1.f / (e0 + e1 + e2);
            float sa = e0*inv, sv = e1*inv, sl = e2*inv;
            float dav = sPP[0] / (sE[0]*sE[1]);
            float dal = sPP[1] / (sE[0]*sE[2]);
            float dvl = sPP[2] / (sE[1]*sE[2]);
            float sav = (sa + sv) / (dav + 0.5f);
            float sal = (sa + sl) / (dal + 0.5f);
            float svl = (sl + sv) / (dvl + 0.5f);
            g_wuni[gb*3+0] = sa; g_wuni[gb*3+1] = sv; g_wuni[gb*3+2] = sl;
            g_sbi [gb*3+0] = sav; g_sbi[gb*3+1] = sal; g_sbi[gb*3+2] = svl;
            float m3 = fmaxf(sav, fmaxf(sal, svl));
            float f0 = expf(sav - m3), f1 = expf(sal - m3), f2 = expf(svl - m3);
            float fi = 1.f / (f0 + f1 + f2);
            g_wbi[gb*3+0] = f0*fi; g_wbi[gb*3+1] = f1*fi; g_wbi[gb*3+2] = f2*fi;
            if (wflag) {
                float* o = outW + (size_t)gb*12;
                o[0] = sa; o[1] = sv; o[2] = sl;
                o[3] = f0*fi; o[4] = f1*fi; o[5] = f2*fi;
            }
        }
    }
}

// -------------------------- kFuse: stage-2 megafusion -----------------------
#define KF_PQ1   0
#define KF_ACT1  6336
#define KF_BI3   9600
#define KF_W2    12864
#define KF_W1    17216
#define KF_B1    25920
#define KF_WBI   25984
#define KF_TOTF  (25984+48+16)
#define KF_SMEM  (KF_TOTF*4)

__global__ __launch_bounds__(256) void kFuse(
    const float* __restrict__ x, const float* __restrict__ b1,
    const float* __restrict__ b2, float* __restrict__ outW, int wflag)
{
    extern __shared__ float sf[];
    float* PQ1s = sf + KF_PQ1;
    float* act1s= sf + KF_ACT1;
    float* bi3c = sf + KF_BI3;
    float* W2ts = sf + KF_W2;
    float* W1ts = sf + KF_W1;
    float* b1s  = sf + KF_B1;
    float* wbis = sf + KF_WBI;

    int tid = threadIdx.x;
    int bb0 = blockIdx.x * 16;
    int lane = tid & 31, wid = tid >> 5;
    int t4 = lane & 3, g = lane >> 2;
    int wm = wid >> 1, wn = wid & 1;

    for (int i = tid; i < 1536; i += 256) {
        int r = i >> 5, c4 = i & 31;
        int p = r >> 4, b = r & 15;
        cpasync16(&PQ1s[r*132 + c4*4], &g_PQ1[((size_t)(bb0 + b)*3 + p)*128 + c4*4]);
    }
    CP_COMMIT;
    if (tid < 64) b1s[tid] = b1[tid];
    if (tid < 48) { int p = tid >> 4, b = tid & 15; wbis[tid] = g_wbi[(bb0 + b)*3 + p]; }
    float su[2][3];
#pragma unroll
    for (int j = 0; j < 2; j++)
#pragma unroll
    for (int m = 0; m < 3; m++)
        su[j][m] = g_wuni[(size_t)(bb0 + 2*wid + j)*3 + m];
    CP_WAIT0;
    __syncthreads();
    for (int i = tid; i < 3072; i += 256) {
        int r = i >> 6, k = i & 63;
        int p = r >> 4, b = r & 15;
        int f = (p == 2) ? 1 : 0;
        int s = (p == 0) ? 1 : 2;
        float tv = PQ1s[(f*16+b)*132 + k] + PQ1s[(s*16+b)*132 + 64 + k] + b1s[k];
        act1s[r*68 + k] = tv > 0.f ? tv : 0.2f*tv;
    }
    __syncthreads();

    unsigned act1u = (unsigned)__cvta_generic_to_shared(act1s);
    unsigned bi3u  = (unsigned)__cvta_generic_to_shared(bi3c);
    unsigned w2tu  = (unsigned)__cvta_generic_to_shared(W2ts);
    unsigned w1tu  = (unsigned)__cvta_generic_to_shared(W1ts);
    unsigned pA1 = a_ptr(act1u, wm*16, 68, lane);
    unsigned pA2 = a_ptr(bi3u,  wm*16, 68, lane);
    unsigned pB1 = b_ptr(w2tu, wn*32, 68, lane);
    unsigned pB2 = b_ptr(w1tu, wn*64, 68, lane);

    float sE[2][3] = {}, sX[2][3] = {}, sP[2][3] = {}, sQ[2][3] = {};
    float4 pq2[8] = {};

    for (int n = 0; n < 16; n++) {
        int n0 = n * 64;
        // group 1: W2t chunk (needed for GEMM1)
        for (int i = tid; i < 1024; i += 256) {
            int r = i >> 4, c4 = i & 15;
            cpasync16(&W2ts[r*68 + c4*4], &g_W2t[(size_t)(n0 + r)*64 + c4*4]);
        }
        CP_COMMIT;
        // group 2: W1t chunk (needed only for GEMM2 — overlaps GEMM1+stats)
        for (int i = tid; i < 2048; i += 256) {
            int r = i >> 4, c4 = i & 15;
            cpasync16(&W1ts[r*68 + c4*4], &g_W1t[(size_t)r*1024 + n0 + c4*4]);
        }
        CP_COMMIT;
        float xr[12];
#pragma unroll
        for (int j = 0; j < 2; j++)
#pragma unroll
        for (int m = 0; m < 3; m++)
#pragma unroll
        for (int h = 0; h < 2; h++)
            xr[(j*3+m)*2+h] = x[((size_t)(bb0 + 2*wid + j)*3 + m)*1024 + n0 + lane + h*32];
        CP_WAIT1;          // W2t arrived; W1t may still be in flight
        __syncthreads();

        // GEMM1: act1 @ W2 chunk -> bi3c (tanh.approx * wbi, lrelu)
        if (wid < 6) {
            float4 acc[4] = {};
#pragma unroll
            for (int ks = 0; ks < 8; ks++) {
                uint4 a  = ldsm4(pA1 + ks*32);
                uint4 b0 = ldsm4(pB1 + ks*32);
                uint4 b1v= ldsm4(pB1 + 16*68*4 + ks*32);
                mma_t(acc[0], a.x,a.y,a.z,a.w, b0.x, b0.y);
                mma_t(acc[1], a.x,a.y,a.z,a.w, b0.z, b0.w);
                mma_t(acc[2], a.x,a.y,a.z,a.w, b1v.x, b1v.y);
                mma_t(acc[3], a.x,a.y,a.z,a.w, b1v.z, b1v.w);
            }
            int r0 = wm*16 + g, r1 = r0 + 8;
            float w0 = wbis[r0], w1 = wbis[r1];
#pragma unroll
            for (int q = 0; q < 4; q++) {
                int col = wn*32 + q*8 + t4*2;
                float2 b2v = *(const float2*)&b2[n0 + col];
                float t, v;
                t = tanh_fast(acc[q].x + b2v.x)*w0; v = t > 0.f ? t : 0.01f*t; bi3c[r0*68 + col]   = v;
                t = tanh_fast(acc[q].y + b2v.y)*w0; v = t > 0.f ? t : 0.01f*t; bi3c[r0*68 + col+1] = v;
                t = tanh_fast(acc[q].z + b2v.x)*w1; v = t > 0.f ? t : 0.01f*t; bi3c[r1*68 + col]   = v;
                t = tanh_fast(acc[q].w + b2v.y)*w1; v = t > 0.f ? t : 0.01f*t; bi3c[r1*68 + col+1] = v;
            }
        }
        __syncthreads();

        // stats + bisum + unimodal (W1t still loading underneath)
#pragma unroll
        for (int j = 0; j < 2; j++) {
            int b = 2*wid + j;
            float* bsrow = &g_bisum[(size_t)(bb0 + b)*1024 + n0];
            float* unrow = &g_uni  [(size_t)(bb0 + b)*1024 + n0];
#pragma unroll
            for (int h = 0; h < 2; h++) {
                int c = lane + (h ? 32 : 0);
                float v0 = bi3c[b*68 + c];
                float v1 = bi3c[(16+b)*68 + c];
                float v2 = bi3c[(32+b)*68 + c];
                bsrow[c] = v0 + v1 + v2;
                float xa_r = xr[(j*3+0)*2+h];
                float xv_r = xr[(j*3+1)*2+h];
                float xl_r = xr[(j*3+2)*2+h];
                unrow[c] = (su[j][0]*xa_r + su[j][1]*xv_r + su[j][2]*xl_r) * (1.0f/3.0f);
                float e0 = exp_poly(v0);
                float e1 = exp_poly(v1);
                float e2 = exp_poly(v2);
                float xa = __expf(xa_r);
                float xv = __expf(xv_r);
                float xl = __expf(xl_r);
                sE[j][0] += e0; sE[j][1] += e1; sE[j][2] += e2;
                sX[j][0] += xa; sX[j][1] += xv; sX[j][2] += xl;
                sP[j][0] = fmaf(e0, e2, sP[j][0]);
                sP[j][1] = fmaf(e0, e1, sP[j][1]);
                sP[j][2] = fmaf(e1, e2, sP[j][2]);
                sQ[j][0] = fmaf(e0, xl, sQ[j][0]);
                sQ[j][1] = fmaf(e1, xv, sQ[j][1]);
                sQ[j][2] = fmaf(e2, xa, sQ[j][2]);
            }
        }
        CP_WAIT0;          // W1t arrived
        __syncthreads();
        if (wid < 6) {
#pragma unroll
            for (int ks = 0; ks < 8; ks++) {
                uint4 a = ldsm4(pA2 + ks*32);
                uint4 bv[4];
#pragma unroll
                for (int p = 0; p < 4; p++) bv[p] = ldsm4(pB2 + p*16*68*4 + ks*32);
#pragma unroll
                for (int q = 0; q < 8; q++) {
                    unsigned b0 = (q & 1) ? bv[q>>1].z : bv[q>>1].x;
                    unsigned b1 = (q & 1) ? bv[q>>1].w : bv[q>>1].y;
                    mma_t(pq2[q], a.x,a.y,a.z,a.w, b0, b1);
                }
            }
        }
        __syncthreads();
    }

    // ---- stats reduce -> w_tri ----
#pragma unroll
    for (int j = 0; j < 2; j++) {
#pragma unroll
        for (int o = 16; o > 0; o >>= 1) {
#pragma unroll
            for (int v = 0; v < 3; v++) {
                sE[j][v] += __shfl_down_sync(0xffffffffu, sE[j][v], o);
                sX[j][v] += __shfl_down_sync(0xffffffffu, sX[j][v], o);
                sP[j][v] += __shfl_down_sync(0xffffffffu, sP[j][v], o);
                sQ[j][v] += __shfl_down_sync(0xffffffffu, sQ[j][v], o);
            }
        }
    }
    if (lane == 0) {
#pragma unroll
        for (int j = 0; j < 2; j++) {
            int b = bb0 + 2*wid + j;
            float d0 = sP[j][0] / (sE[j][0]*sE[j][2]);
            float d1 = sP[j][1] / (sE[j][0]*sE[j][1]);
            float d2 = sP[j][2] / (sE[j][1]*sE[j][2]);
            float d3 = sQ[j][0] / (sE[j][0]*sX[j][2]);
            float d4 = sQ[j][1] / (sE[j][1]*sX[j][1]);
            float d5 = sQ[j][2] / (sE[j][2]*sX[j][0]);
            float sa = g_wuni[b*3+0], sv = g_wuni[b*3+1], sl = g_wuni[b*3+2];
            float sav = g_sbi[b*3+0], sal = g_sbi[b*3+1], svl = g_sbi[b*3+2];
            float nn[6];
            nn[0] = (sav + svl)/(d0 + 0.5f);
            nn[1] = (sav + sal)/(d1 + 0.5f);
            nn[2] = (sal + svl)/(d2 + 0.5f);
            nn[3] = (sav + sl )/(d3 + 0.5f);
            nn[4] = (sal + sv )/(d4 + 0.5f);
            nn[5] = (sa  + svl)/(d5 + 0.5f);
            float m = nn[0];
#pragma unroll
            for (int k = 1; k < 6; k++) m = fmaxf(m, nn[k]);
            float e[6], ss = 0.f;
#pragma unroll
            for (int k = 0; k < 6; k++) { e[k] = expf(nn[k]-m); ss += e[k]; }
            float inv = 1.f/ss;
#pragma unroll
            for (int k = 0; k < 6; k++) {
                g_wtri[(size_t)b*6 + k] = e[k]*inv;
                if (wflag) outW[(size_t)b*12 + 6 + k] = e[k]*inv;
            }
        }
    }

    // ---- PQ2 -> smem (reuse W1ts region as [48][136]) ----
    __syncthreads();
    if (wid < 6) {
        int r0 = wm*16 + g, r1 = r0 + 8;
#pragma unroll
        for (int q = 0; q < 8; q++) {
            int col = wn*64 + q*8 + t4*2;
            W1ts[r0*136 + col]   = pq2[q].x;
            W1ts[r0*136 + col+1] = pq2[q].y;
            W1ts[r1*136 + col]   = pq2[q].z;
            W1ts[r1*136 + col+1] = pq2[q].w;
        }
    }
    __syncthreads();
    // ---- act2 ----
    const int PR[6] = {0,0,2,0,1,2};
    const int QR[6] = {2,1,1,2,1,0};
    const int QS[6] = {0,0,0,1,1,1};
    for (int i = tid; i < 6144; i += 256) {
        int p = i >> 10, rem = i & 1023;
        int b = rem >> 6, k = rem & 63;
        float pv = W1ts[(PR[p]*16 + b)*136 + k];
        float qv = QS[p] ? PQ1s[(QR[p]*16 + b)*132 + 64 + k]
                         : W1ts[(QR[p]*16 + b)*136 + 64 + k];
        float tv = pv + qv + b1s[k];
        g_act2[((size_t)p*NB + bb0 + b)*64 + k] = tv > 0.f ? tv : 0.2f*tv;
    }
}

// -------------------------- k6: stage-2 second layer ------------------------
#define K6_SMEM ((2*128*68 + 64*68 + 768)*4)
__global__ __launch_bounds__(256) void k6_mma(const float* __restrict__ b2)
{
    extern __shared__ float sm6[];
    float* AsB   = sm6;
    float* W2ts  = sm6 + 2*128*68;
    float* wtriS = sm6 + 2*128*68 + 64*68;     // [128][6]
    int tid = threadIdx.x;
    int b0 = blockIdx.x * 128, n0 = blockIdx.y * 64;

    for (int i = tid; i < 1024; i += 256) {
        int r = i >> 4, c4 = i & 15;
        cpasync16(&W2ts[r*68 + c4*4], &g_W2t[(size_t)(n0 + r)*64 + c4*4]);
    }
    {
        const float* Ap = g_act2 + ((size_t)0*NB + b0)*64;
        for (int i = tid; i < 2048; i += 256) {
            int r = i >> 4, c4 = i & 15;
            cpasync16(&AsB[r*68 + c4*4], &Ap[(size_t)r*64 + c4*4]);
        }
    }
    CP_COMMIT;
    for (int i = tid; i < 768; i += 256) wtriS[i] = g_wtri[(size_t)b0*6 + i];

    int lane = tid & 31, wid = tid >> 5;
    int t4 = lane & 3, g = lane >> 2;
    int wm = wid >> 1, wn = wid & 1;
    int rw = wm*32, cw = wn*32;

    unsigned w2tu = (unsigned)__cvta_generic_to_shared(W2ts);
    unsigned pB  = b_ptr(w2tu, cw, 68, lane);
    unsigned As0u = (unsigned)__cvta_generic_to_shared(AsB);

    float4 tri[2][4] = {};
#pragma unroll 1
    for (int p = 0; p < 6; p++) {
        if (p + 1 < 6) {
            const float* Ap = g_act2 + ((size_t)(p+1)*NB + b0)*64;
            float* Ad = AsB + ((p+1) & 1)*128*68;
            for (int i = tid; i < 2048; i += 256) {
                int r = i >> 4, c4 = i & 15;
                cpasync16(&Ad[r*68 + c4*4], &Ap[(size_t)r*64 + c4*4]);
            }
            CP_COMMIT;
            CP_WAIT1;
        } else {
            CP_WAIT0;
        }
        __syncthreads();
        unsigned Au = As0u + (unsigned)((p & 1)*128*68*4);
        unsigned pA0 = a_ptr(Au, rw, 68, lane);
        unsigned pA1 = pA0 + 16*68*4;
        float4 acc[2][4] = {};
#pragma unroll
        for (int ks = 0; ks < 8; ks++) {
            uint4 a0 = ldsm4(pA0 + ks*32);
            uint4 a1 = ldsm4(pA1 + ks*32);
            uint4 b0v = ldsm4(pB + ks*32);
            uint4 b1v= ldsm4(pB + 16*68*4 + ks*32);
            mma_t(acc[0][0], a0.x,a0.y,a0.z,a0.w, b0v.x, b0v.y);
            mma_t(acc[0][1], a0.x,a0.y,a0.z,a0.w, b0v.z, b0v.w);
            mma_t(acc[0][2], a0.x,a0.y,a0.z,a0.w, b1v.x, b1v.y);
            mma_t(acc[0][3], a0.x,a0.y,a0.z,a0.w, b1v.z, b1v.w);
            mma_t(acc[1][0], a1.x,a1.y,a1.z,a1.w, b0v.x, b0v.y);
            mma_t(acc[1][1], a1.x,a1.y,a1.z,a1.w, b0v.z, b0v.w);
            mma_t(acc[1][2], a1.x,a1.y,a1.z,a1.w, b1v.x, b1v.y);
            mma_t(acc[1][3], a1.x,a1.y,a1.z,a1.w, b1v.z, b1v.w);
        }
#pragma unroll
        for (int m = 0; m < 2; m++) {
            int lr0 = rw + m*16 + g;
            int lr1 = lr0 + 8;
            float wt0 = wtriS[lr0*6 + p];
            float wt1 = wtriS[lr1*6 + p];
#pragma unroll
            for (int q = 0; q < 4; q++) {
                int col = n0 + cw + q*8 + t4*2;
                float2 b2v = *(const float2*)&b2[col];
                float t;
                t = tanh_fast(acc[m][q].x + b2v.x)*wt0; tri[m][q].x += (t > 0.f ? t : 0.01f*t);
                t = tanh_fast(acc[m][q].y + b2v.y)*wt0; tri[m][q].y += (t > 0.f ? t : 0.01f*t);
                t = tanh_fast(acc[m][q].z + b2v.x)*wt1; tri[m][q].z += (t > 0.f ? t : 0.01f*t);
                t = tanh_fast(acc[m][q].w + b2v.y)*wt1; tri[m][q].w += (t > 0.f ? t : 0.01f*t);
            }
        }
        __syncthreads();
    }
#pragma unroll
    for (int m = 0; m < 2; m++) {
        size_t r0 = b0 + rw + m*16 + g, r1 = r0 + 8;
#pragma unroll
        for (int q = 0; q < 4; q++) {
            int col = n0 + cw + q*8 + t4*2;
            float2 o0; o0.x = tri[m][q].x; o0.y = tri[m][q].y;
            float2 o1; o1.x = tri[m][q].z; o1.y = tri[m][q].w;
            *(float2*)&g_tri[r0*1024 + col] = o0;
            *(float2*)&g_tri[r1*1024 + col] = o1;
        }
    }
}

// -------------------------- k7: fused head (tf32 layer1, K=64 chunks) -------
#define K7_SMEM ((4352 + 4608 + 3328 + 3328 + 512 + 3000)*4)
__global__ __launch_bounds__(256) void k7_final(
    const float* __restrict__ bnb,
    const float* __restrict__ l1b,
    const float* __restrict__ l2W, const float* __restrict__ l2b,
    const float* __restrict__ l3W, const float* __restrict__ l3b,
    float* __restrict__ out)
{
    extern __shared__ float pool[];
    float* As  = pool;
    float* Bs  = pool + 4352;
    float* Y1  = pool + 8960;
    float* Y2  = pool + 12288;
    float* Y3  = pool + 15616;
    float* W23 = pool + 16128;
    int tid = threadIdx.x;
    int b0 = blockIdx.x * 64;
    int lane = tid & 31, wid = tid >> 5;
    int g = lane >> 2, t4 = lane & 3;
    int wm = wid >> 2, wn = wid & 3;
    int rw = wm*32, cw = wn*16;

    for (int i = tid; i < 2500; i += 256) {
        int k = i / 50, c = i - k*50;
        W23[k*52 + c] = l2W[i];
    }
    for (int i = tid; i < 400; i += 256) W23[2600 + i] = l3W[i];

    float4 acc[2][2] = {};
    for (int t = 0; t < 48; t++) {
        int kk = t * 64;
        int region = kk >> 10;
        const float* src = region == 0 ? g_uni : (region == 1 ? g_bisum : g_tri);
        __syncthreads();
        for (int i = tid; i < 1024; i += 256) {
            int k = i >> 4, c4 = i & 15;
            cpasync16(&Bs[k*72 + c4*4], &g_l1Wp[(size_t)(kk + k)*64 + c4*4]);
        }
        CP_COMMIT;
        for (int i = tid; i < 1024; i += 256) {
            int r = i >> 4, c4 = i & 15;
            float4 v = *(const float4*)&src[(size_t)(b0 + r)*1024 + (kk & 1023) + c4*4];
            int j = kk + c4*4;
            float* d = &As[r*68 + c4*4];
            d[0] = f2tf_f(fmaf(v.x, g_bnsc[j],   bnb[j]));
            d[1] = f2tf_f(fmaf(v.y, g_bnsc[j+1], bnb[j+1]));
            d[2] = f2tf_f(fmaf(v.z, g_bnsc[j+2], bnb[j+2]));
            d[3] = f2tf_f(fmaf(v.w, g_bnsc[j+3], bnb[j+3]));
        }
        CP_WAIT0;
        __syncthreads();
#pragma unroll
        for (int ks = 0; ks < 8; ks++) {
            unsigned a[2][4], bf[2][2];
#pragma unroll
            for (int m = 0; m < 2; m++) {
                int r = rw + m*16 + g;
                a[m][0] = __float_as_uint(As[r*68 + ks*8 + t4]);
                a[m][1] = __float_as_uint(As[(r+8)*68 + ks*8 + t4]);
                a[m][2] = __float_as_uint(As[r*68 + ks*8 + t4 + 4]);
                a[m][3] = __float_as_uint(As[(r+8)*68 + ks*8 + t4 + 4]);
            }
#pragma unroll
            for (int n = 0; n < 2; n++) {
                int c = cw + n*8 + g;
                bf[n][0] = __float_as_uint(Bs[(ks*8 + t4)*72 + c]);
                bf[n][1] = __float_as_uint(Bs[(ks*8 + t4 + 4)*72 + c]);
            }
#pragma unroll
            for (int m = 0; m < 2; m++)
#pragma unroll
            for (int n = 0; n < 2; n++)
                mma_t(acc[m][n], a[m][0],a[m][1],a[m][2],a[m][3], bf[n][0], bf[n][1]);
        }
    }
    __syncthreads();
#pragma unroll
    for (int m = 0; m < 2; m++) {
        int r0 = rw + m*16 + g, r1 = r0 + 8;
#pragma unroll
        for (int n = 0; n < 2; n++) {
            int c = cw + n*8 + t4*2;
            if (c < 50)   { Y1[r0*52 + c]   = tanhf(acc[m][n].x + l1b[c]);
                            Y1[r1*52 + c]   = tanhf(acc[m][n].z + l1b[c]); }
            if (c+1 < 50) { Y1[r0*52 + c+1] = tanhf(acc[m][n].y + l1b[c+1]);
                            Y1[r1*52 + c+1] = tanhf(acc[m][n].w + l1b[c+1]); }
        }
    }
    __syncthreads();

    for (int o = tid; o < 3200; o += 256) {
        int r = o / 50, c = o - r*50;
        float a = l2b[c];
        for (int k = 0; k < 50; k++)
            a = fmaf(Y1[r*52 + k], W23[k*52 + c], a);
        Y2[r*52 + c] = tanhf(a);
    }
    __syncthreads();

    for (int o = tid; o < 512; o += 256) {
        int r = o >> 3, c = o & 7;
        float a = l3b[c];
        for (int k = 0; k < 50; k++)
            a = fmaf(Y2[r*52 + k], W23[2600 + k*8 + c], a);
        Y3[r*8 + c] = a;
    }
    __syncthreads();
    if (tid < 64) {
        int r = tid;
        float m = -1e30f;
#pragma unroll
        for (int c = 0; c < 8; c++) m = fmaxf(m, Y3[r*8 + c]);
        float e[8], s = 0.f;
#pragma unroll
        for (int c = 0; c < 8; c++) { e[c] = expf(Y3[r*8 + c] - m); s += e[c]; }
        float inv = 1.f / s;
        float* orow = out + (size_t)(b0 + r)*8;
#pragma unroll
        for (int c = 0; c < 8; c++) orow[c] = e[c]*inv;
    }
}

// -------------------------- launch ------------------------------------------
extern "C" void kernel_launch(void* const* d_in, const int* in_sizes, int n_in,
                              void* d_out, int out_size)
{
    const float* x    = (const float*)d_in[0];
    const float* attW = (const float*)d_in[1];
    const float* attb = (const float*)d_in[2];
    const float* gfW1 = (const float*)d_in[3];
    const float* gfb1 = (const float*)d_in[4];
    const float* gfW2 = (const float*)d_in[5];
    const float* gfb2 = (const float*)d_in[6];
    const float* bng  = (const float*)d_in[7];
    const float* bnb  = (const float*)d_in[8];
    const float* l1W  = (const float*)d_in[9];
    const float* l1b  = (const float*)d_in[10];
    const float* l2W  = (const float*)d_in[11];
    const float* l2b  = (const float*)d_in[12];
    const float* l3W  = (const float*)d_in[13];
    const float* l3b  = (const float*)d_in[14];
    float* out  = (float*)d_out;
    int wflag = (out_size >= NB*20) ? 1 : 0;
    float* outW = out + (size_t)NB*8;

    static int attr_done = 0;
    if (!attr_done) {
        cudaFuncSetAttribute(k_projA, cudaFuncAttributeMaxDynamicSharedMemorySize, KPA_SMEM);
        cudaFuncSetAttribute(kFuse,   cudaFuncAttributeMaxDynamicSharedMemorySize, KF_SMEM);
        cudaFuncSetAttribute(k6_mma,  cudaFuncAttributeMaxDynamicSharedMemorySize, K6_SMEM);
        cudaFuncSetAttribute(k7_final,cudaFuncAttributeMaxDynamicSharedMemorySize, K7_SMEM);
        attr_done = 1;
    }

    k0_prep<<<1549, 256>>>(gfW1, gfW2, l1W, bng);
    k_projA<<<NR3/96, 256, KPA_SMEM>>>(x, attW, attb, outW, wflag);
    kFuse<<<NB/16, 256, KF_SMEM>>>(x, gfb1, gfb2, outW, wflag);
    dim3 g6(NB/128, 16);
    k6_mma<<<g6, 256, K6_SMEM>>>(gfb2);
    k7_final<<<NB/64, 256, K7_SMEM>>>(bnb, l1b, l2W, l2b, l3W, l3b, out);
}